// round 6
// baseline (speedup 1.0000x reference)
#include <cuda_runtime.h>
#include <math.h>
#include <stdint.h>

// Problem dims
#define SS 50
#define LL 1024
#define DD 768
#define DD4 192
#define SP 64   // padded step dim for cross attention

// ---------------- static scratch (alloc-free rule) ----------------
__device__ float g_bufA[(size_t)SS * LL * DD];
__device__ float g_bufB[(size_t)SS * LL * DD];
__device__ float g_bufC[(size_t)SS * LL * DD];
__device__ float g_q[(size_t)LL * SP * DD4];
__device__ float g_k[(size_t)LL * SP * DD4];
__device__ float g_scores[(size_t)SS * LL * LL];   // also xt_pad [LL,SP,DD]
__device__ float g_xT[(size_t)LL * DD * SP];       // xT / xtpadT scratch
__device__ float g_wT[118849536];                  // transposed weights

// =============== helpers =====================
__device__ __forceinline__ uint32_t smem_u32(const void* p) {
    uint32_t a;
    asm("{ .reg .u64 t; cvta.to.shared.u64 t, %1; cvt.u32.u64 %0, t; }" : "=r"(a) : "l"(p));
    return a;
}
__device__ __forceinline__ uint32_t f2tf_bits(uint32_t raw) {
    uint32_t r;
    float f = __uint_as_float(raw);
    asm("cvt.rna.tf32.f32 %0, %1;" : "=r"(r) : "f"(f));
    return r;
}
__device__ __forceinline__ void mma_tf32(float* d, const uint32_t* a, const uint32_t* b) {
    asm volatile(
        "mma.sync.aligned.m16n8k8.row.col.f32.tf32.tf32.f32 "
        "{%0,%1,%2,%3}, {%4,%5,%6,%7}, {%8,%9}, {%0,%1,%2,%3};\n"
        : "+f"(d[0]), "+f"(d[1]), "+f"(d[2]), "+f"(d[3])
        : "r"(a[0]), "r"(a[1]), "r"(a[2]), "r"(a[3]),
          "r"(b[0]), "r"(b[1]));
}
__device__ __forceinline__ void cp_async16(uint32_t smem_addr, const void* gptr, uint32_t src_bytes) {
    asm volatile("cp.async.ca.shared.global [%0], [%1], 16, %2;"
                 :: "r"(smem_addr), "l"(gptr), "r"(src_bytes));
}
#define CP_COMMIT() asm volatile("cp.async.commit_group;" ::: "memory")
#define CP_WAIT2()  asm volatile("cp.async.wait_group 2;" ::: "memory")

// =================================================================
// cp.async-pipelined TF32 NT GEMM (mma.sync m16n8k8)
// C[b] = A[b] @ B[b]^T (+bias)(+relu)
// A: [M,K] row-major. B: [N,K] row-major. K % 16 == 0, N even.
// CTA 128x128, 8 warps (warp tile 64x32), 4-stage cp.async ring.
// =================================================================
#define RSTRIDE 20                     // words per smem row (conflict-free)
#define OPW     (128 * RSTRIDE)        // 2560 words per operand per stage
#define STGW    (2 * OPW)              // 5120 words per stage
#define NSTAGE  4
#define GEMM_SMEM_BYTES (NSTAGE * STGW * 4)   // 81920

template<bool BIAS, bool RELU>
__global__ __launch_bounds__(256, 2)
void mma_gemm_kernel(const float* __restrict__ Ab, const float* __restrict__ Bb,
                     const float* __restrict__ biasb, float* __restrict__ Cb,
                     int M, int N, int K,
                     long sA, long sB, long sBias, long sC)
{
    extern __shared__ __align__(16) uint32_t sm[];
    const uint32_t smb = smem_u32(sm);

    const int b = blockIdx.z;
    const float* A = Ab + (long)b * sA;
    const float* B = Bb + (long)b * sB;
    float* C = Cb + (long)b * sC;

    const int brow = blockIdx.y * 128;
    const int bcol = blockIdx.x * 128;
    const int tid = threadIdx.x;
    const int wid = tid >> 5;
    const int lane = tid & 31;
    const int g = lane >> 2;
    const int c = lane & 3;
    const int warp_m = (wid & 1) * 64;
    const int warp_n = (wid >> 1) * 32;

    const int nkt = K >> 4;

    float acc[4][4][4];
    #pragma unroll
    for (int i = 0; i < 4; i++)
        #pragma unroll
        for (int j = 0; j < 4; j++)
            #pragma unroll
            for (int r = 0; r < 4; r++)
                acc[i][j][r] = 0.0f;

    // per-thread staging map: idx = i*256+tid -> (operand row, 16B chunk)
    auto issue_stage = [&](int kt) {
        if (kt < nkt) {
            int k0 = kt << 4;
            uint32_t sbase = smb + ((kt & (NSTAGE - 1)) * STGW) * 4;
            #pragma unroll
            for (int i = 0; i < 4; i++) {
                int idx = i * 256 + tid;          // 0..1023
                int row = idx >> 2;               // 0..255
                int q = idx & 3;
                if (row < 128) {
                    int gr = brow + row;
                    const float* gp = A + (long)gr * K + k0 + q * 4;
                    uint32_t dst = sbase + (row * RSTRIDE + q * 4) * 4;
                    cp_async16(dst, gp, (gr < M) ? 16u : 0u);
                } else {
                    int r = row - 128;
                    int gn = bcol + r;
                    const float* gp = B + (long)gn * K + k0 + q * 4;
                    uint32_t dst = sbase + (OPW + r * RSTRIDE + q * 4) * 4;
                    cp_async16(dst, gp, (gn < N) ? 16u : 0u);
                }
            }
        }
        CP_COMMIT();   // always commit (possibly empty) to keep group count in lockstep
    };

    issue_stage(0);
    issue_stage(1);
    issue_stage(2);

    for (int kt = 0; kt < nkt; kt++) {
        CP_WAIT2();
        __syncthreads();
        issue_stage(kt + 3);

        const uint32_t* As = sm + (kt & (NSTAGE - 1)) * STGW;
        const uint32_t* Bs = As + OPW;

        #pragma unroll
        for (int ks = 0; ks < 16; ks += 8) {
            uint32_t af[4][4], bf[4][2];
            #pragma unroll
            for (int am = 0; am < 4; am++) {
                int r0 = warp_m + am * 16 + g;
                af[am][0] = f2tf_bits(As[r0 * RSTRIDE + ks + c]);
                af[am][1] = f2tf_bits(As[(r0 + 8) * RSTRIDE + ks + c]);
                af[am][2] = f2tf_bits(As[r0 * RSTRIDE + ks + c + 4]);
                af[am][3] = f2tf_bits(As[(r0 + 8) * RSTRIDE + ks + c + 4]);
            }
            #pragma unroll
            for (int bn = 0; bn < 4; bn++) {
                int col = warp_n + bn * 8 + g;
                bf[bn][0] = f2tf_bits(Bs[col * RSTRIDE + ks + c]);
                bf[bn][1] = f2tf_bits(Bs[col * RSTRIDE + ks + c + 4]);
            }
            #pragma unroll
            for (int am = 0; am < 4; am++)
                #pragma unroll
                for (int bn = 0; bn < 4; bn++)
                    mma_tf32(acc[am][bn], af[am], bf[bn]);
        }
    }

    // ---- epilogue ----
    #pragma unroll
    for (int am = 0; am < 4; am++) {
        int row0 = brow + warp_m + am * 16 + g;
        #pragma unroll
        for (int bn = 0; bn < 4; bn++) {
            int col = bcol + warp_n + bn * 8 + c * 2;
            if (col >= N) continue;
            float v0 = acc[am][bn][0], v1 = acc[am][bn][1];
            float v2 = acc[am][bn][2], v3 = acc[am][bn][3];
            if (BIAS) {
                float b0 = biasb[(long)b * sBias + col];
                float b1 = biasb[(long)b * sBias + col + 1];
                v0 += b0; v1 += b1; v2 += b0; v3 += b1;
            }
            if (RELU) {
                v0 = fmaxf(v0, 0.f); v1 = fmaxf(v1, 0.f);
                v2 = fmaxf(v2, 0.f); v3 = fmaxf(v3, 0.f);
            }
            if (row0 < M)     *(float2*)&C[(long)row0 * N + col]       = make_float2(v0, v1);
            if (row0 + 8 < M) *(float2*)&C[(long)(row0 + 8) * N + col] = make_float2(v2, v3);
        }
    }
}

// ---------------- tiled transpose: [B, R, C] -> [B, C, R] ----------------
__global__ __launch_bounds__(256)
void transpose_kernel(const float* __restrict__ in, float* __restrict__ out, int R, int C)
{
    __shared__ float t[32][33];
    long z = blockIdx.z;
    const float* src = in + z * (long)R * C;
    float* dst = out + z * (long)R * C;
    int c0 = blockIdx.x * 32, r0 = blockIdx.y * 32;
    int tx = threadIdx.x, ty = threadIdx.y;   // (32, 8)
    #pragma unroll
    for (int j = ty; j < 32; j += 8) {
        int r = r0 + j, cc = c0 + tx;
        if (r < R && cc < C) t[j][tx] = src[(long)r * C + cc];
    }
    __syncthreads();
    #pragma unroll
    for (int j = ty; j < 32; j += 8) {
        int cc = c0 + j, r = r0 + tx;
        if (r < R && cc < C) dst[(long)cc * R + r] = t[tx][j];
    }
}

// ---------------- row softmax (pre-scale, padded stride, pad->0) ----------------
__global__ __launch_bounds__(256)
void softmax_kernel(float* __restrict__ data, int n, int stride, float scale)
{
    long row = blockIdx.x;
    float* p = data + row * (long)stride;
    int t = threadIdx.x;
    int w = t >> 5, lane = t & 31;

    float loc[4];
    int cnt = 0;
    float mx = -3.0e38f;
    for (int i = t; i < n; i += 256) {
        float v = p[i] * scale;
        loc[cnt++] = v;
        mx = fmaxf(mx, v);
    }
    #pragma unroll
    for (int o = 16; o > 0; o >>= 1) mx = fmaxf(mx, __shfl_xor_sync(0xffffffffu, mx, o));
    __shared__ float red[8];
    if (lane == 0) red[w] = mx;
    __syncthreads();
    if (t < 8) {
        float v = red[t];
        #pragma unroll
        for (int o = 4; o > 0; o >>= 1) v = fmaxf(v, __shfl_xor_sync(0xffu, v, o));
        if (t == 0) red[0] = v;
    }
    __syncthreads();
    mx = red[0];
    __syncthreads();

    float sum = 0.0f;
    for (int cc = 0; cc < cnt; cc++) {
        float e = __expf(loc[cc] - mx);
        loc[cc] = e;
        sum += e;
    }
    #pragma unroll
    for (int o = 16; o > 0; o >>= 1) sum += __shfl_xor_sync(0xffffffffu, sum, o);
    if (lane == 0) red[w] = sum;
    __syncthreads();
    if (t < 8) {
        float v = red[t];
        #pragma unroll
        for (int o = 4; o > 0; o >>= 1) v += __shfl_xor_sync(0xffu, v, o);
        if (t == 0) red[0] = v;
    }
    __syncthreads();
    float inv = 1.0f / red[0];

    cnt = 0;
    for (int i = t; i < n; i += 256) p[i] = loc[cnt++] * inv;
    for (int i = t; i < stride; i += 256) if (i >= n) p[i] = 0.0f;
}

// ---------------- fused residual + LayerNorm, generalized index mapping ----------
__global__ __launch_bounds__(256)
void ln_kernel(const float* __restrict__ resid, const float* __restrict__ h,
               const float* __restrict__ gam, const float* __restrict__ bet,
               float* __restrict__ out, int J,
               long ri, long rj, long hi, long hj, long oi, long oj, long gstride)
{
    long b = blockIdx.x;
    long i = b / J, j = b % J;
    const float* r  = resid + (i * ri + j * rj) * DD;
    const float* hh = h     + (i * hi + j * hj) * DD;
    float* op       = out   + (i * oi + j * oj) * DD;
    const float* gp = gam + i * gstride;
    const float* bp = bet + i * gstride;
    int t = threadIdx.x;
    int w = t >> 5, lane = t & 31;

    float v[3];
    float s = 0.0f, s2 = 0.0f;
    #pragma unroll
    for (int k = 0; k < 3; k++) {
        int d = t + k * 256;
        float val = r[d] + hh[d];
        v[k] = val;
        s += val;
        s2 += val * val;
    }
    #pragma unroll
    for (int o = 16; o > 0; o >>= 1) {
        s  += __shfl_xor_sync(0xffffffffu, s, o);
        s2 += __shfl_xor_sync(0xffffffffu, s2, o);
    }
    __shared__ float rs[8], rs2[8];
    if (lane == 0) { rs[w] = s; rs2[w] = s2; }
    __syncthreads();
    if (t < 8) {
        s = rs[t]; s2 = rs2[t];
        #pragma unroll
        for (int o = 4; o > 0; o >>= 1) {
            s  += __shfl_xor_sync(0xffu, s, o);
            s2 += __shfl_xor_sync(0xffu, s2, o);
        }
        if (t == 0) { rs[0] = s; rs2[0] = s2; }
    }
    __syncthreads();
    float mean = rs[0] * (1.0f / DD);
    float var  = rs2[0] * (1.0f / DD) - mean * mean;
    float inv  = rsqrtf(var + 1e-5f);

    #pragma unroll
    for (int k = 0; k < 3; k++) {
        int d = t + k * 256;
        op[d] = (v[k] - mean) * inv * gp[d] + bp[d];
    }
}

// ---------------- zero the pad rows of xt_pad [LL, SP, DD] ----------------
__global__ __launch_bounds__(256)
void zero_pad_kernel(float* __restrict__ xt)
{
    long idx = (long)blockIdx.x * 256 + threadIdx.x;
    const long per_l = (long)(SP - SS) * DD;
    const long total = (long)LL * per_l;
    if (idx >= total) return;
    long l = idx / per_l;
    long off = idx % per_l;
    xt[((long)l * SP + SS) * DD + off] = 0.0f;
}

// ---------------- launch plumbing ----------------
static inline int cdiv(int a, int b) { return (a + b - 1) / b; }

// mode: 0 = plain, 1 = bias, 2 = bias+relu
static void tgemm(const float* A, const float* B, const float* bias, float* C,
                  int M, int N, int K, int batch,
                  long sA, long sB, long sBias, long sC, int mode)
{
    dim3 grid(cdiv(N, 128), cdiv(M, 128), batch);
    if (mode == 0) {
        cudaFuncSetAttribute(mma_gemm_kernel<false, false>,
                             cudaFuncAttributeMaxDynamicSharedMemorySize, GEMM_SMEM_BYTES);
        mma_gemm_kernel<false, false><<<grid, 256, GEMM_SMEM_BYTES>>>(A, B, bias, C, M, N, K, sA, sB, sBias, sC);
    } else if (mode == 1) {
        cudaFuncSetAttribute(mma_gemm_kernel<true, false>,
                             cudaFuncAttributeMaxDynamicSharedMemorySize, GEMM_SMEM_BYTES);
        mma_gemm_kernel<true, false><<<grid, 256, GEMM_SMEM_BYTES>>>(A, B, bias, C, M, N, K, sA, sB, sBias, sC);
    } else {
        cudaFuncSetAttribute(mma_gemm_kernel<true, true>,
                             cudaFuncAttributeMaxDynamicSharedMemorySize, GEMM_SMEM_BYTES);
        mma_gemm_kernel<true, true><<<grid, 256, GEMM_SMEM_BYTES>>>(A, B, bias, C, M, N, K, sA, sB, sBias, sC);
    }
}

static void tr(const float* in, float* out, int R, int C, int batch)
{
    dim3 grid(cdiv(C, 32), cdiv(R, 32), batch);
    transpose_kernel<<<grid, dim3(32, 8)>>>(in, out, R, C);
}

extern "C" void kernel_launch(void* const* d_in, const int* in_sizes, int n_in,
                              void* d_out, int out_size)
{
    (void)in_sizes; (void)n_in; (void)out_size;

    const float* x        = (const float*)d_in[0];
    const float* pre_Wq   = (const float*)d_in[1];
    const float* pre_Wk   = (const float*)d_in[2];
    const float* pre_Wv   = (const float*)d_in[3];
    const float* ln1_g    = (const float*)d_in[4];
    const float* ln1_b    = (const float*)d_in[5];
    const float* pre_W1   = (const float*)d_in[6];
    const float* pre_b1   = (const float*)d_in[7];
    const float* pre_W2   = (const float*)d_in[8];
    const float* pre_b2   = (const float*)d_in[9];
    const float* ln4p_g   = (const float*)d_in[10];
    const float* ln4p_b   = (const float*)d_in[11];
    const float* cross_Wq = (const float*)d_in[12];
    const float* cross_Wk = (const float*)d_in[13];
    const float* cross_Wv = (const float*)d_in[14];
    const float* ln2_g    = (const float*)d_in[15];
    const float* ln2_b    = (const float*)d_in[16];
    const float* post_Wq  = (const float*)d_in[17];
    const float* post_Wk  = (const float*)d_in[18];
    const float* post_Wv  = (const float*)d_in[19];
    const float* ln3_g    = (const float*)d_in[20];
    const float* ln3_b    = (const float*)d_in[21];
    const float* post_W1  = (const float*)d_in[22];
    const float* post_b1  = (const float*)d_in[23];
    const float* post_W2  = (const float*)d_in[24];
    const float* post_b2  = (const float*)d_in[25];
    const float* ln4_g    = (const float*)d_in[26];
    const float* ln4_b    = (const float*)d_in[27];
    float* out = (float*)d_out;

    float *bufA, *bufB, *bufC, *q, *k, *scores, *xT, *wT;
    cudaGetSymbolAddress((void**)&bufA, g_bufA);
    cudaGetSymbolAddress((void**)&bufB, g_bufB);
    cudaGetSymbolAddress((void**)&bufC, g_bufC);
    cudaGetSymbolAddress((void**)&q, g_q);
    cudaGetSymbolAddress((void**)&k, g_k);
    cudaGetSymbolAddress((void**)&scores, g_scores);
    cudaGetSymbolAddress((void**)&xT, g_xT);
    cudaGetSymbolAddress((void**)&wT, g_wT);
    float* xt_pad = scores;

    // transposed-weight layout inside wT
    const long SZ_QK = (long)SS * DD4 * DD;
    const long SZ_V  = (long)SS * DD * DD;
    float* preWqT  = wT;
    float* preWkT  = preWqT  + SZ_QK;
    float* preWvT  = preWkT  + SZ_QK;
    float* preW1T  = preWvT  + SZ_V;
    float* preW2T  = preW1T  + SZ_QK;
    float* postWqT = preW2T  + SZ_QK;
    float* postWkT = postWqT + SZ_QK;
    float* postWvT = postWkT + SZ_QK;
    float* postW1T = postWvT + SZ_V;
    float* postW2T = postW1T + SZ_QK;
    float* crossWqT = postW2T + SZ_QK;
    float* crossWkT = crossWqT + (long)DD4 * DD;
    float* crossWvT = crossWkT + (long)DD4 * DD;

    const float scale = 1.0f / sqrtf((float)DD4);
    const long LD  = (long)LL * DD;
    const long LD4 = (long)LL * DD4;

    // ---------------- weight transposes (NT operands) ----------------
    tr(pre_Wq,  preWqT,  DD,  DD4, SS);
    tr(pre_Wk,  preWkT,  DD,  DD4, SS);
    tr(pre_Wv,  preWvT,  DD,  DD,  SS);
    tr(pre_W1,  preW1T,  DD,  DD4, SS);
    tr(pre_W2,  preW2T,  DD4, DD,  SS);
    tr(post_Wq, postWqT, DD,  DD4, SS);
    tr(post_Wk, postWkT, DD,  DD4, SS);
    tr(post_Wv, postWvT, DD,  DD,  SS);
    tr(post_W1, postW1T, DD,  DD4, SS);
    tr(post_W2, postW2T, DD4, DD,  SS);
    tr(cross_Wq, crossWqT, DD, DD4, 1);
    tr(cross_Wk, crossWkT, DD, DD4, 1);
    tr(cross_Wv, crossWvT, DD, DD,  1);

    // ================= pre_self_step attention =================
    tgemm(x, preWqT, nullptr, q, LL, DD4, DD, SS, LD, (long)DD4 * DD, 0, LD4, 0);
    tgemm(x, preWkT, nullptr, k, LL, DD4, DD, SS, LD, (long)DD4 * DD, 0, LD4, 0);
    tgemm(q, k, nullptr, scores, LL, LL, DD4, SS, LD4, LD4, 0, (long)LL * LL, 0);
    softmax_kernel<<<SS * LL, 256>>>(scores, LL, LL, scale);
    tr(x, xT, LL, DD, SS);                       // xT: [S, D, L]
    tgemm(scores, xT, nullptr, bufB, LL, DD, LL, SS,
          (long)LL * LL, (long)DD * LL, 0, LD, 0);
    tgemm(bufB, preWvT, nullptr, bufC, LL, DD, DD, SS, LD, (long)DD * DD, 0, LD, 0);
    ln_kernel<<<SS * LL, 256>>>(x, bufC, ln1_g, ln1_b, bufA, LL, LL, 1, LL, 1, LL, 1, DD);

    // ================= pre_mlp =================
    tgemm(bufA, preW1T, pre_b1, q, LL, DD4, DD, SS, LD, (long)DD4 * DD, DD4, LD4, 2);
    tgemm(q, preW2T, pre_b2, bufC, LL, DD, DD4, SS, LD4, (long)DD * DD4, DD, LD, 1);
    ln_kernel<<<SS * LL, 256>>>(bufA, bufC, ln4p_g, ln4p_b, xt_pad, LL, LL, 1, LL, 1, 1, SP, DD);
    zero_pad_kernel<<<cdiv(LL * (SP - SS) * DD, 256), 256>>>(xt_pad);

    // ================= cross_step attention (padded S -> SP) =================
    tgemm(xt_pad, crossWqT, nullptr, q, LL * SP, DD4, DD, 1, 0, 0, 0, 0, 0);
    tgemm(xt_pad, crossWkT, nullptr, k, LL * SP, DD4, DD, 1, 0, 0, 0, 0, 0);
    tgemm(q, k, nullptr, bufB, SP, SP, DD4, LL,
          (long)SP * DD4, (long)SP * DD4, 0, (long)SP * SP, 0);
    softmax_kernel<<<LL * SP, 256>>>(bufB, SS, SP, scale);
    tr(xt_pad, xT, SP, DD, LL);                  // xtpadT: [L, D, SP]
    tgemm(bufB, xT, nullptr, bufC, SS, DD, SP, LL,
          (long)SP * SP, (long)DD * SP, 0, (long)SS * DD, 0);
    tgemm(bufC, crossWvT, nullptr, bufB, LL * SS, DD, DD, 1, 0, 0, 0, 0, 0);
    ln_kernel<<<LL * SS, 256>>>(xt_pad, bufB, ln2_g, ln2_b, bufA, SS, SP, 1, SS, 1, 1, LL, 0);

    // ================= post_self_step attention =================
    tgemm(bufA, postWqT, nullptr, q, LL, DD4, DD, SS, LD, (long)DD4 * DD, 0, LD4, 0);
    tgemm(bufA, postWkT, nullptr, k, LL, DD4, DD, SS, LD, (long)DD4 * DD, 0, LD4, 0);
    tgemm(q, k, nullptr, scores, LL, LL, DD4, SS, LD4, LD4, 0, (long)LL * LL, 0);
    softmax_kernel<<<SS * LL, 256>>>(scores, LL, LL, scale);
    tr(bufA, xT, LL, DD, SS);
    tgemm(scores, xT, nullptr, bufB, LL, DD, LL, SS,
          (long)LL * LL, (long)DD * LL, 0, LD, 0);
    tgemm(bufB, postWvT, nullptr, bufC, LL, DD, DD, SS, LD, (long)DD * DD, 0, LD, 0);
    ln_kernel<<<SS * LL, 256>>>(bufA, bufC, ln3_g, ln3_b, bufB, LL, LL, 1, LL, 1, LL, 1, DD);

    // ================= post_mlp =================
    tgemm(bufB, postW1T, post_b1, q, LL, DD4, DD, SS, LD, (long)DD4 * DD, DD4, LD4, 2);
    tgemm(q, postW2T, post_b2, bufC, LL, DD, DD4, SS, LD4, (long)DD * DD4, DD, LD, 1);
    ln_kernel<<<SS * LL, 256>>>(bufB, bufC, ln4_g, ln4_b, out, LL, LL, 1, LL, 1, LL, 1, DD);
}

// round 7
// speedup vs baseline: 1.0067x; 1.0067x over previous
#include <cuda_runtime.h>
#include <math.h>
#include <stdint.h>

// Problem dims
#define SS 50
#define LL 1024
#define DD 768
#define DD4 192
#define SP 64   // padded step dim for cross attention

// ---------------- static scratch (alloc-free rule) ----------------
__device__ float g_bufA[(size_t)SS * LL * DD];
__device__ float g_bufB[(size_t)SS * LL * DD];
__device__ float g_bufC[(size_t)SS * LL * DD];
__device__ float g_q[(size_t)LL * SP * DD4];
__device__ float g_k[(size_t)LL * SP * DD4];
__device__ float g_scores[(size_t)SS * LL * LL];   // also xt_pad [LL,SP,DD]
__device__ float g_xT[(size_t)LL * DD * SP];       // xT / xtpadT scratch
__device__ float g_wT[118849536];                  // transposed weights

// =============== helpers =====================
__device__ __forceinline__ uint32_t smem_u32(const void* p) {
    uint32_t a;
    asm("{ .reg .u64 t; cvta.to.shared.u64 t, %1; cvt.u32.u64 %0, t; }" : "=r"(a) : "l"(p));
    return a;
}
__device__ __forceinline__ float f2tf(float f) {
    uint32_t r;
    asm("cvt.rna.tf32.f32 %0, %1;" : "=r"(r) : "f"(f));
    return __uint_as_float(r);
}
__device__ __forceinline__ void mma_tf32(float* d, const uint32_t* a, const uint32_t* b) {
    asm volatile(
        "mma.sync.aligned.m16n8k8.row.col.f32.tf32.tf32.f32 "
        "{%0,%1,%2,%3}, {%4,%5,%6,%7}, {%8,%9}, {%0,%1,%2,%3};\n"
        : "+f"(d[0]), "+f"(d[1]), "+f"(d[2]), "+f"(d[3])
        : "r"(a[0]), "r"(a[1]), "r"(a[2]), "r"(a[3]),
          "r"(b[0]), "r"(b[1]));
}
__device__ __forceinline__ void cp_async16(uint32_t smem_addr, const void* gptr, uint32_t src_bytes) {
    asm volatile("cp.async.ca.shared.global [%0], [%1], 16, %2;"
                 :: "r"(smem_addr), "l"(gptr), "r"(src_bytes));
}
#define CP_COMMIT() asm volatile("cp.async.commit_group;" ::: "memory")
#define CP_WAIT2()  asm volatile("cp.async.wait_group 2;" ::: "memory")

// =================================================================
// cp.async-pipelined TF32 NT GEMM (mma.sync m16n8k8)
// Operands are ALREADY tf32-truncated by producers -> pure LDS+MMA loop.
// C[b] = A[b] @ B[b]^T (+bias)(+relu)(+tf32-truncate on store)
// A: [M,K] row-major. B: [N,K] row-major. K % 16 == 0, N even.
// =================================================================
#define RSTRIDE 20
#define OPW     (128 * RSTRIDE)
#define STGW    (2 * OPW)
#define NSTAGE  4
#define GEMM_SMEM_BYTES (NSTAGE * STGW * 4)   // 81920

template<bool BIAS, bool RELU, bool CVT>
__global__ __launch_bounds__(256, 2)
void mma_gemm_kernel(const float* __restrict__ Ab, const float* __restrict__ Bb,
                     const float* __restrict__ biasb, float* __restrict__ Cb,
                     int M, int N, int K,
                     long sA, long sB, long sBias, long sC)
{
    extern __shared__ __align__(16) uint32_t sm[];
    const uint32_t smb = smem_u32(sm);

    const int b = blockIdx.z;
    const float* A = Ab + (long)b * sA;
    const float* B = Bb + (long)b * sB;
    float* C = Cb + (long)b * sC;

    const int brow = blockIdx.y * 128;
    const int bcol = blockIdx.x * 128;
    const int tid = threadIdx.x;
    const int wid = tid >> 5;
    const int lane = tid & 31;
    const int g = lane >> 2;
    const int c = lane & 3;
    const int warp_m = (wid & 1) * 64;
    const int warp_n = (wid >> 1) * 32;

    const int nkt = K >> 4;

    float acc[4][4][4];
    #pragma unroll
    for (int i = 0; i < 4; i++)
        #pragma unroll
        for (int j = 0; j < 4; j++)
            #pragma unroll
            for (int r = 0; r < 4; r++)
                acc[i][j][r] = 0.0f;

    auto issue_stage = [&](int kt) {
        if (kt < nkt) {
            int k0 = kt << 4;
            uint32_t sbase = smb + ((kt & (NSTAGE - 1)) * STGW) * 4;
            #pragma unroll
            for (int i = 0; i < 4; i++) {
                int idx = i * 256 + tid;
                int row = idx >> 2;
                int q = idx & 3;
                if (row < 128) {
                    int gr = brow + row;
                    const float* gp = A + (long)gr * K + k0 + q * 4;
                    uint32_t dst = sbase + (row * RSTRIDE + q * 4) * 4;
                    cp_async16(dst, gp, (gr < M) ? 16u : 0u);
                } else {
                    int r = row - 128;
                    int gn = bcol + r;
                    const float* gp = B + (long)gn * K + k0 + q * 4;
                    uint32_t dst = sbase + (OPW + r * RSTRIDE + q * 4) * 4;
                    cp_async16(dst, gp, (gn < N) ? 16u : 0u);
                }
            }
        }
        CP_COMMIT();
    };

    issue_stage(0);
    issue_stage(1);
    issue_stage(2);

    for (int kt = 0; kt < nkt; kt++) {
        CP_WAIT2();
        __syncthreads();
        issue_stage(kt + 3);

        const uint32_t* As = sm + (kt & (NSTAGE - 1)) * STGW;
        const uint32_t* Bs = As + OPW;

        #pragma unroll
        for (int ks = 0; ks < 16; ks += 8) {
            uint32_t af[4][4], bf[4][2];
            #pragma unroll
            for (int am = 0; am < 4; am++) {
                int r0 = warp_m + am * 16 + g;
                af[am][0] = As[r0 * RSTRIDE + ks + c];
                af[am][1] = As[(r0 + 8) * RSTRIDE + ks + c];
                af[am][2] = As[r0 * RSTRIDE + ks + c + 4];
                af[am][3] = As[(r0 + 8) * RSTRIDE + ks + c + 4];
            }
            #pragma unroll
            for (int bn = 0; bn < 4; bn++) {
                int col = warp_n + bn * 8 + g;
                bf[bn][0] = Bs[col * RSTRIDE + ks + c];
                bf[bn][1] = Bs[col * RSTRIDE + ks + c + 4];
            }
            #pragma unroll
            for (int am = 0; am < 4; am++)
                #pragma unroll
                for (int bn = 0; bn < 4; bn++)
                    mma_tf32(acc[am][bn], af[am], bf[bn]);
        }
    }

    // ---- epilogue ----
    #pragma unroll
    for (int am = 0; am < 4; am++) {
        int row0 = brow + warp_m + am * 16 + g;
        #pragma unroll
        for (int bn = 0; bn < 4; bn++) {
            int col = bcol + warp_n + bn * 8 + c * 2;
            if (col >= N) continue;
            float v0 = acc[am][bn][0], v1 = acc[am][bn][1];
            float v2 = acc[am][bn][2], v3 = acc[am][bn][3];
            if (BIAS) {
                float b0 = biasb[(long)b * sBias + col];
                float b1 = biasb[(long)b * sBias + col + 1];
                v0 += b0; v1 += b1; v2 += b0; v3 += b1;
            }
            if (RELU) {
                v0 = fmaxf(v0, 0.f); v1 = fmaxf(v1, 0.f);
                v2 = fmaxf(v2, 0.f); v3 = fmaxf(v3, 0.f);
            }
            if (CVT) {
                v0 = f2tf(v0); v1 = f2tf(v1); v2 = f2tf(v2); v3 = f2tf(v3);
            }
            if (row0 < M)     *(float2*)&C[(long)row0 * N + col]       = make_float2(v0, v1);
            if (row0 + 8 < M) *(float2*)&C[(long)(row0 + 8) * N + col] = make_float2(v2, v3);
        }
    }
}

// ---------------- tiled transpose (+tf32 truncate): [B,R,C] -> [B,C,R] --------
__global__ __launch_bounds__(256)
void transpose_kernel(const float* __restrict__ in, float* __restrict__ out, int R, int C)
{
    __shared__ float t[32][33];
    long z = blockIdx.z;
    const float* src = in + z * (long)R * C;
    float* dst = out + z * (long)R * C;
    int c0 = blockIdx.x * 32, r0 = blockIdx.y * 32;
    int tx = threadIdx.x, ty = threadIdx.y;
    #pragma unroll
    for (int j = ty; j < 32; j += 8) {
        int r = r0 + j, cc = c0 + tx;
        if (r < R && cc < C) t[j][tx] = src[(long)r * C + cc];
    }
    __syncthreads();
    #pragma unroll
    for (int j = ty; j < 32; j += 8) {
        int cc = c0 + j, r = r0 + tx;
        if (r < R && cc < C) dst[(long)cc * R + r] = f2tf(t[tx][j]);
    }
}

// ---------------- elementwise tf32 truncate copy (float4) ----------------
__global__ __launch_bounds__(256)
void cvt_kernel(const float* __restrict__ in, float* __restrict__ out, long n4)
{
    long i = (long)blockIdx.x * 256 + threadIdx.x;
    if (i >= n4) return;
    float4 v = ((const float4*)in)[i];
    v.x = f2tf(v.x); v.y = f2tf(v.y); v.z = f2tf(v.z); v.w = f2tf(v.w);
    ((float4*)out)[i] = v;
}

// ---------------- row softmax (pre-scale, padded stride, tf32 out) ----------
__global__ __launch_bounds__(256)
void softmax_kernel(float* __restrict__ data, int n, int stride, float scale)
{
    long row = blockIdx.x;
    float* p = data + row * (long)stride;
    int t = threadIdx.x;
    int w = t >> 5, lane = t & 31;

    float loc[4];
    int cnt = 0;
    float mx = -3.0e38f;
    for (int i = t; i < n; i += 256) {
        float v = p[i] * scale;
        loc[cnt++] = v;
        mx = fmaxf(mx, v);
    }
    #pragma unroll
    for (int o = 16; o > 0; o >>= 1) mx = fmaxf(mx, __shfl_xor_sync(0xffffffffu, mx, o));
    __shared__ float red[8];
    if (lane == 0) red[w] = mx;
    __syncthreads();
    if (t < 8) {
        float v = red[t];
        #pragma unroll
        for (int o = 4; o > 0; o >>= 1) v = fmaxf(v, __shfl_xor_sync(0xffu, v, o));
        if (t == 0) red[0] = v;
    }
    __syncthreads();
    mx = red[0];
    __syncthreads();

    float sum = 0.0f;
    for (int cc = 0; cc < cnt; cc++) {
        float e = __expf(loc[cc] - mx);
        loc[cc] = e;
        sum += e;
    }
    #pragma unroll
    for (int o = 16; o > 0; o >>= 1) sum += __shfl_xor_sync(0xffffffffu, sum, o);
    if (lane == 0) red[w] = sum;
    __syncthreads();
    if (t < 8) {
        float v = red[t];
        #pragma unroll
        for (int o = 4; o > 0; o >>= 1) v += __shfl_xor_sync(0xffu, v, o);
        if (t == 0) red[0] = v;
    }
    __syncthreads();
    float inv = 1.0f / red[0];

    cnt = 0;
    for (int i = t; i < n; i += 256) p[i] = f2tf(loc[cnt++] * inv);
    for (int i = t; i < stride; i += 256) if (i >= n) p[i] = 0.0f;
}

// ---------------- fused residual + LayerNorm, generalized index mapping ----------
__global__ __launch_bounds__(256)
void ln_kernel(const float* __restrict__ resid, const float* __restrict__ h,
               const float* __restrict__ gam, const float* __restrict__ bet,
               float* __restrict__ out, int J,
               long ri, long rj, long hi, long hj, long oi, long oj, long gstride,
               int cvt_out)
{
    long b = blockIdx.x;
    long i = b / J, j = b % J;
    const float* r  = resid + (i * ri + j * rj) * DD;
    const float* hh = h     + (i * hi + j * hj) * DD;
    float* op       = out   + (i * oi + j * oj) * DD;
    const float* gp = gam + i * gstride;
    const float* bp = bet + i * gstride;
    int t = threadIdx.x;
    int w = t >> 5, lane = t & 31;

    float v[3];
    float s = 0.0f, s2 = 0.0f;
    #pragma unroll
    for (int k = 0; k < 3; k++) {
        int d = t + k * 256;
        float val = r[d] + hh[d];
        v[k] = val;
        s += val;
        s2 += val * val;
    }
    #pragma unroll
    for (int o = 16; o > 0; o >>= 1) {
        s  += __shfl_xor_sync(0xffffffffu, s, o);
        s2 += __shfl_xor_sync(0xffffffffu, s2, o);
    }
    __shared__ float rs[8], rs2[8];
    if (lane == 0) { rs[w] = s; rs2[w] = s2; }
    __syncthreads();
    if (t < 8) {
        s = rs[t]; s2 = rs2[t];
        #pragma unroll
        for (int o = 4; o > 0; o >>= 1) {
            s  += __shfl_xor_sync(0xffu, s, o);
            s2 += __shfl_xor_sync(0xffu, s2, o);
        }
        if (t == 0) { rs[0] = s; rs2[0] = s2; }
    }
    __syncthreads();
    float mean = rs[0] * (1.0f / DD);
    float var  = rs2[0] * (1.0f / DD) - mean * mean;
    float inv  = rsqrtf(var + 1e-5f);

    #pragma unroll
    for (int k = 0; k < 3; k++) {
        int d = t + k * 256;
        float o = (v[k] - mean) * inv * gp[d] + bp[d];
        op[d] = cvt_out ? f2tf(o) : o;
    }
}

// ---------------- zero the pad rows of xt_pad [LL, SP, DD] ----------------
__global__ __launch_bounds__(256)
void zero_pad_kernel(float* __restrict__ xt)
{
    long idx = (long)blockIdx.x * 256 + threadIdx.x;
    const long per_l = (long)(SP - SS) * DD;
    const long total = (long)LL * per_l;
    if (idx >= total) return;
    long l = idx / per_l;
    long off = idx % per_l;
    xt[((long)l * SP + SS) * DD + off] = 0.0f;
}

// ---------------- launch plumbing ----------------
static inline int cdiv(int a, int b) { return (a + b - 1) / b; }

// mode: 0 = plain, 1 = bias, 2 = bias+relu+cvt, 3 = cvt
static void tgemm(const float* A, const float* B, const float* bias, float* C,
                  int M, int N, int K, int batch,
                  long sA, long sB, long sBias, long sC, int mode)
{
    dim3 grid(cdiv(N, 128), cdiv(M, 128), batch);
    if (mode == 0) {
        cudaFuncSetAttribute(mma_gemm_kernel<false, false, false>,
                             cudaFuncAttributeMaxDynamicSharedMemorySize, GEMM_SMEM_BYTES);
        mma_gemm_kernel<false, false, false><<<grid, 256, GEMM_SMEM_BYTES>>>(A, B, bias, C, M, N, K, sA, sB, sBias, sC);
    } else if (mode == 1) {
        cudaFuncSetAttribute(mma_gemm_kernel<true, false, false>,
                             cudaFuncAttributeMaxDynamicSharedMemorySize, GEMM_SMEM_BYTES);
        mma_gemm_kernel<true, false, false><<<grid, 256, GEMM_SMEM_BYTES>>>(A, B, bias, C, M, N, K, sA, sB, sBias, sC);
    } else if (mode == 2) {
        cudaFuncSetAttribute(mma_gemm_kernel<true, true, true>,
                             cudaFuncAttributeMaxDynamicSharedMemorySize, GEMM_SMEM_BYTES);
        mma_gemm_kernel<true, true, true><<<grid, 256, GEMM_SMEM_BYTES>>>(A, B, bias, C, M, N, K, sA, sB, sBias, sC);
    } else {
        cudaFuncSetAttribute(mma_gemm_kernel<false, false, true>,
                             cudaFuncAttributeMaxDynamicSharedMemorySize, GEMM_SMEM_BYTES);
        mma_gemm_kernel<false, false, true><<<grid, 256, GEMM_SMEM_BYTES>>>(A, B, bias, C, M, N, K, sA, sB, sBias, sC);
    }
}

static void tr(const float* in, float* out, int R, int C, int batch)
{
    dim3 grid(cdiv(C, 32), cdiv(R, 32), batch);
    transpose_kernel<<<grid, dim3(32, 8)>>>(in, out, R, C);
}

extern "C" void kernel_launch(void* const* d_in, const int* in_sizes, int n_in,
                              void* d_out, int out_size)
{
    (void)in_sizes; (void)n_in; (void)out_size;

    const float* x        = (const float*)d_in[0];
    const float* pre_Wq   = (const float*)d_in[1];
    const float* pre_Wk   = (const float*)d_in[2];
    const float* pre_Wv   = (const float*)d_in[3];
    const float* ln1_g    = (const float*)d_in[4];
    const float* ln1_b    = (const float*)d_in[5];
    const float* pre_W1   = (const float*)d_in[6];
    const float* pre_b1   = (const float*)d_in[7];
    const float* pre_W2   = (const float*)d_in[8];
    const float* pre_b2   = (const float*)d_in[9];
    const float* ln4p_g   = (const float*)d_in[10];
    const float* ln4p_b   = (const float*)d_in[11];
    const float* cross_Wq = (const float*)d_in[12];
    const float* cross_Wk = (const float*)d_in[13];
    const float* cross_Wv = (const float*)d_in[14];
    const float* ln2_g    = (const float*)d_in[15];
    const float* ln2_b    = (const float*)d_in[16];
    const float* post_Wq  = (const float*)d_in[17];
    const float* post_Wk  = (const float*)d_in[18];
    const float* post_Wv  = (const float*)d_in[19];
    const float* ln3_g    = (const float*)d_in[20];
    const float* ln3_b    = (const float*)d_in[21];
    const float* post_W1  = (const float*)d_in[22];
    const float* post_b1  = (const float*)d_in[23];
    const float* post_W2  = (const float*)d_in[24];
    const float* post_b2  = (const float*)d_in[25];
    const float* ln4_g    = (const float*)d_in[26];
    const float* ln4_b    = (const float*)d_in[27];
    float* out = (float*)d_out;

    float *bufA, *bufB, *bufC, *q, *k, *scores, *xT, *wT;
    cudaGetSymbolAddress((void**)&bufA, g_bufA);
    cudaGetSymbolAddress((void**)&bufB, g_bufB);
    cudaGetSymbolAddress((void**)&bufC, g_bufC);
    cudaGetSymbolAddress((void**)&q, g_q);
    cudaGetSymbolAddress((void**)&k, g_k);
    cudaGetSymbolAddress((void**)&scores, g_scores);
    cudaGetSymbolAddress((void**)&xT, g_xT);
    cudaGetSymbolAddress((void**)&wT, g_wT);
    float* xt_pad = scores;

    const long SZ_QK = (long)SS * DD4 * DD;
    const long SZ_V  = (long)SS * DD * DD;
    float* preWqT  = wT;
    float* preWkT  = preWqT  + SZ_QK;
    float* preWvT  = preWkT  + SZ_QK;
    float* preW1T  = preWvT  + SZ_V;
    float* preW2T  = preW1T  + SZ_QK;
    float* postWqT = preW2T  + SZ_QK;
    float* postWkT = postWqT + SZ_QK;
    float* postWvT = postWkT + SZ_QK;
    float* postW1T = postWvT + SZ_V;
    float* postW2T = postW1T + SZ_QK;
    float* crossWqT = postW2T + SZ_QK;
    float* crossWkT = crossWqT + (long)DD4 * DD;
    float* crossWvT = crossWkT + (long)DD4 * DD;

    const float scale = 1.0f / sqrtf((float)DD4);
    const long LD  = (long)LL * DD;
    const long LD4 = (long)LL * DD4;

    // ---------------- weight transposes (tf32-truncated, NT operands) --------
    tr(pre_Wq,  preWqT,  DD,  DD4, SS);
    tr(pre_Wk,  preWkT,  DD,  DD4, SS);
    tr(pre_Wv,  preWvT,  DD,  DD,  SS);
    tr(pre_W1,  preW1T,  DD,  DD4, SS);
    tr(pre_W2,  preW2T,  DD4, DD,  SS);
    tr(post_Wq, postWqT, DD,  DD4, SS);
    tr(post_Wk, postWkT, DD,  DD4, SS);
    tr(post_Wv, postWvT, DD,  DD,  SS);
    tr(post_W1, postW1T, DD,  DD4, SS);
    tr(post_W2, postW2T, DD4, DD,  SS);
    tr(cross_Wq, crossWqT, DD, DD4, 1);
    tr(cross_Wk, crossWkT, DD, DD4, 1);
    tr(cross_Wv, crossWvT, DD, DD,  1);

    // xc = tf32(x)  (A-operand for pre q/k projections; bufB is free until a@x)
    float* xc = bufB;
    cvt_kernel<<<cdiv((int)(SS * LD / 4), 256), 256>>>(x, xc, SS * LD / 4);

    // ================= pre_self_step attention =================
    tgemm(xc, preWqT, nullptr, q, LL, DD4, DD, SS, LD, (long)DD4 * DD, 0, LD4, 3);
    tgemm(xc, preWkT, nullptr, k, LL, DD4, DD, SS, LD, (long)DD4 * DD, 0, LD4, 3);
    tgemm(q, k, nullptr, scores, LL, LL, DD4, SS, LD4, LD4, 0, (long)LL * LL, 0);
    softmax_kernel<<<SS * LL, 256>>>(scores, LL, LL, scale);
    tr(x, xT, LL, DD, SS);                       // xT: [S, D, L], truncated
    tgemm(scores, xT, nullptr, bufB, LL, DD, LL, SS,
          (long)LL * LL, (long)DD * LL, 0, LD, 3);
    tgemm(bufB, preWvT, nullptr, bufC, LL, DD, DD, SS, LD, (long)DD * DD, 0, LD, 0);
    ln_kernel<<<SS * LL, 256>>>(x, bufC, ln1_g, ln1_b, bufA, LL, LL, 1, LL, 1, LL, 1, DD, 1);

    // ================= pre_mlp =================
    tgemm(bufA, preW1T, pre_b1, q, LL, DD4, DD, SS, LD, (long)DD4 * DD, DD4, LD4, 2);
    tgemm(q, preW2T, pre_b2, bufC, LL, DD, DD4, SS, LD4, (long)DD * DD4, DD, LD, 1);
    ln_kernel<<<SS * LL, 256>>>(bufA, bufC, ln4p_g, ln4p_b, xt_pad, LL, LL, 1, LL, 1, 1, SP, DD, 1);
    zero_pad_kernel<<<cdiv(LL * (SP - SS) * DD, 256), 256>>>(xt_pad);

    // ================= cross_step attention (padded S -> SP) =================
    tgemm(xt_pad, crossWqT, nullptr, q, LL * SP, DD4, DD, 1, 0, 0, 0, 0, 3);
    tgemm(xt_pad, crossWkT, nullptr, k, LL * SP, DD4, DD, 1, 0, 0, 0, 0, 3);
    tgemm(q, k, nullptr, bufB, SP, SP, DD4, LL,
          (long)SP * DD4, (long)SP * DD4, 0, (long)SP * SP, 0);
    softmax_kernel<<<LL * SP, 256>>>(bufB, SS, SP, scale);
    tr(xt_pad, xT, SP, DD, LL);                  // xtpadT: [L, D, SP], truncated
    tgemm(bufB, xT, nullptr, bufC, SS, DD, SP, LL,
          (long)SP * SP, (long)DD * SP, 0, (long)SS * DD, 3);
    tgemm(bufC, crossWvT, nullptr, bufB, LL * SS, DD, DD, 1, 0, 0, 0, 0, 0);
    ln_kernel<<<LL * SS, 256>>>(xt_pad, bufB, ln2_g, ln2_b, bufA, SS, SP, 1, SS, 1, 1, LL, 0, 1);

    // ================= post_self_step attention =================
    tgemm(bufA, postWqT, nullptr, q, LL, DD4, DD, SS, LD, (long)DD4 * DD, 0, LD4, 3);
    tgemm(bufA, postWkT, nullptr, k, LL, DD4, DD, SS, LD, (long)DD4 * DD, 0, LD4, 3);
    tgemm(q, k, nullptr, scores, LL, LL, DD4, SS, LD4, LD4, 0, (long)LL * LL, 0);
    softmax_kernel<<<SS * LL, 256>>>(scores, LL, LL, scale);
    tr(bufA, xT, LL, DD, SS);
    tgemm(scores, xT, nullptr, bufB, LL, DD, LL, SS,
          (long)LL * LL, (long)DD * LL, 0, LD, 3);
    tgemm(bufB, postWvT, nullptr, bufC, LL, DD, DD, SS, LD, (long)DD * DD, 0, LD, 0);
    ln_kernel<<<SS * LL, 256>>>(bufA, bufC, ln3_g, ln3_b, bufB, LL, LL, 1, LL, 1, LL, 1, DD, 1);

    // ================= post_mlp =================
    tgemm(bufB, postW1T, post_b1, q, LL, DD4, DD, SS, LD, (long)DD4 * DD, DD4, LD4, 2);
    tgemm(q, postW2T, post_b2, bufC, LL, DD, DD4, SS, LD4, (long)DD * DD4, DD, LD, 1);
    ln_kernel<<<SS * LL, 256>>>(bufB, bufC, ln4_g, ln4_b, out, LL, LL, 1, LL, 1, LL, 1, DD, 0);
}

// round 8
// speedup vs baseline: 1.0899x; 1.0827x over previous
#include <cuda_runtime.h>
#include <math.h>
#include <stdint.h>

// Problem dims
#define SS 50
#define LL 1024
#define DD 768
#define DD4 192
#define SP 64   // padded step dim for cross attention
#define QKN 384 // fused q||k projection width

// ---------------- static scratch (alloc-free rule) ----------------
__device__ float g_bufA[(size_t)SS * LL * DD];
__device__ float g_bufB[(size_t)SS * LL * DD];
__device__ float g_bufC[(size_t)SS * LL * DD];
__device__ float g_qk[(size_t)LL * SP * QKN];      // fused q/k outputs (25.2M)
__device__ float g_scores[(size_t)SS * LL * LL];   // also xt_pad [LL,SP,DD]
__device__ float g_wT[118849536];                  // concat/truncated weights

// =============== helpers =====================
__device__ __forceinline__ uint32_t smem_u32(const void* p) {
    uint32_t a;
    asm("{ .reg .u64 t; cvta.to.shared.u64 t, %1; cvt.u32.u64 %0, t; }" : "=r"(a) : "l"(p));
    return a;
}
__device__ __forceinline__ float f2tf(float f) {
    uint32_t r;
    asm("cvt.rna.tf32.f32 %0, %1;" : "=r"(r) : "f"(f));
    return __uint_as_float(r);
}
__device__ __forceinline__ void mma_tf32(float* d, const uint32_t* a, const uint32_t* b) {
    asm volatile(
        "mma.sync.aligned.m16n8k8.row.col.f32.tf32.tf32.f32 "
        "{%0,%1,%2,%3}, {%4,%5,%6,%7}, {%8,%9}, {%0,%1,%2,%3};\n"
        : "+f"(d[0]), "+f"(d[1]), "+f"(d[2]), "+f"(d[3])
        : "r"(a[0]), "r"(a[1]), "r"(a[2]), "r"(a[3]),
          "r"(b[0]), "r"(b[1]));
}
__device__ __forceinline__ void cp_async16(uint32_t smem_addr, const void* gptr, uint32_t src_bytes) {
    asm volatile("cp.async.ca.shared.global [%0], [%1], 16, %2;"
                 :: "r"(smem_addr), "l"(gptr), "r"(src_bytes));
}
#define CP_COMMIT() asm volatile("cp.async.commit_group;" ::: "memory")
#define CP_WAIT2()  asm volatile("cp.async.wait_group 2;" ::: "memory")

// =================================================================
// cp.async-pipelined TF32 GEMM (mma.sync m16n8k8), BM=256 x BN=128
// Operands pre-truncated to tf32 by producers.
// NT: C = A @ B^T  (B [N,K] row-major, ldb)
// NN: C = A @ B    (B [K,N] row-major, ldb)
// MODE: 0 plain, 1 +bias, 2 +bias+relu+cvt, 3 +cvt
// =================================================================
#define BMt 256
#define BNt 128
#define ARS 20                 // A smem row stride (words)
#define BRS_NT 20
#define BRS_NN 132
#define AWORDS (BMt * ARS)     // 5120
#define BWORDS 2560            // max(128*20, 16*132)
#define STGW (AWORDS + BWORDS) // 7680
#define NSTAGE 4
#define GEMM_SMEM_BYTES (NSTAGE * STGW * 4)  // 122880

template<bool TRANSB, int MODE>
__global__ __launch_bounds__(512, 1)
void mma_gemm_kernel(const float* __restrict__ Ab, const float* __restrict__ Bb,
                     const float* __restrict__ biasb, float* __restrict__ Cb,
                     int M, int N, int K, int lda, int ldb, int ldc,
                     long sA, long sB, long sBias, long sC)
{
    extern __shared__ __align__(16) uint32_t sm[];
    const uint32_t smb = smem_u32(sm);

    const int b = blockIdx.z;
    const float* A = Ab + (long)b * sA;
    const float* B = Bb + (long)b * sB;
    float* C = Cb + (long)b * sC;

    const int brow = blockIdx.y * BMt;
    const int bcol = blockIdx.x * BNt;
    const int tid = threadIdx.x;
    const int wid = tid >> 5;
    const int lane = tid & 31;
    const int g = lane >> 2;
    const int c = lane & 3;
    const int warp_m = (wid & 3) * 64;    // 4 m-groups
    const int warp_n = (wid >> 2) * 32;   // 4 n-groups

    const int nkt = K >> 4;

    float acc[4][4][4];
    #pragma unroll
    for (int i = 0; i < 4; i++)
        #pragma unroll
        for (int j = 0; j < 4; j++)
            #pragma unroll
            for (int r = 0; r < 4; r++)
                acc[i][j][r] = 0.0f;

    auto issue_stage = [&](int kt) {
        if (kt < nkt) {
            int k0 = kt << 4;
            uint32_t sbase = smb + ((kt & (NSTAGE - 1)) * STGW) * 4;
            // A: 256 rows x 4 chunks = 1024 cp.asyncs (2 per thread)
            #pragma unroll
            for (int i = 0; i < 2; i++) {
                int idx = i * 512 + tid;
                int row = idx >> 2, q = idx & 3;
                int gr = brow + row;
                const float* gp = A + (long)gr * lda + k0 + q * 4;
                uint32_t dst = sbase + (row * ARS + q * 4) * 4;
                cp_async16(dst, gp, (gr < M) ? 16u : 0u);
            }
            // B: 512 cp.asyncs (1 per thread)
            if (TRANSB) {
                int row = tid >> 2, q = tid & 3;
                int gn = bcol + row;
                const float* gp = B + (long)gn * ldb + k0 + q * 4;
                uint32_t dst = sbase + (AWORDS + row * BRS_NT + q * 4) * 4;
                cp_async16(dst, gp, (gn < N) ? 16u : 0u);
            } else {
                int kk = tid >> 5;
                int nq = (tid & 31) << 2;
                int gn = bcol + nq;
                const float* gp = B + (long)(k0 + kk) * ldb + gn;
                uint32_t dst = sbase + (AWORDS + kk * BRS_NN + nq) * 4;
                cp_async16(dst, gp, (gn < N) ? 16u : 0u);
            }
        }
        CP_COMMIT();
    };

    issue_stage(0);
    issue_stage(1);
    issue_stage(2);

    for (int kt = 0; kt < nkt; kt++) {
        CP_WAIT2();
        __syncthreads();
        issue_stage(kt + 3);

        const uint32_t* As = sm + (kt & (NSTAGE - 1)) * STGW;
        const uint32_t* Bs = As + AWORDS;

        #pragma unroll
        for (int ks = 0; ks < 16; ks += 8) {
            uint32_t af[4][4], bf[4][2];
            #pragma unroll
            for (int am = 0; am < 4; am++) {
                int r0 = warp_m + am * 16 + g;
                af[am][0] = As[r0 * ARS + ks + c];
                af[am][1] = As[(r0 + 8) * ARS + ks + c];
                af[am][2] = As[r0 * ARS + ks + c + 4];
                af[am][3] = As[(r0 + 8) * ARS + ks + c + 4];
            }
            #pragma unroll
            for (int bn = 0; bn < 4; bn++) {
                int col = warp_n + bn * 8 + g;
                if (TRANSB) {
                    bf[bn][0] = Bs[col * BRS_NT + ks + c];
                    bf[bn][1] = Bs[col * BRS_NT + ks + c + 4];
                } else {
                    bf[bn][0] = Bs[(ks + c) * BRS_NN + col];
                    bf[bn][1] = Bs[(ks + c + 4) * BRS_NN + col];
                }
            }
            #pragma unroll
            for (int am = 0; am < 4; am++)
                #pragma unroll
                for (int bn = 0; bn < 4; bn++)
                    mma_tf32(acc[am][bn], af[am], bf[bn]);
        }
    }

    // ---- epilogue ----
    #pragma unroll
    for (int am = 0; am < 4; am++) {
        int row0 = brow + warp_m + am * 16 + g;
        #pragma unroll
        for (int bn = 0; bn < 4; bn++) {
            int col = bcol + warp_n + bn * 8 + c * 2;
            if (col >= N) continue;
            float v0 = acc[am][bn][0], v1 = acc[am][bn][1];
            float v2 = acc[am][bn][2], v3 = acc[am][bn][3];
            if (MODE == 1 || MODE == 2) {
                float b0 = biasb[(long)b * sBias + col];
                float b1 = biasb[(long)b * sBias + col + 1];
                v0 += b0; v1 += b1; v2 += b0; v3 += b1;
            }
            if (MODE == 2) {
                v0 = fmaxf(v0, 0.f); v1 = fmaxf(v1, 0.f);
                v2 = fmaxf(v2, 0.f); v3 = fmaxf(v3, 0.f);
            }
            if (MODE == 2 || MODE == 3) {
                v0 = f2tf(v0); v1 = f2tf(v1); v2 = f2tf(v2); v3 = f2tf(v3);
            }
            if (row0 < M)     *(float2*)&C[(long)row0 * ldc + col]       = make_float2(v0, v1);
            if (row0 + 8 < M) *(float2*)&C[(long)(row0 + 8) * ldc + col] = make_float2(v2, v3);
        }
    }
}

// ---------------- elementwise tf32 truncate copy (float4) ----------------
__global__ __launch_bounds__(256)
void cvt_kernel(const float* __restrict__ in, float* __restrict__ out, long n4)
{
    long i = (long)blockIdx.x * 256 + threadIdx.x;
    if (i >= n4) return;
    float4 v = ((const float4*)in)[i];
    v.x = f2tf(v.x); v.y = f2tf(v.y); v.z = f2tf(v.z); v.w = f2tf(v.w);
    ((float4*)out)[i] = v;
}

// ---------------- concat Wq||Wk -> [batch, D, 384], tf32-truncated --------
__global__ __launch_bounds__(256)
void concat_qk_kernel(const float* __restrict__ Wq, const float* __restrict__ Wk,
                      float* __restrict__ out, long total)
{
    long i = (long)blockIdx.x * 256 + threadIdx.x;
    if (i >= total) return;
    long j = i % QKN;
    long bd = i / QKN;             // b*D + d
    float v = (j < DD4) ? Wq[bd * DD4 + j] : Wk[bd * DD4 + (j - DD4)];
    out[i] = f2tf(v);
}

// ---------------- row softmax (pre-scale, padded stride, tf32 out) ----------
__global__ __launch_bounds__(256)
void softmax_kernel(float* __restrict__ data, int n, int stride, float scale)
{
    long row = blockIdx.x;
    float* p = data + row * (long)stride;
    int t = threadIdx.x;
    int w = t >> 5, lane = t & 31;

    float loc[4];
    int cnt = 0;
    float mx = -3.0e38f;
    for (int i = t; i < n; i += 256) {
        float v = p[i] * scale;
        loc[cnt++] = v;
        mx = fmaxf(mx, v);
    }
    #pragma unroll
    for (int o = 16; o > 0; o >>= 1) mx = fmaxf(mx, __shfl_xor_sync(0xffffffffu, mx, o));
    __shared__ float red[8];
    if (lane == 0) red[w] = mx;
    __syncthreads();
    if (t < 8) {
        float v = red[t];
        #pragma unroll
        for (int o = 4; o > 0; o >>= 1) v = fmaxf(v, __shfl_xor_sync(0xffu, v, o));
        if (t == 0) red[0] = v;
    }
    __syncthreads();
    mx = red[0];
    __syncthreads();

    float sum = 0.0f;
    for (int cc = 0; cc < cnt; cc++) {
        float e = __expf(loc[cc] - mx);
        loc[cc] = e;
        sum += e;
    }
    #pragma unroll
    for (int o = 16; o > 0; o >>= 1) sum += __shfl_xor_sync(0xffffffffu, sum, o);
    if (lane == 0) red[w] = sum;
    __syncthreads();
    if (t < 8) {
        float v = red[t];
        #pragma unroll
        for (int o = 4; o > 0; o >>= 1) v += __shfl_xor_sync(0xffu, v, o);
        if (t == 0) red[0] = v;
    }
    __syncthreads();
    float inv = 1.0f / red[0];

    cnt = 0;
    for (int i = t; i < n; i += 256) p[i] = f2tf(loc[cnt++] * inv);
    for (int i = t; i < stride; i += 256) if (i >= n) p[i] = 0.0f;
}

// ---------------- fused residual + LayerNorm, generalized index mapping ----------
__global__ __launch_bounds__(256)
void ln_kernel(const float* __restrict__ resid, const float* __restrict__ h,
               const float* __restrict__ gam, const float* __restrict__ bet,
               float* __restrict__ out, int J,
               long ri, long rj, long hi, long hj, long oi, long oj, long gstride,
               int cvt_out)
{
    long b = blockIdx.x;
    long i = b / J, j = b % J;
    const float* r  = resid + (i * ri + j * rj) * DD;
    const float* hh = h     + (i * hi + j * hj) * DD;
    float* op       = out   + (i * oi + j * oj) * DD;
    const float* gp = gam + i * gstride;
    const float* bp = bet + i * gstride;
    int t = threadIdx.x;
    int w = t >> 5, lane = t & 31;

    float v[3];
    float s = 0.0f, s2 = 0.0f;
    #pragma unroll
    for (int k = 0; k < 3; k++) {
        int d = t + k * 256;
        float val = r[d] + hh[d];
        v[k] = val;
        s += val;
        s2 += val * val;
    }
    #pragma unroll
    for (int o = 16; o > 0; o >>= 1) {
        s  += __shfl_xor_sync(0xffffffffu, s, o);
        s2 += __shfl_xor_sync(0xffffffffu, s2, o);
    }
    __shared__ float rs[8], rs2[8];
    if (lane == 0) { rs[w] = s; rs2[w] = s2; }
    __syncthreads();
    if (t < 8) {
        s = rs[t]; s2 = rs2[t];
        #pragma unroll
        for (int o = 4; o > 0; o >>= 1) {
            s  += __shfl_xor_sync(0xffu, s, o);
            s2 += __shfl_xor_sync(0xffu, s2, o);
        }
        if (t == 0) { rs[0] = s; rs2[0] = s2; }
    }
    __syncthreads();
    float mean = rs[0] * (1.0f / DD);
    float var  = rs2[0] * (1.0f / DD) - mean * mean;
    float inv  = rsqrtf(var + 1e-5f);

    #pragma unroll
    for (int k = 0; k < 3; k++) {
        int d = t + k * 256;
        float o = (v[k] - mean) * inv * gp[d] + bp[d];
        op[d] = cvt_out ? f2tf(o) : o;
    }
}

// ---------------- zero the pad rows of xt_pad [LL, SP, DD] ----------------
__global__ __launch_bounds__(256)
void zero_pad_kernel(float* __restrict__ xt)
{
    long idx = (long)blockIdx.x * 256 + threadIdx.x;
    const long per_l = (long)(SP - SS) * DD;
    const long total = (long)LL * per_l;
    if (idx >= total) return;
    long l = idx / per_l;
    long off = idx % per_l;
    xt[((long)l * SP + SS) * DD + off] = 0.0f;
}

// ---------------- launch plumbing ----------------
static inline int cdiv(int a, int b) { return (a + b - 1) / b; }

template<bool TRANSB, int MODE>
static void launch_gemm(const float* A, const float* B, const float* bias, float* C,
                        int M, int N, int K, int lda, int ldb, int ldc, int batch,
                        long sA, long sB, long sBias, long sC)
{
    dim3 grid(cdiv(N, BNt), cdiv(M, BMt), batch);
    cudaFuncSetAttribute(mma_gemm_kernel<TRANSB, MODE>,
                         cudaFuncAttributeMaxDynamicSharedMemorySize, GEMM_SMEM_BYTES);
    mma_gemm_kernel<TRANSB, MODE><<<grid, 512, GEMM_SMEM_BYTES>>>(
        A, B, bias, C, M, N, K, lda, ldb, ldc, sA, sB, sBias, sC);
}

extern "C" void kernel_launch(void* const* d_in, const int* in_sizes, int n_in,
                              void* d_out, int out_size)
{
    (void)in_sizes; (void)n_in; (void)out_size;

    const float* x        = (const float*)d_in[0];
    const float* pre_Wq   = (const float*)d_in[1];
    const float* pre_Wk   = (const float*)d_in[2];
    const float* pre_Wv   = (const float*)d_in[3];
    const float* ln1_g    = (const float*)d_in[4];
    const float* ln1_b    = (const float*)d_in[5];
    const float* pre_W1   = (const float*)d_in[6];
    const float* pre_b1   = (const float*)d_in[7];
    const float* pre_W2   = (const float*)d_in[8];
    const float* pre_b2   = (const float*)d_in[9];
    const float* ln4p_g   = (const float*)d_in[10];
    const float* ln4p_b   = (const float*)d_in[11];
    const float* cross_Wq = (const float*)d_in[12];
    const float* cross_Wk = (const float*)d_in[13];
    const float* cross_Wv = (const float*)d_in[14];
    const float* ln2_g    = (const float*)d_in[15];
    const float* ln2_b    = (const float*)d_in[16];
    const float* post_Wq  = (const float*)d_in[17];
    const float* post_Wk  = (const float*)d_in[18];
    const float* post_Wv  = (const float*)d_in[19];
    const float* ln3_g    = (const float*)d_in[20];
    const float* ln3_b    = (const float*)d_in[21];
    const float* post_W1  = (const float*)d_in[22];
    const float* post_b1  = (const float*)d_in[23];
    const float* post_W2  = (const float*)d_in[24];
    const float* post_b2  = (const float*)d_in[25];
    const float* ln4_g    = (const float*)d_in[26];
    const float* ln4_b    = (const float*)d_in[27];
    float* out = (float*)d_out;

    float *bufA, *bufB, *bufC, *qk, *scores, *wbuf;
    cudaGetSymbolAddress((void**)&bufA, g_bufA);
    cudaGetSymbolAddress((void**)&bufB, g_bufB);
    cudaGetSymbolAddress((void**)&bufC, g_bufC);
    cudaGetSymbolAddress((void**)&qk, g_qk);
    cudaGetSymbolAddress((void**)&scores, g_scores);
    cudaGetSymbolAddress((void**)&wbuf, g_wT);
    float* xt_pad = scores;

    // wbuf layout: truncated/concatenated weights
    const long SZ_QKW = (long)SS * DD * QKN;     // 14,745,600
    const long SZ_VW  = (long)SS * DD * DD;      // 29,491,200
    const long SZ_W1  = (long)SS * DD * DD4;     // 7,372,800
    float* qkPre   = wbuf;
    float* qkPost  = qkPre  + SZ_QKW;
    float* qkCross = qkPost + SZ_QKW;
    float* WvPreC  = qkCross + (long)DD * QKN;
    float* WvPostC = WvPreC  + SZ_VW;
    float* W1PreC  = WvPostC + SZ_VW;
    float* W1PostC = W1PreC  + SZ_W1;
    float* W2PreC  = W1PostC + SZ_W1;
    float* W2PostC = W2PreC  + SZ_W1;
    float* WvCrossC = W2PostC + SZ_W1;

    const float scale = 1.0f / sqrtf((float)DD4);
    const long LD  = (long)LL * DD;

    // ---------------- weight prep (concat + truncate) ----------------
    {
        long t1 = SZ_QKW;
        concat_qk_kernel<<<cdiv((int)(t1 / 1), 256) , 256>>>(pre_Wq, pre_Wk, qkPre, t1);
        concat_qk_kernel<<<cdiv((int)(t1 / 1), 256) , 256>>>(post_Wq, post_Wk, qkPost, t1);
        long t2 = (long)DD * QKN;
        concat_qk_kernel<<<cdiv((int)t2, 256), 256>>>(cross_Wq, cross_Wk, qkCross, t2);
        cvt_kernel<<<cdiv((int)(SZ_VW / 4), 256), 256>>>(pre_Wv,  WvPreC,  SZ_VW / 4);
        cvt_kernel<<<cdiv((int)(SZ_VW / 4), 256), 256>>>(post_Wv, WvPostC, SZ_VW / 4);
        cvt_kernel<<<cdiv((int)(SZ_W1 / 4), 256), 256>>>(pre_W1,  W1PreC,  SZ_W1 / 4);
        cvt_kernel<<<cdiv((int)(SZ_W1 / 4), 256), 256>>>(post_W1, W1PostC, SZ_W1 / 4);
        cvt_kernel<<<cdiv((int)(SZ_W1 / 4), 256), 256>>>(pre_W2,  W2PreC,  SZ_W1 / 4);
        cvt_kernel<<<cdiv((int)(SZ_W1 / 4), 256), 256>>>(post_W2, W2PostC, SZ_W1 / 4);
        cvt_kernel<<<cdiv((int)((long)DD * DD / 4), 256), 256>>>(cross_Wv, WvCrossC, (long)DD * DD / 4);
    }

    // xc = tf32(x) in bufB (alive until pre a@x completes)
    float* xc = bufB;
    cvt_kernel<<<cdiv((int)(SS * LD / 4), 256), 256>>>(x, xc, SS * LD / 4);

    // ================= pre_self_step attention =================
    // qk = xc @ qkPre  [50][1024,384]
    launch_gemm<false, 3>(xc, qkPre, nullptr, qk, LL, QKN, DD, DD, QKN, QKN, SS,
                          LD, (long)DD * QKN, 0, (long)LL * QKN);
    // scores = q @ k^T
    launch_gemm<true, 0>(qk, qk + DD4, nullptr, scores, LL, LL, DD4, QKN, QKN, LL, SS,
                         (long)LL * QKN, (long)LL * QKN, 0, (long)LL * LL);
    softmax_kernel<<<SS * LL, 256>>>(scores, LL, LL, scale);
    // av = scores @ x (NN)
    launch_gemm<false, 3>(scores, xc, nullptr, bufC, LL, DD, LL, LL, DD, DD, SS,
                          (long)LL * LL, LD, 0, LD);
    // h = av @ Wv (NN)
    launch_gemm<false, 0>(bufC, WvPreC, nullptr, bufB, LL, DD, DD, DD, DD, DD, SS,
                          LD, (long)DD * DD, 0, LD);
    ln_kernel<<<SS * LL, 256>>>(x, bufB, ln1_g, ln1_b, bufA, LL, LL, 1, LL, 1, LL, 1, DD, 1);

    // ================= pre_mlp =================
    launch_gemm<false, 2>(bufA, W1PreC, pre_b1, qk, LL, DD4, DD, DD, DD4, DD4, SS,
                          LD, (long)DD * DD4, DD4, (long)LL * DD4);
    launch_gemm<false, 1>(qk, W2PreC, pre_b2, bufC, LL, DD, DD4, DD4, DD, DD, SS,
                          (long)LL * DD4, (long)DD4 * DD, DD, LD);
    ln_kernel<<<SS * LL, 256>>>(bufA, bufC, ln4p_g, ln4p_b, xt_pad, LL, LL, 1, LL, 1, 1, SP, DD, 1);
    zero_pad_kernel<<<cdiv(LL * (SP - SS) * DD, 256), 256>>>(xt_pad);

    // ================= cross_step attention (padded S -> SP) =================
    launch_gemm<false, 3>(xt_pad, qkCross, nullptr, qk, LL * SP, QKN, DD, DD, QKN, QKN, 1,
                          0, 0, 0, 0);
    launch_gemm<true, 0>(qk, qk + DD4, nullptr, bufB, SP, SP, DD4, QKN, QKN, SP, LL,
                         (long)SP * QKN, (long)SP * QKN, 0, (long)SP * SP);
    softmax_kernel<<<LL * SP, 256>>>(bufB, SS, SP, scale);
    // av = scores @ xt_pad (NN), M=50 valid rows
    launch_gemm<false, 3>(bufB, xt_pad, nullptr, bufC, SS, DD, SP, SP, DD, DD, LL,
                          (long)SP * SP, (long)SP * DD, 0, (long)SS * DD);
    launch_gemm<false, 0>(bufC, WvCrossC, nullptr, bufB, LL * SS, DD, DD, DD, DD, DD, 1,
                          0, 0, 0, 0);
    ln_kernel<<<LL * SS, 256>>>(xt_pad, bufB, ln2_g, ln2_b, bufA, SS, SP, 1, SS, 1, 1, LL, 0, 1);

    // ================= post_self_step attention =================
    launch_gemm<false, 3>(bufA, qkPost, nullptr, qk, LL, QKN, DD, DD, QKN, QKN, SS,
                          LD, (long)DD * QKN, 0, (long)LL * QKN);
    launch_gemm<true, 0>(qk, qk + DD4, nullptr, scores, LL, LL, DD4, QKN, QKN, LL, SS,
                         (long)LL * QKN, (long)LL * QKN, 0, (long)LL * LL);
    softmax_kernel<<<SS * LL, 256>>>(scores, LL, LL, scale);
    launch_gemm<false, 3>(scores, bufA, nullptr, bufC, LL, DD, LL, LL, DD, DD, SS,
                          (long)LL * LL, LD, 0, LD);
    launch_gemm<false, 0>(bufC, WvPostC, nullptr, bufB, LL, DD, DD, DD, DD, DD, SS,
                          LD, (long)DD * DD, 0, LD);
    ln_kernel<<<SS * LL, 256>>>(bufA, bufB, ln3_g, ln3_b, bufC, LL, LL, 1, LL, 1, LL, 1, DD, 1);

    // ================= post_mlp =================
    launch_gemm<false, 2>(bufC, W1PostC, post_b1, qk, LL, DD4, DD, DD, DD4, DD4, SS,
                          LD, (long)DD * DD4, DD4, (long)LL * DD4);
    launch_gemm<false, 1>(qk, W2PostC, post_b2, bufB, LL, DD, DD4, DD4, DD, DD, SS,
                          (long)LL * DD4, (long)DD4 * DD, DD, LD);
    ln_kernel<<<SS * LL, 256>>>(bufC, bufB, ln4_g, ln4_b, out, LL, LL, 1, LL, 1, LL, 1, DD, 0);
}

// round 9
// speedup vs baseline: 1.2538x; 1.1504x over previous
#include <cuda_runtime.h>
#include <math.h>
#include <stdint.h>

// Problem dims
#define SS 50
#define LL 1024
#define DD 768
#define DD4 192
#define SP 64   // padded step dim for cross attention
#define QKN 384 // fused q||k projection width

// ---------------- static scratch (alloc-free rule) ----------------
__device__ float g_bufA[(size_t)SS * LL * DD];
__device__ float g_bufB[(size_t)SS * LL * DD];
__device__ float g_bufC[(size_t)SS * LL * DD];
__device__ float g_qk[(size_t)LL * SP * QKN];
__device__ float g_scores[(size_t)SS * LL * LL];   // also xt_pad [LL,SP,DD]
__device__ float g_wT[118849536];                  // concat/truncated weights

// =============== helpers =====================
__device__ __forceinline__ uint32_t smem_u32(const void* p) {
    uint32_t a;
    asm("{ .reg .u64 t; cvta.to.shared.u64 t, %1; cvt.u32.u64 %0, t; }" : "=r"(a) : "l"(p));
    return a;
}
__device__ __forceinline__ float f2tf(float f) {
    uint32_t r;
    asm("cvt.rna.tf32.f32 %0, %1;" : "=r"(r) : "f"(f));
    return __uint_as_float(r);
}
__device__ __forceinline__ void mma_tf32(float* d, const uint32_t* a, const uint32_t* b) {
    asm volatile(
        "mma.sync.aligned.m16n8k8.row.col.f32.tf32.tf32.f32 "
        "{%0,%1,%2,%3}, {%4,%5,%6,%7}, {%8,%9}, {%0,%1,%2,%3};\n"
        : "+f"(d[0]), "+f"(d[1]), "+f"(d[2]), "+f"(d[3])
        : "r"(a[0]), "r"(a[1]), "r"(a[2]), "r"(a[3]),
          "r"(b[0]), "r"(b[1]));
}
__device__ __forceinline__ void cp_async16(uint32_t smem_addr, const void* gptr, uint32_t src_bytes) {
    asm volatile("cp.async.ca.shared.global [%0], [%1], 16, %2;"
                 :: "r"(smem_addr), "l"(gptr), "r"(src_bytes));
}
#define CP_COMMIT() asm volatile("cp.async.commit_group;" ::: "memory")
#define CP_WAIT2()  asm volatile("cp.async.wait_group 2;" ::: "memory")

// =================================================================
// cp.async-pipelined TF32 GEMM (mma.sync m16n8k8)
// CTA tile 128x256, 8 warps, warp tile 64x64 (fragment re-reads A:x4 -> A:x4,B:x2)
// NT: C = A @ B^T   NN: C = A @ B
// MODE: 0 plain, 1 +bias, 2 +bias+relu+cvt, 3 +cvt
// =================================================================
#define BMt 128
#define BNt 256
#define ARS 20                  // A smem row stride (words)
#define BRS_NT 20
#define BRS_NN 264              // conflict-free: (c*264+g) % 32 = c*8+g distinct
#define AWORDS (BMt * ARS)      // 2560
#define BWORDS 5120             // max(256*20, 16*264=4224)
#define STGW (AWORDS + BWORDS)  // 7680
#define NSTAGE 4
#define GEMM_SMEM_BYTES (NSTAGE * STGW * 4)  // 122880

template<bool TRANSB, int MODE>
__global__ __launch_bounds__(256, 1)
void mma_gemm_kernel(const float* __restrict__ Ab, const float* __restrict__ Bb,
                     const float* __restrict__ biasb, float* __restrict__ Cb,
                     int M, int N, int K, int lda, int ldb, int ldc,
                     long sA, long sB, long sBias, long sC)
{
    extern __shared__ __align__(16) uint32_t sm[];
    const uint32_t smb = smem_u32(sm);

    const int b = blockIdx.z;
    const float* A = Ab + (long)b * sA;
    const float* B = Bb + (long)b * sB;
    float* C = Cb + (long)b * sC;

    const int brow = blockIdx.y * BMt;
    const int bcol = blockIdx.x * BNt;
    const int tid = threadIdx.x;
    const int wid = tid >> 5;
    const int lane = tid & 31;
    const int g = lane >> 2;
    const int c = lane & 3;
    const int warp_m = (wid & 1) * 64;    // 2 m-groups of 64
    const int warp_n = (wid >> 1) * 64;   // 4 n-groups of 64

    const int nkt = K >> 4;

    float acc[4][8][4];
    #pragma unroll
    for (int i = 0; i < 4; i++)
        #pragma unroll
        for (int j = 0; j < 8; j++)
            #pragma unroll
            for (int r = 0; r < 4; r++)
                acc[i][j][r] = 0.0f;

    auto issue_stage = [&](int kt) {
        if (kt < nkt) {
            int k0 = kt << 4;
            uint32_t sbase = smb + ((kt & (NSTAGE - 1)) * STGW) * 4;
            // A: 128 rows x 4 chunks = 512 ops (2 per thread)
            #pragma unroll
            for (int i = 0; i < 2; i++) {
                int idx = i * 256 + tid;
                int row = idx >> 2, q = idx & 3;
                int gr = brow + row;
                const float* gp = A + (long)gr * lda + k0 + q * 4;
                uint32_t dst = sbase + (row * ARS + q * 4) * 4;
                cp_async16(dst, gp, (gr < M) ? 16u : 0u);
            }
            // B: 1024 ops (4 per thread)
            if (TRANSB) {
                #pragma unroll
                for (int i = 0; i < 4; i++) {
                    int idx = i * 256 + tid;
                    int row = idx >> 2, q = idx & 3;
                    int gn = bcol + row;
                    const float* gp = B + (long)gn * ldb + k0 + q * 4;
                    uint32_t dst = sbase + (AWORDS + row * BRS_NT + q * 4) * 4;
                    cp_async16(dst, gp, (gn < N) ? 16u : 0u);
                }
            } else {
                #pragma unroll
                for (int i = 0; i < 4; i++) {
                    int idx = i * 256 + tid;
                    int kk = idx >> 6;
                    int nq = (idx & 63) << 2;
                    int gn = bcol + nq;
                    const float* gp = B + (long)(k0 + kk) * ldb + gn;
                    uint32_t dst = sbase + (AWORDS + kk * BRS_NN + nq) * 4;
                    cp_async16(dst, gp, (gn < N) ? 16u : 0u);
                }
            }
        }
        CP_COMMIT();
    };

    issue_stage(0);
    issue_stage(1);
    issue_stage(2);

    for (int kt = 0; kt < nkt; kt++) {
        CP_WAIT2();
        __syncthreads();
        issue_stage(kt + 3);

        const uint32_t* As = sm + (kt & (NSTAGE - 1)) * STGW;
        const uint32_t* Bs = As + AWORDS;

        #pragma unroll
        for (int ks = 0; ks < 16; ks += 8) {
            uint32_t af[4][4], bf[8][2];
            #pragma unroll
            for (int am = 0; am < 4; am++) {
                int r0 = warp_m + am * 16 + g;
                af[am][0] = As[r0 * ARS + ks + c];
                af[am][1] = As[(r0 + 8) * ARS + ks + c];
                af[am][2] = As[r0 * ARS + ks + c + 4];
                af[am][3] = As[(r0 + 8) * ARS + ks + c + 4];
            }
            #pragma unroll
            for (int bn = 0; bn < 8; bn++) {
                int col = warp_n + bn * 8 + g;
                if (TRANSB) {
                    bf[bn][0] = Bs[col * BRS_NT + ks + c];
                    bf[bn][1] = Bs[col * BRS_NT + ks + c + 4];
                } else {
                    bf[bn][0] = Bs[(ks + c) * BRS_NN + col];
                    bf[bn][1] = Bs[(ks + c + 4) * BRS_NN + col];
                }
            }
            #pragma unroll
            for (int am = 0; am < 4; am++)
                #pragma unroll
                for (int bn = 0; bn < 8; bn++)
                    mma_tf32(acc[am][bn], af[am], bf[bn]);
        }
    }

    // ---- epilogue ----
    #pragma unroll
    for (int am = 0; am < 4; am++) {
        int row0 = brow + warp_m + am * 16 + g;
        #pragma unroll
        for (int bn = 0; bn < 8; bn++) {
            int col = bcol + warp_n + bn * 8 + c * 2;
            if (col >= N) continue;
            float v0 = acc[am][bn][0], v1 = acc[am][bn][1];
            float v2 = acc[am][bn][2], v3 = acc[am][bn][3];
            if (MODE == 1 || MODE == 2) {
                float b0 = biasb[(long)b * sBias + col];
                float b1 = biasb[(long)b * sBias + col + 1];
                v0 += b0; v1 += b1; v2 += b0; v3 += b1;
            }
            if (MODE == 2) {
                v0 = fmaxf(v0, 0.f); v1 = fmaxf(v1, 0.f);
                v2 = fmaxf(v2, 0.f); v3 = fmaxf(v3, 0.f);
            }
            if (MODE == 2 || MODE == 3) {
                v0 = f2tf(v0); v1 = f2tf(v1); v2 = f2tf(v2); v3 = f2tf(v3);
            }
            if (row0 < M)     *(float2*)&C[(long)row0 * ldc + col]       = make_float2(v0, v1);
            if (row0 + 8 < M) *(float2*)&C[(long)(row0 + 8) * ldc + col] = make_float2(v2, v3);
        }
    }
}

// ---------------- elementwise tf32 truncate copy (float4) ----------------
__global__ __launch_bounds__(256)
void cvt_kernel(const float* __restrict__ in, float* __restrict__ out, long n4)
{
    long i = (long)blockIdx.x * 256 + threadIdx.x;
    if (i >= n4) return;
    float4 v = ((const float4*)in)[i];
    v.x = f2tf(v.x); v.y = f2tf(v.y); v.z = f2tf(v.z); v.w = f2tf(v.w);
    ((float4*)out)[i] = v;
}

// ---------------- concat Wq||Wk -> [batch, D, 384], tf32-truncated --------
__global__ __launch_bounds__(256)
void concat_qk_kernel(const float* __restrict__ Wq, const float* __restrict__ Wk,
                      float* __restrict__ out, long total)
{
    long i = (long)blockIdx.x * 256 + threadIdx.x;
    if (i >= total) return;
    long j = i % QKN;
    long bd = i / QKN;
    float v = (j < DD4) ? Wq[bd * DD4 + j] : Wk[bd * DD4 + (j - DD4)];
    out[i] = f2tf(v);
}

// ---------------- row softmax (pre-scale, padded stride, tf32 out) ----------
__global__ __launch_bounds__(256)
void softmax_kernel(float* __restrict__ data, int n, int stride, float scale)
{
    long row = blockIdx.x;
    float* p = data + row * (long)stride;
    int t = threadIdx.x;
    int w = t >> 5, lane = t & 31;

    float loc[4];
    int cnt = 0;
    float mx = -3.0e38f;
    for (int i = t; i < n; i += 256) {
        float v = p[i] * scale;
        loc[cnt++] = v;
        mx = fmaxf(mx, v);
    }
    #pragma unroll
    for (int o = 16; o > 0; o >>= 1) mx = fmaxf(mx, __shfl_xor_sync(0xffffffffu, mx, o));
    __shared__ float red[8];
    if (lane == 0) red[w] = mx;
    __syncthreads();
    if (t < 8) {
        float v = red[t];
        #pragma unroll
        for (int o = 4; o > 0; o >>= 1) v = fmaxf(v, __shfl_xor_sync(0xffu, v, o));
        if (t == 0) red[0] = v;
    }
    __syncthreads();
    mx = red[0];
    __syncthreads();

    float sum = 0.0f;
    for (int cc = 0; cc < cnt; cc++) {
        float e = __expf(loc[cc] - mx);
        loc[cc] = e;
        sum += e;
    }
    #pragma unroll
    for (int o = 16; o > 0; o >>= 1) sum += __shfl_xor_sync(0xffffffffu, sum, o);
    if (lane == 0) red[w] = sum;
    __syncthreads();
    if (t < 8) {
        float v = red[t];
        #pragma unroll
        for (int o = 4; o > 0; o >>= 1) v += __shfl_xor_sync(0xffu, v, o);
        if (t == 0) red[0] = v;
    }
    __syncthreads();
    float inv = 1.0f / red[0];

    cnt = 0;
    for (int i = t; i < n; i += 256) p[i] = f2tf(loc[cnt++] * inv);
    for (int i = t; i < stride; i += 256) if (i >= n) p[i] = 0.0f;
}

// ---------------- fused residual + LayerNorm, generalized index mapping ----------
__global__ __launch_bounds__(256)
void ln_kernel(const float* __restrict__ resid, const float* __restrict__ h,
               const float* __restrict__ gam, const float* __restrict__ bet,
               float* __restrict__ out, int J,
               long ri, long rj, long hi, long hj, long oi, long oj, long gstride,
               int cvt_out)
{
    long b = blockIdx.x;
    long i = b / J, j = b % J;
    const float* r  = resid + (i * ri + j * rj) * DD;
    const float* hh = h     + (i * hi + j * hj) * DD;
    float* op       = out   + (i * oi + j * oj) * DD;
    const float* gp = gam + i * gstride;
    const float* bp = bet + i * gstride;
    int t = threadIdx.x;
    int w = t >> 5, lane = t & 31;

    float v[3];
    float s = 0.0f, s2 = 0.0f;
    #pragma unroll
    for (int k = 0; k < 3; k++) {
        int d = t + k * 256;
        float val = r[d] + hh[d];
        v[k] = val;
        s += val;
        s2 += val * val;
    }
    #pragma unroll
    for (int o = 16; o > 0; o >>= 1) {
        s  += __shfl_xor_sync(0xffffffffu, s, o);
        s2 += __shfl_xor_sync(0xffffffffu, s2, o);
    }
    __shared__ float rs[8], rs2[8];
    if (lane == 0) { rs[w] = s; rs2[w] = s2; }
    __syncthreads();
    if (t < 8) {
        s = rs[t]; s2 = rs2[t];
        #pragma unroll
        for (int o = 4; o > 0; o >>= 1) {
            s  += __shfl_xor_sync(0xffu, s, o);
            s2 += __shfl_xor_sync(0xffu, s2, o);
        }
        if (t == 0) { rs[0] = s; rs2[0] = s2; }
    }
    __syncthreads();
    float mean = rs[0] * (1.0f / DD);
    float var  = rs2[0] * (1.0f / DD) - mean * mean;
    float inv  = rsqrtf(var + 1e-5f);

    #pragma unroll
    for (int k = 0; k < 3; k++) {
        int d = t + k * 256;
        float o = (v[k] - mean) * inv * gp[d] + bp[d];
        op[d] = cvt_out ? f2tf(o) : o;
    }
}

// ---------------- zero the pad rows of xt_pad [LL, SP, DD] ----------------
__global__ __launch_bounds__(256)
void zero_pad_kernel(float* __restrict__ xt)
{
    long idx = (long)blockIdx.x * 256 + threadIdx.x;
    const long per_l = (long)(SP - SS) * DD;
    const long total = (long)LL * per_l;
    if (idx >= total) return;
    long l = idx / per_l;
    long off = idx % per_l;
    xt[((long)l * SP + SS) * DD + off] = 0.0f;
}

// ---------------- launch plumbing ----------------
static inline int cdiv(int a, int b) { return (a + b - 1) / b; }

template<bool TRANSB, int MODE>
static void launch_gemm(const float* A, const float* B, const float* bias, float* C,
                        int M, int N, int K, int lda, int ldb, int ldc, int batch,
                        long sA, long sB, long sBias, long sC)
{
    dim3 grid(cdiv(N, BNt), cdiv(M, BMt), batch);
    cudaFuncSetAttribute(mma_gemm_kernel<TRANSB, MODE>,
                         cudaFuncAttributeMaxDynamicSharedMemorySize, GEMM_SMEM_BYTES);
    mma_gemm_kernel<TRANSB, MODE><<<grid, 256, GEMM_SMEM_BYTES>>>(
        A, B, bias, C, M, N, K, lda, ldb, ldc, sA, sB, sBias, sC);
}

extern "C" void kernel_launch(void* const* d_in, const int* in_sizes, int n_in,
                              void* d_out, int out_size)
{
    (void)in_sizes; (void)n_in; (void)out_size;

    const float* x        = (const float*)d_in[0];
    const float* pre_Wq   = (const float*)d_in[1];
    const float* pre_Wk   = (const float*)d_in[2];
    const float* pre_Wv   = (const float*)d_in[3];
    const float* ln1_g    = (const float*)d_in[4];
    const float* ln1_b    = (const float*)d_in[5];
    const float* pre_W1   = (const float*)d_in[6];
    const float* pre_b1   = (const float*)d_in[7];
    const float* pre_W2   = (const float*)d_in[8];
    const float* pre_b2   = (const float*)d_in[9];
    const float* ln4p_g   = (const float*)d_in[10];
    const float* ln4p_b   = (const float*)d_in[11];
    const float* cross_Wq = (const float*)d_in[12];
    const float* cross_Wk = (const float*)d_in[13];
    const float* cross_Wv = (const float*)d_in[14];
    const float* ln2_g    = (const float*)d_in[15];
    const float* ln2_b    = (const float*)d_in[16];
    const float* post_Wq  = (const float*)d_in[17];
    const float* post_Wk  = (const float*)d_in[18];
    const float* post_Wv  = (const float*)d_in[19];
    const float* ln3_g    = (const float*)d_in[20];
    const float* ln3_b    = (const float*)d_in[21];
    const float* post_W1  = (const float*)d_in[22];
    const float* post_b1  = (const float*)d_in[23];
    const float* post_W2  = (const float*)d_in[24];
    const float* post_b2  = (const float*)d_in[25];
    const float* ln4_g    = (const float*)d_in[26];
    const float* ln4_b    = (const float*)d_in[27];
    float* out = (float*)d_out;

    float *bufA, *bufB, *bufC, *qk, *scores, *wbuf;
    cudaGetSymbolAddress((void**)&bufA, g_bufA);
    cudaGetSymbolAddress((void**)&bufB, g_bufB);
    cudaGetSymbolAddress((void**)&bufC, g_bufC);
    cudaGetSymbolAddress((void**)&qk, g_qk);
    cudaGetSymbolAddress((void**)&scores, g_scores);
    cudaGetSymbolAddress((void**)&wbuf, g_wT);
    float* xt_pad = scores;

    const long SZ_QKW = (long)SS * DD * QKN;
    const long SZ_VW  = (long)SS * DD * DD;
    const long SZ_W1  = (long)SS * DD * DD4;
    float* qkPre   = wbuf;
    float* qkPost  = qkPre  + SZ_QKW;
    float* qkCross = qkPost + SZ_QKW;
    float* WvPreC  = qkCross + (long)DD * QKN;
    float* WvPostC = WvPreC  + SZ_VW;
    float* W1PreC  = WvPostC + SZ_VW;
    float* W1PostC = W1PreC  + SZ_W1;
    float* W2PreC  = W1PostC + SZ_W1;
    float* W2PostC = W2PreC  + SZ_W1;
    float* WvCrossC = W2PostC + SZ_W1;

    const float scale = 1.0f / sqrtf((float)DD4);
    const long LD  = (long)LL * DD;

    // ---------------- weight prep (concat + truncate) ----------------
    {
        long t1 = SZ_QKW;
        concat_qk_kernel<<<cdiv((int)t1, 256), 256>>>(pre_Wq, pre_Wk, qkPre, t1);
        concat_qk_kernel<<<cdiv((int)t1, 256), 256>>>(post_Wq, post_Wk, qkPost, t1);
        long t2 = (long)DD * QKN;
        concat_qk_kernel<<<cdiv((int)t2, 256), 256>>>(cross_Wq, cross_Wk, qkCross, t2);
        cvt_kernel<<<cdiv((int)(SZ_VW / 4), 256), 256>>>(pre_Wv,  WvPreC,  SZ_VW / 4);
        cvt_kernel<<<cdiv((int)(SZ_VW / 4), 256), 256>>>(post_Wv, WvPostC, SZ_VW / 4);
        cvt_kernel<<<cdiv((int)(SZ_W1 / 4), 256), 256>>>(pre_W1,  W1PreC,  SZ_W1 / 4);
        cvt_kernel<<<cdiv((int)(SZ_W1 / 4), 256), 256>>>(post_W1, W1PostC, SZ_W1 / 4);
        cvt_kernel<<<cdiv((int)(SZ_W1 / 4), 256), 256>>>(pre_W2,  W2PreC,  SZ_W1 / 4);
        cvt_kernel<<<cdiv((int)(SZ_W1 / 4), 256), 256>>>(post_W2, W2PostC, SZ_W1 / 4);
        cvt_kernel<<<cdiv((int)((long)DD * DD / 4), 256), 256>>>(cross_Wv, WvCrossC, (long)DD * DD / 4);
    }

    // xc = tf32(x) in bufB (alive until pre a@x completes)
    float* xc = bufB;
    cvt_kernel<<<cdiv((int)(SS * LD / 4), 256), 256>>>(x, xc, SS * LD / 4);

    // ================= pre_self_step attention =================
    launch_gemm<false, 3>(xc, qkPre, nullptr, qk, LL, QKN, DD, DD, QKN, QKN, SS,
                          LD, (long)DD * QKN, 0, (long)LL * QKN);
    launch_gemm<true, 0>(qk, qk + DD4, nullptr, scores, LL, LL, DD4, QKN, QKN, LL, SS,
                         (long)LL * QKN, (long)LL * QKN, 0, (long)LL * LL);
    softmax_kernel<<<SS * LL, 256>>>(scores, LL, LL, scale);
    launch_gemm<false, 3>(scores, xc, nullptr, bufC, LL, DD, LL, LL, DD, DD, SS,
                          (long)LL * LL, LD, 0, LD);
    launch_gemm<false, 0>(bufC, WvPreC, nullptr, bufB, LL, DD, DD, DD, DD, DD, SS,
                          LD, (long)DD * DD, 0, LD);
    ln_kernel<<<SS * LL, 256>>>(x, bufB, ln1_g, ln1_b, bufA, LL, LL, 1, LL, 1, LL, 1, DD, 1);

    // ================= pre_mlp =================
    launch_gemm<false, 2>(bufA, W1PreC, pre_b1, qk, LL, DD4, DD, DD, DD4, DD4, SS,
                          LD, (long)DD * DD4, DD4, (long)LL * DD4);
    launch_gemm<false, 1>(qk, W2PreC, pre_b2, bufC, LL, DD, DD4, DD4, DD, DD, SS,
                          (long)LL * DD4, (long)DD4 * DD, DD, LD);
    ln_kernel<<<SS * LL, 256>>>(bufA, bufC, ln4p_g, ln4p_b, xt_pad, LL, LL, 1, LL, 1, 1, SP, DD, 1);
    zero_pad_kernel<<<cdiv(LL * (SP - SS) * DD, 256), 256>>>(xt_pad);

    // ================= cross_step attention (padded S -> SP) =================
    launch_gemm<false, 3>(xt_pad, qkCross, nullptr, qk, LL * SP, QKN, DD, DD, QKN, QKN, 1,
                          0, 0, 0, 0);
    launch_gemm<true, 0>(qk, qk + DD4, nullptr, bufB, SP, SP, DD4, QKN, QKN, SP, LL,
                         (long)SP * QKN, (long)SP * QKN, 0, (long)SP * SP);
    softmax_kernel<<<LL * SP, 256>>>(bufB, SS, SP, scale);
    launch_gemm<false, 3>(bufB, xt_pad, nullptr, bufC, SS, DD, SP, SP, DD, DD, LL,
                          (long)SP * SP, (long)SP * DD, 0, (long)SS * DD);
    launch_gemm<false, 0>(bufC, WvCrossC, nullptr, bufB, LL * SS, DD, DD, DD, DD, DD, 1,
                          0, 0, 0, 0);
    ln_kernel<<<LL * SS, 256>>>(xt_pad, bufB, ln2_g, ln2_b, bufA, SS, SP, 1, SS, 1, 1, LL, 0, 1);

    // ================= post_self_step attention =================
    launch_gemm<false, 3>(bufA, qkPost, nullptr, qk, LL, QKN, DD, DD, QKN, QKN, SS,
                          LD, (long)DD * QKN, 0, (long)LL * QKN);
    launch_gemm<true, 0>(qk, qk + DD4, nullptr, scores, LL, LL, DD4, QKN, QKN, LL, SS,
                         (long)LL * QKN, (long)LL * QKN, 0, (long)LL * LL);
    softmax_kernel<<<SS * LL, 256>>>(scores, LL, LL, scale);
    launch_gemm<false, 3>(scores, bufA, nullptr, bufC, LL, DD, LL, LL, DD, DD, SS,
                          (long)LL * LL, LD, 0, LD);
    launch_gemm<false, 0>(bufC, WvPostC, nullptr, bufB, LL, DD, DD, DD, DD, DD, SS,
                          LD, (long)DD * DD, 0, LD);
    ln_kernel<<<SS * LL, 256>>>(bufA, bufB, ln3_g, ln3_b, bufC, LL, LL, 1, LL, 1, LL, 1, DD, 1);

    // ================= post_mlp =================
    launch_gemm<false, 2>(bufC, W1PostC, post_b1, qk, LL, DD4, DD, DD, DD4, DD4, SS,
                          LD, (long)DD * DD4, DD4, (long)LL * DD4);
    launch_gemm<false, 1>(qk, W2PostC, post_b2, bufB, LL, DD, DD4, DD4, DD, DD, SS,
                          (long)LL * DD4, (long)DD4 * DD, DD, LD);
    ln_kernel<<<SS * LL, 256>>>(bufC, bufB, ln4_g, ln4_b, out, LL, LL, 1, LL, 1, LL, 1, DD, 0);
}

// round 10
// speedup vs baseline: 1.6125x; 1.2861x over previous
#include <cuda_runtime.h>
#include <cuda_fp16.h>
#include <math.h>
#include <stdint.h>

// Problem dims
#define SS 50
#define LL 1024
#define DD 768
#define DD4 192
#define SP 64   // padded step dim for cross attention
#define QKN 384 // fused q||k projection width

// ---------------- static scratch (alloc-free rule) ----------------
__device__ float  g_bufA[(size_t)SS * LL * DD];
__device__ float  g_bufB[(size_t)SS * LL * DD];
__device__ float  g_bufC[(size_t)SS * LL * DD];
__device__ float  g_xtpad[(size_t)LL * SP * DD];
__device__ __half g_xh[(size_t)SS * LL * DD];
__device__ __half g_lnh[(size_t)SS * LL * DD];
__device__ __half g_xtph[(size_t)LL * SP * DD];
__device__ __half g_qkh[(size_t)LL * SP * QKN];
__device__ __half g_avh[(size_t)SS * LL * DD];
__device__ __half g_scoresh[(size_t)SS * LL * LL];
__device__ __half g_hT[(size_t)LL * DD * SP];     // activation transposes
__device__ __half g_wh[119000000];                // transposed half weights

// =============== helpers =====================
__device__ __forceinline__ uint32_t smem_u32(const void* p) {
    uint32_t a;
    asm("{ .reg .u64 t; cvta.to.shared.u64 t, %1; cvt.u32.u64 %0, t; }" : "=r"(a) : "l"(p));
    return a;
}
__device__ __forceinline__ void mma_f16(float* d, const uint32_t* a, const uint32_t* b) {
    asm volatile(
        "mma.sync.aligned.m16n8k16.row.col.f32.f16.f16.f32 "
        "{%0,%1,%2,%3}, {%4,%5,%6,%7}, {%8,%9}, {%0,%1,%2,%3};\n"
        : "+f"(d[0]), "+f"(d[1]), "+f"(d[2]), "+f"(d[3])
        : "r"(a[0]), "r"(a[1]), "r"(a[2]), "r"(a[3]),
          "r"(b[0]), "r"(b[1]));
}
__device__ __forceinline__ void cp_async16(uint32_t smem_addr, const void* gptr, uint32_t src_bytes) {
    asm volatile("cp.async.ca.shared.global [%0], [%1], 16, %2;"
                 :: "r"(smem_addr), "l"(gptr), "r"(src_bytes));
}
#define CP_COMMIT() asm volatile("cp.async.commit_group;" ::: "memory")
#define CP_WAIT2()  asm volatile("cp.async.wait_group 2;" ::: "memory")

// =================================================================
// cp.async-pipelined FP16 NT GEMM (mma.sync m16n8k16, fp32 accum)
// C[b] = A[b] @ B[b]^T   A:[M,K] half, B:[N,K] half, K % 32 == 0
// CTA tile 128x256, 8 warps, warp tile 64x64, K-tile 32, 4-stage ring.
// MODE: 0 f32 out | 1 f32 out +bias | 2 f16 out +bias+relu | 3 f16 out
// =================================================================
#define BMt 128
#define BNt 256
#define RS 20                    // smem row stride in 4B words (40 halves)
#define AWORDS (BMt * RS)        // 2560
#define BWORDS (BNt * RS)        // 5120
#define STGW (AWORDS + BWORDS)   // 7680
#define NSTAGE 4
#define GEMM_SMEM_BYTES (NSTAGE * STGW * 4)   // 122880

template<int MODE>
__global__ __launch_bounds__(256, 1)
void mma_gemm_kernel(const __half* __restrict__ Ab, const __half* __restrict__ Bb,
                     const float* __restrict__ biasb, void* __restrict__ Cb,
                     int M, int N, int K, int lda, int ldb, int ldc,
                     long sA, long sB, long sBias, long sC)
{
    constexpr bool BIAS = (MODE == 1 || MODE == 2);
    constexpr bool RELU = (MODE == 2);
    constexpr bool OUTH = (MODE >= 2);

    extern __shared__ __align__(16) uint32_t sm[];
    const uint32_t smb = smem_u32(sm);

    const int b = blockIdx.z;
    const __half* A = Ab + (long)b * sA;
    const __half* B = Bb + (long)b * sB;

    const int brow = blockIdx.y * BMt;
    const int bcol = blockIdx.x * BNt;
    const int tid = threadIdx.x;
    const int wid = tid >> 5;
    const int lane = tid & 31;
    const int g = lane >> 2;
    const int c = lane & 3;
    const int warp_m = (wid & 1) * 64;
    const int warp_n = (wid >> 1) * 64;

    const int nkt = K >> 5;   // K-tiles of 32

    float acc[4][8][4];
    #pragma unroll
    for (int i = 0; i < 4; i++)
        #pragma unroll
        for (int j = 0; j < 8; j++)
            #pragma unroll
            for (int r = 0; r < 4; r++)
                acc[i][j][r] = 0.0f;

    auto issue_stage = [&](int kt) {
        if (kt < nkt) {
            int k0 = kt << 5;    // halves
            uint32_t sbase = smb + ((kt & (NSTAGE - 1)) * STGW) * 4;
            // A: 128 rows x 4 chunks (16B = 8 halves) = 512 -> 2/thread
            #pragma unroll
            for (int i = 0; i < 2; i++) {
                int idx = i * 256 + tid;
                int row = idx >> 2, q = idx & 3;
                int gr = brow + row;
                const __half* gp = A + (long)gr * lda + k0 + q * 8;
                uint32_t dst = sbase + (row * RS + q * 4) * 4;
                cp_async16(dst, gp, (gr < M) ? 16u : 0u);
            }
            // B: 256 rows x 4 chunks = 1024 -> 4/thread
            #pragma unroll
            for (int i = 0; i < 4; i++) {
                int idx = i * 256 + tid;
                int row = idx >> 2, q = idx & 3;
                int gn = bcol + row;
                const __half* gp = B + (long)gn * ldb + k0 + q * 8;
                uint32_t dst = sbase + (AWORDS + row * RS + q * 4) * 4;
                cp_async16(dst, gp, (gn < N) ? 16u : 0u);
            }
        }
        CP_COMMIT();
    };

    issue_stage(0);
    issue_stage(1);
    issue_stage(2);

    for (int kt = 0; kt < nkt; kt++) {
        CP_WAIT2();
        __syncthreads();
        issue_stage(kt + 3);

        const uint32_t* As = sm + (kt & (NSTAGE - 1)) * STGW;
        const uint32_t* Bs = As + AWORDS;

        #pragma unroll
        for (int ks = 0; ks < 2; ks++) {       // two k16 steps
            int ws = ks * 8;                   // word offset
            uint32_t af[4][4], bf[8][2];
            #pragma unroll
            for (int am = 0; am < 4; am++) {
                int r0 = warp_m + am * 16 + g;
                af[am][0] = As[r0 * RS + ws + c];
                af[am][1] = As[(r0 + 8) * RS + ws + c];
                af[am][2] = As[r0 * RS + ws + c + 4];
                af[am][3] = As[(r0 + 8) * RS + ws + c + 4];
            }
            #pragma unroll
            for (int bn = 0; bn < 8; bn++) {
                int col = warp_n + bn * 8 + g;
                bf[bn][0] = Bs[col * RS + ws + c];
                bf[bn][1] = Bs[col * RS + ws + c + 4];
            }
            #pragma unroll
            for (int am = 0; am < 4; am++)
                #pragma unroll
                for (int bn = 0; bn < 8; bn++)
                    mma_f16(acc[am][bn], af[am], bf[bn]);
        }
    }

    // ---- epilogue ----
    #pragma unroll
    for (int am = 0; am < 4; am++) {
        int row0 = brow + warp_m + am * 16 + g;
        #pragma unroll
        for (int bn = 0; bn < 8; bn++) {
            int col = bcol + warp_n + bn * 8 + c * 2;
            if (col >= N) continue;
            float v0 = acc[am][bn][0], v1 = acc[am][bn][1];
            float v2 = acc[am][bn][2], v3 = acc[am][bn][3];
            if (BIAS) {
                float b0 = biasb[(long)b * sBias + col];
                float b1 = biasb[(long)b * sBias + col + 1];
                v0 += b0; v1 += b1; v2 += b0; v3 += b1;
            }
            if (RELU) {
                v0 = fmaxf(v0, 0.f); v1 = fmaxf(v1, 0.f);
                v2 = fmaxf(v2, 0.f); v3 = fmaxf(v3, 0.f);
            }
            if (OUTH) {
                __half* C = (__half*)Cb + (long)b * sC;
                __half2 h01 = __floats2half2_rn(v0, v1);
                __half2 h23 = __floats2half2_rn(v2, v3);
                if (row0 < M)     *(__half2*)&C[(long)row0 * ldc + col]       = h01;
                if (row0 + 8 < M) *(__half2*)&C[(long)(row0 + 8) * ldc + col] = h23;
            } else {
                float* C = (float*)Cb + (long)b * sC;
                if (row0 < M)     *(float2*)&C[(long)row0 * ldc + col]       = make_float2(v0, v1);
                if (row0 + 8 < M) *(float2*)&C[(long)(row0 + 8) * ldc + col] = make_float2(v2, v3);
            }
        }
    }
}

// ---------------- float -> half elementwise (x) ----------------
__global__ __launch_bounds__(256)
void f2h_kernel(const float* __restrict__ in, __half* __restrict__ out, long n4)
{
    long i = (long)blockIdx.x * 256 + threadIdx.x;
    if (i >= n4) return;
    float4 v = ((const float4*)in)[i];
    __half2 a = __floats2half2_rn(v.x, v.y);
    __half2 b = __floats2half2_rn(v.z, v.w);
    ((__half2*)out)[i * 2]     = a;
    ((__half2*)out)[i * 2 + 1] = b;
}

// ------- weight transpose float[R][C] -> half[C][R], batched -------
__global__ __launch_bounds__(256)
void trw_kernel(const float* __restrict__ in, __half* __restrict__ out,
                int R, int C, long sIn, long sOut)
{
    __shared__ float t[32][33];
    long z = blockIdx.z;
    const float* src = in + z * sIn;
    __half* dst = out + z * sOut;
    int c0 = blockIdx.x * 32, r0 = blockIdx.y * 32;
    int tx = threadIdx.x, ty = threadIdx.y;
    #pragma unroll
    for (int j = ty; j < 32; j += 8) {
        int r = r0 + j, cc = c0 + tx;
        if (r < R && cc < C) t[j][tx] = src[(long)r * C + cc];
    }
    __syncthreads();
    #pragma unroll
    for (int j = ty; j < 32; j += 8) {
        int cc = c0 + j, r = r0 + tx;
        if (r < R && cc < C) dst[(long)cc * R + r] = __float2half_rn(t[tx][j]);
    }
}

// ------- activation transpose half[R][C] -> half[C][R], batched -------
__global__ __launch_bounds__(256)
void trh_kernel(const __half* __restrict__ in, __half* __restrict__ out, int R, int C)
{
    __shared__ __half t[32][33];
    long z = blockIdx.z;
    const __half* src = in + z * (long)R * C;
    __half* dst = out + z * (long)R * C;
    int c0 = blockIdx.x * 32, r0 = blockIdx.y * 32;
    int tx = threadIdx.x, ty = threadIdx.y;
    #pragma unroll
    for (int j = ty; j < 32; j += 8) {
        int r = r0 + j, cc = c0 + tx;
        if (r < R && cc < C) t[j][tx] = src[(long)r * C + cc];
    }
    __syncthreads();
    #pragma unroll
    for (int j = ty; j < 32; j += 8) {
        int cc = c0 + j, r = r0 + tx;
        if (r < R && cc < C) dst[(long)cc * R + r] = t[tx][j];
    }
}

// ---------------- row softmax on half (pre-scale, padded stride) ----------
__global__ __launch_bounds__(256)
void softmax_kernel(__half* __restrict__ data, int n, int stride, float scale)
{
    long row = blockIdx.x;
    __half* p = data + row * (long)stride;
    int t = threadIdx.x;
    int w = t >> 5, lane = t & 31;

    float loc[4];
    int cnt = 0;
    float mx = -3.0e38f;
    for (int i = t; i < n; i += 256) {
        float v = __half2float(p[i]) * scale;
        loc[cnt++] = v;
        mx = fmaxf(mx, v);
    }
    #pragma unroll
    for (int o = 16; o > 0; o >>= 1) mx = fmaxf(mx, __shfl_xor_sync(0xffffffffu, mx, o));
    __shared__ float red[8];
    if (lane == 0) red[w] = mx;
    __syncthreads();
    if (t < 8) {
        float v = red[t];
        #pragma unroll
        for (int o = 4; o > 0; o >>= 1) v = fmaxf(v, __shfl_xor_sync(0xffu, v, o));
        if (t == 0) red[0] = v;
    }
    __syncthreads();
    mx = red[0];
    __syncthreads();

    float sum = 0.0f;
    for (int cc = 0; cc < cnt; cc++) {
        float e = __expf(loc[cc] - mx);
        loc[cc] = e;
        sum += e;
    }
    #pragma unroll
    for (int o = 16; o > 0; o >>= 1) sum += __shfl_xor_sync(0xffffffffu, sum, o);
    if (lane == 0) red[w] = sum;
    __syncthreads();
    if (t < 8) {
        float v = red[t];
        #pragma unroll
        for (int o = 4; o > 0; o >>= 1) v += __shfl_xor_sync(0xffu, v, o);
        if (t == 0) red[0] = v;
    }
    __syncthreads();
    float inv = 1.0f / red[0];

    cnt = 0;
    for (int i = t; i < n; i += 256) p[i] = __float2half_rn(loc[cnt++] * inv);
    for (int i = t; i < stride; i += 256) if (i >= n) p[i] = __float2half_rn(0.0f);
}

// -------- fused residual + LayerNorm; fp32 out (+ optional fp16 mirror) ------
__global__ __launch_bounds__(256)
void ln_kernel(const float* __restrict__ resid, const float* __restrict__ h,
               const float* __restrict__ gam, const float* __restrict__ bet,
               float* __restrict__ out, __half* __restrict__ outh, int J,
               long ri, long rj, long hi, long hj, long oi, long oj, long gstride)
{
    long b = blockIdx.x;
    long i = b / J, j = b % J;
    const float* r  = resid + (i * ri + j * rj) * DD;
    const float* hh = h     + (i * hi + j * hj) * DD;
    long orow = i * oi + j * oj;
    float* op = out + orow * DD;
    const float* gp = gam + i * gstride;
    const float* bp = bet + i * gstride;
    int t = threadIdx.x;
    int w = t >> 5, lane = t & 31;

    float v[3];
    float s = 0.0f, s2 = 0.0f;
    #pragma unroll
    for (int k = 0; k < 3; k++) {
        int d = t + k * 256;
        float val = r[d] + hh[d];
        v[k] = val;
        s += val;
        s2 += val * val;
    }
    #pragma unroll
    for (int o = 16; o > 0; o >>= 1) {
        s  += __shfl_xor_sync(0xffffffffu, s, o);
        s2 += __shfl_xor_sync(0xffffffffu, s2, o);
    }
    __shared__ float rs[8], rs2[8];
    if (lane == 0) { rs[w] = s; rs2[w] = s2; }
    __syncthreads();
    if (t < 8) {
        s = rs[t]; s2 = rs2[t];
        #pragma unroll
        for (int o = 4; o > 0; o >>= 1) {
            s  += __shfl_xor_sync(0xffu, s, o);
            s2 += __shfl_xor_sync(0xffu, s2, o);
        }
        if (t == 0) { rs[0] = s; rs2[0] = s2; }
    }
    __syncthreads();
    float mean = rs[0] * (1.0f / DD);
    float var  = rs2[0] * (1.0f / DD) - mean * mean;
    float inv  = rsqrtf(var + 1e-5f);

    #pragma unroll
    for (int k = 0; k < 3; k++) {
        int d = t + k * 256;
        float o = (v[k] - mean) * inv * gp[d] + bp[d];
        op[d] = o;
        if (outh) outh[orow * DD + d] = __float2half_rn(o);
    }
}

// ---------------- zero pad rows of xt_pad (float + half) ----------------
__global__ __launch_bounds__(256)
void zero_pad_kernel(float* __restrict__ xt, __half* __restrict__ xth)
{
    long idx = (long)blockIdx.x * 256 + threadIdx.x;
    const long per_l = (long)(SP - SS) * DD;
    const long total = (long)LL * per_l;
    if (idx >= total) return;
    long l = idx / per_l;
    long off = idx % per_l;
    long p = ((long)l * SP + SS) * DD + off;
    xt[p] = 0.0f;
    xth[p] = __float2half_rn(0.0f);
}

// ---------------- launch plumbing ----------------
static inline int cdiv(int a, int b) { return (a + b - 1) / b; }

template<int MODE>
static void launch_gemm(const __half* A, const __half* B, const float* bias, void* C,
                        int M, int N, int K, int lda, int ldb, int ldc, int batch,
                        long sA, long sB, long sBias, long sC)
{
    dim3 grid(cdiv(N, BNt), cdiv(M, BMt), batch);
    cudaFuncSetAttribute(mma_gemm_kernel<MODE>,
                         cudaFuncAttributeMaxDynamicSharedMemorySize, GEMM_SMEM_BYTES);
    mma_gemm_kernel<MODE><<<grid, 256, GEMM_SMEM_BYTES>>>(
        A, B, bias, C, M, N, K, lda, ldb, ldc, sA, sB, sBias, sC);
}

static void trw(const float* in, __half* out, int R, int C, int batch, long sIn, long sOut)
{
    dim3 grid(cdiv(C, 32), cdiv(R, 32), batch);
    trw_kernel<<<grid, dim3(32, 8)>>>(in, out, R, C, sIn, sOut);
}
static void trh(const __half* in, __half* out, int R, int C, int batch)
{
    dim3 grid(cdiv(C, 32), cdiv(R, 32), batch);
    trh_kernel<<<grid, dim3(32, 8)>>>(in, out, R, C);
}

extern "C" void kernel_launch(void* const* d_in, const int* in_sizes, int n_in,
                              void* d_out, int out_size)
{
    (void)in_sizes; (void)n_in; (void)out_size;

    const float* x        = (const float*)d_in[0];
    const float* pre_Wq   = (const float*)d_in[1];
    const float* pre_Wk   = (const float*)d_in[2];
    const float* pre_Wv   = (const float*)d_in[3];
    const float* ln1_g    = (const float*)d_in[4];
    const float* ln1_b    = (const float*)d_in[5];
    const float* pre_W1   = (const float*)d_in[6];
    const float* pre_b1   = (const float*)d_in[7];
    const float* pre_W2   = (const float*)d_in[8];
    const float* pre_b2   = (const float*)d_in[9];
    const float* ln4p_g   = (const float*)d_in[10];
    const float* ln4p_b   = (const float*)d_in[11];
    const float* cross_Wq = (const float*)d_in[12];
    const float* cross_Wk = (const float*)d_in[13];
    const float* cross_Wv = (const float*)d_in[14];
    const float* ln2_g    = (const float*)d_in[15];
    const float* ln2_b    = (const float*)d_in[16];
    const float* post_Wq  = (const float*)d_in[17];
    const float* post_Wk  = (const float*)d_in[18];
    const float* post_Wv  = (const float*)d_in[19];
    const float* ln3_g    = (const float*)d_in[20];
    const float* ln3_b    = (const float*)d_in[21];
    const float* post_W1  = (const float*)d_in[22];
    const float* post_b1  = (const float*)d_in[23];
    const float* post_W2  = (const float*)d_in[24];
    const float* post_b2  = (const float*)d_in[25];
    const float* ln4_g    = (const float*)d_in[26];
    const float* ln4_b    = (const float*)d_in[27];
    float* out = (float*)d_out;

    float *bufA, *bufB, *bufC, *xt_pad;
    __half *xh, *lnh, *xtph, *qkh, *avh, *scoresh, *hT, *wh;
    cudaGetSymbolAddress((void**)&bufA, g_bufA);
    cudaGetSymbolAddress((void**)&bufB, g_bufB);
    cudaGetSymbolAddress((void**)&bufC, g_bufC);
    cudaGetSymbolAddress((void**)&xt_pad, g_xtpad);
    cudaGetSymbolAddress((void**)&xh, g_xh);
    cudaGetSymbolAddress((void**)&lnh, g_lnh);
    cudaGetSymbolAddress((void**)&xtph, g_xtph);
    cudaGetSymbolAddress((void**)&qkh, g_qkh);
    cudaGetSymbolAddress((void**)&avh, g_avh);
    cudaGetSymbolAddress((void**)&scoresh, g_scoresh);
    cudaGetSymbolAddress((void**)&hT, g_hT);
    cudaGetSymbolAddress((void**)&wh, g_wh);

    // half weight layout (all [N][K] row-major, i.e. transposed)
    const long SZ_QKW = (long)SS * QKN * DD;
    const long SZ_VW  = (long)SS * DD * DD;
    const long SZ_W1  = (long)SS * DD4 * DD;   // W1^T [D4][D]
    __half* qkPreT   = wh;
    __half* qkPostT  = qkPreT  + SZ_QKW;
    __half* qkCrossT = qkPostT + SZ_QKW;
    __half* WvPreT   = qkCrossT + (long)QKN * DD;
    __half* WvPostT  = WvPreT  + SZ_VW;
    __half* WvCrossT = WvPostT + SZ_VW;
    __half* W1PreT   = WvCrossT + (long)DD * DD;
    __half* W1PostT  = W1PreT  + SZ_W1;
    __half* W2PreT   = W1PostT + SZ_W1;        // W2^T [D][D4]
    __half* W2PostT  = W2PreT  + SZ_W1;

    const float scale = 1.0f / sqrtf((float)DD4);
    const long LD = (long)LL * DD;

    // ---------------- weight prep: transpose + f16 ----------------
    // qk concat: Wq^T into rows [0,192), Wk^T into rows [192,384)
    trw(pre_Wq,  qkPreT,                  DD, DD4, SS, (long)DD * DD4, (long)QKN * DD);
    trw(pre_Wk,  qkPreT + (long)DD4 * DD, DD, DD4, SS, (long)DD * DD4, (long)QKN * DD);
    trw(post_Wq, qkPostT,                  DD, DD4, SS, (long)DD * DD4, (long)QKN * DD);
    trw(post_Wk, qkPostT + (long)DD4 * DD, DD, DD4, SS, (long)DD * DD4, (long)QKN * DD);
    trw(cross_Wq, qkCrossT,                  DD, DD4, 1, 0, 0);
    trw(cross_Wk, qkCrossT + (long)DD4 * DD, DD, DD4, 1, 0, 0);
    trw(pre_Wv,  WvPreT,  DD, DD, SS, (long)DD * DD, (long)DD * DD);
    trw(post_Wv, WvPostT, DD, DD, SS, (long)DD * DD, (long)DD * DD);
    trw(cross_Wv, WvCrossT, DD, DD, 1, 0, 0);
    trw(pre_W1,  W1PreT,  DD, DD4, SS, (long)DD * DD4, (long)DD4 * DD);
    trw(post_W1, W1PostT, DD, DD4, SS, (long)DD * DD4, (long)DD4 * DD);
    trw(pre_W2,  W2PreT,  DD4, DD, SS, (long)DD4 * DD, (long)DD * DD4);
    trw(post_W2, W2PostT, DD4, DD, SS, (long)DD4 * DD, (long)DD * DD4);

    // xh = f16(x)
    f2h_kernel<<<cdiv((int)(SS * LD / 4), 256), 256>>>(x, xh, SS * LD / 4);

    // ================= pre_self_step attention =================
    launch_gemm<3>(xh, qkPreT, nullptr, qkh, LL, QKN, DD, DD, DD, QKN, SS,
                   LD, SZ_QKW / SS, 0, (long)LL * QKN);
    launch_gemm<3>(qkh, qkh + DD4, nullptr, scoresh, LL, LL, DD4, QKN, QKN, LL, SS,
                   (long)LL * QKN, (long)LL * QKN, 0, (long)LL * LL);
    softmax_kernel<<<SS * LL, 256>>>(scoresh, LL, LL, scale);
    trh(xh, hT, LL, DD, SS);   // hT = x^T [S][D][L]
    launch_gemm<3>(scoresh, hT, nullptr, avh, LL, DD, LL, LL, LL, DD, SS,
                   (long)LL * LL, LD, 0, LD);
    launch_gemm<0>(avh, WvPreT, nullptr, bufB, LL, DD, DD, DD, DD, DD, SS,
                   LD, (long)DD * DD, 0, LD);
    ln_kernel<<<SS * LL, 256>>>(x, bufB, ln1_g, ln1_b, bufA, lnh, LL,
                                LL, 1, LL, 1, LL, 1, DD);

    // ================= pre_mlp =================
    launch_gemm<2>(lnh, W1PreT, pre_b1, qkh, LL, DD4, DD, DD, DD, DD4, SS,
                   LD, (long)DD4 * DD, DD4, (long)LL * DD4);
    launch_gemm<1>(qkh, W2PreT, pre_b2, bufB, LL, DD, DD4, DD4, DD4, DD, SS,
                   (long)LL * DD4, (long)DD * DD4, DD, LD);
    ln_kernel<<<SS * LL, 256>>>(bufA, bufB, ln4p_g, ln4p_b, xt_pad, xtph, LL,
                                LL, 1, LL, 1, 1, SP, DD);
    zero_pad_kernel<<<cdiv(LL * (SP - SS) * DD, 256), 256>>>(xt_pad, xtph);

    // ================= cross_step attention (padded S -> SP) =================
    launch_gemm<3>(xtph, qkCrossT, nullptr, qkh, LL * SP, QKN, DD, DD, DD, QKN, 1,
                   0, 0, 0, 0);
    launch_gemm<3>(qkh, qkh + DD4, nullptr, scoresh, SP, SP, DD4, QKN, QKN, SP, LL,
                   (long)SP * QKN, (long)SP * QKN, 0, (long)SP * SP);
    softmax_kernel<<<LL * SP, 256>>>(scoresh, SS, SP, scale);
    trh(xtph, hT, SP, DD, LL);  // hT = xtp^T [L][D][SP]
    launch_gemm<3>(scoresh, hT, nullptr, avh, SS, DD, SP, SP, SP, DD, LL,
                   (long)SP * SP, (long)DD * SP, 0, (long)SS * DD);
    launch_gemm<0>(avh, WvCrossT, nullptr, bufB, LL * SS, DD, DD, DD, DD, DD, 1,
                   0, 0, 0, 0);
    ln_kernel<<<LL * SS, 256>>>(xt_pad, bufB, ln2_g, ln2_b, bufA, lnh, SS,
                                SP, 1, SS, 1, 1, LL, 0);

    // ================= post_self_step attention =================
    launch_gemm<3>(lnh, qkPostT, nullptr, qkh, LL, QKN, DD, DD, DD, QKN, SS,
                   LD, SZ_QKW / SS, 0, (long)LL * QKN);
    launch_gemm<3>(qkh, qkh + DD4, nullptr, scoresh, LL, LL, DD4, QKN, QKN, LL, SS,
                   (long)LL * QKN, (long)LL * QKN, 0, (long)LL * LL);
    softmax_kernel<<<SS * LL, 256>>>(scoresh, LL, LL, scale);
    trh(lnh, hT, LL, DD, SS);
    launch_gemm<3>(scoresh, hT, nullptr, avh, LL, DD, LL, LL, LL, DD, SS,
                   (long)LL * LL, LD, 0, LD);
    launch_gemm<0>(avh, WvPostT, nullptr, bufB, LL, DD, DD, DD, DD, DD, SS,
                   LD, (long)DD * DD, 0, LD);
    ln_kernel<<<SS * LL, 256>>>(bufA, bufB, ln3_g, ln3_b, bufC, lnh, LL,
                                LL, 1, LL, 1, LL, 1, DD);

    // ================= post_mlp =================
    launch_gemm<2>(lnh, W1PostT, post_b1, qkh, LL, DD4, DD, DD, DD, DD4, SS,
                   LD, (long)DD4 * DD, DD4, (long)LL * DD4);
    launch_gemm<1>(qkh, W2PostT, post_b2, bufB, LL, DD, DD4, DD4, DD4, DD, SS,
                   (long)LL * DD4, (long)DD * DD4, DD, LD);
    ln_kernel<<<SS * LL, 256>>>(bufC, bufB, ln4_g, ln4_b, out, nullptr, LL,
                                LL, 1, LL, 1, LL, 1, DD);
}

// round 11
// speedup vs baseline: 1.6828x; 1.0436x over previous
#include <cuda_runtime.h>
#include <cuda_fp16.h>
#include <math.h>
#include <stdint.h>

// Problem dims
#define SS 50
#define LL 1024
#define DD 768
#define DD4 192
#define SP 64   // padded step dim for cross attention
#define QKN 384 // fused q||k projection width

// ---------------- static scratch (alloc-free rule) ----------------
__device__ float  g_bufA[(size_t)SS * LL * DD];
__device__ float  g_bufB[(size_t)SS * LL * DD];
__device__ float  g_bufC[(size_t)SS * LL * DD];
__device__ float  g_xtpad[(size_t)LL * SP * DD];
__device__ __half g_xh[(size_t)SS * LL * DD];
__device__ __half g_lnh[(size_t)SS * LL * DD];
__device__ __half g_xtph[(size_t)LL * SP * DD];
__device__ __half g_qkh[(size_t)LL * SP * QKN];
__device__ __half g_avh[(size_t)SS * LL * DD];
__device__ __half g_scoresh[(size_t)SS * LL * LL];
__device__ __half g_hT[(size_t)LL * DD * SP];
__device__ __half g_wh[119000000];

// =============== helpers =====================
__device__ __forceinline__ uint32_t smem_u32(const void* p) {
    uint32_t a;
    asm("{ .reg .u64 t; cvta.to.shared.u64 t, %1; cvt.u32.u64 %0, t; }" : "=r"(a) : "l"(p));
    return a;
}
__device__ __forceinline__ void mma_f16(float* d, const uint32_t* a, const uint32_t* b) {
    asm volatile(
        "mma.sync.aligned.m16n8k16.row.col.f32.f16.f16.f32 "
        "{%0,%1,%2,%3}, {%4,%5,%6,%7}, {%8,%9}, {%0,%1,%2,%3};\n"
        : "+f"(d[0]), "+f"(d[1]), "+f"(d[2]), "+f"(d[3])
        : "r"(a[0]), "r"(a[1]), "r"(a[2]), "r"(a[3]),
          "r"(b[0]), "r"(b[1]));
}
__device__ __forceinline__ void ldsm_x4(uint32_t& r0, uint32_t& r1, uint32_t& r2, uint32_t& r3,
                                        uint32_t addr) {
    asm volatile("ldmatrix.sync.aligned.m8n8.x4.shared.b16 {%0,%1,%2,%3}, [%4];"
                 : "=r"(r0), "=r"(r1), "=r"(r2), "=r"(r3) : "r"(addr));
}
__device__ __forceinline__ void cp_async16(uint32_t smem_addr, const void* gptr, uint32_t src_bytes) {
    asm volatile("cp.async.ca.shared.global [%0], [%1], 16, %2;"
                 :: "r"(smem_addr), "l"(gptr), "r"(src_bytes));
}
#define CP_COMMIT() asm volatile("cp.async.commit_group;" ::: "memory")
#define CP_WAIT2()  asm volatile("cp.async.wait_group 2;" ::: "memory")

// =================================================================
// cp.async-pipelined FP16 NT GEMM (mma.sync m16n8k16, ldmatrix frags)
// C[b] = A[b] @ B[b]^T   A:[M,K] half, B:[N,K] half, K % 32 == 0
// CTA 128x256, 8 warps, warp tile 64x64, K-tile 32, 4-stage ring.
// MODE: 0 f32 out | 1 f32 out +bias | 2 f16 out +bias+relu | 3 f16 out
// =================================================================
#define BMt 128
#define BNt 256
#define RS 20                    // smem row stride in 4B words (40 halves, 80B)
#define AWORDS (BMt * RS)
#define BWORDS (BNt * RS)
#define STGW (AWORDS + BWORDS)
#define NSTAGE 4
#define GEMM_SMEM_BYTES (NSTAGE * STGW * 4)   // 122880

template<int MODE>
__global__ __launch_bounds__(256, 1)
void mma_gemm_kernel(const __half* __restrict__ Ab, const __half* __restrict__ Bb,
                     const float* __restrict__ biasb, void* __restrict__ Cb,
                     int M, int N, int K, int lda, int ldb, int ldc,
                     long sA, long sB, long sBias, long sC)
{
    constexpr bool BIAS = (MODE == 1 || MODE == 2);
    constexpr bool RELU = (MODE == 2);
    constexpr bool OUTH = (MODE >= 2);

    extern __shared__ __align__(16) uint32_t sm[];
    const uint32_t smb = smem_u32(sm);

    const int b = blockIdx.z;
    const __half* A = Ab + (long)b * sA;
    const __half* B = Bb + (long)b * sB;

    const int brow = blockIdx.y * BMt;
    const int bcol = blockIdx.x * BNt;
    const int tid = threadIdx.x;
    const int wid = tid >> 5;
    const int lane = tid & 31;
    const int g = lane >> 2;
    const int c = lane & 3;
    const int warp_m = (wid & 1) * 64;
    const int warp_n = (wid >> 1) * 64;

    // ldmatrix lane-address components (halves)
    const int a_row = (lane & 7) + ((lane >> 3) & 1) * 8;   // row within 16-row block
    const int a_koff = ((lane >> 4) & 1) * 8;               // k-half offset
    const int b_row = (lane & 7) + ((lane >> 4) & 1) * 8;   // n within 16-col pair
    const int b_koff = ((lane >> 3) & 1) * 8;

    const int nkt = K >> 5;

    float acc[4][8][4];
    #pragma unroll
    for (int i = 0; i < 4; i++)
        #pragma unroll
        for (int j = 0; j < 8; j++)
            #pragma unroll
            for (int r = 0; r < 4; r++)
                acc[i][j][r] = 0.0f;

    auto issue_stage = [&](int kt) {
        if (kt < nkt) {
            int k0 = kt << 5;
            uint32_t sbase = smb + ((kt & (NSTAGE - 1)) * STGW) * 4;
            #pragma unroll
            for (int i = 0; i < 2; i++) {
                int idx = i * 256 + tid;
                int row = idx >> 2, q = idx & 3;
                int gr = brow + row;
                const __half* gp = A + (long)gr * lda + k0 + q * 8;
                uint32_t dst = sbase + (row * RS + q * 4) * 4;
                cp_async16(dst, gp, (gr < M) ? 16u : 0u);
            }
            #pragma unroll
            for (int i = 0; i < 4; i++) {
                int idx = i * 256 + tid;
                int row = idx >> 2, q = idx & 3;
                int gn = bcol + row;
                const __half* gp = B + (long)gn * ldb + k0 + q * 8;
                uint32_t dst = sbase + (AWORDS + row * RS + q * 4) * 4;
                cp_async16(dst, gp, (gn < N) ? 16u : 0u);
            }
        }
        CP_COMMIT();
    };

    issue_stage(0);
    issue_stage(1);
    issue_stage(2);

    for (int kt = 0; kt < nkt; kt++) {
        CP_WAIT2();
        __syncthreads();
        issue_stage(kt + 3);

        uint32_t As = smb + ((kt & (NSTAGE - 1)) * STGW) * 4;
        uint32_t Bs = As + AWORDS * 4;

        #pragma unroll
        for (int ks = 0; ks < 2; ks++) {         // two k16 steps
            int kh = ks * 16;                    // k-half base
            uint32_t af[4][4], bf[8][2];
            #pragma unroll
            for (int am = 0; am < 4; am++) {
                uint32_t addr = As + ((warp_m + am * 16 + a_row) * RS) * 4
                                   + (kh + a_koff) * 2;
                ldsm_x4(af[am][0], af[am][1], af[am][2], af[am][3], addr);
            }
            #pragma unroll
            for (int p = 0; p < 4; p++) {        // each x4 covers bn=2p, 2p+1
                uint32_t addr = Bs + ((warp_n + p * 16 + b_row) * RS) * 4
                                   + (kh + b_koff) * 2;
                ldsm_x4(bf[2 * p][0], bf[2 * p][1], bf[2 * p + 1][0], bf[2 * p + 1][1], addr);
            }
            #pragma unroll
            for (int am = 0; am < 4; am++)
                #pragma unroll
                for (int bn = 0; bn < 8; bn++)
                    mma_f16(acc[am][bn], af[am], bf[bn]);
        }
    }

    // ---- epilogue ----
    #pragma unroll
    for (int am = 0; am < 4; am++) {
        int row0 = brow + warp_m + am * 16 + g;
        #pragma unroll
        for (int bn = 0; bn < 8; bn++) {
            int col = bcol + warp_n + bn * 8 + c * 2;
            if (col >= N) continue;
            float v0 = acc[am][bn][0], v1 = acc[am][bn][1];
            float v2 = acc[am][bn][2], v3 = acc[am][bn][3];
            if (BIAS) {
                float b0 = biasb[(long)b * sBias + col];
                float b1 = biasb[(long)b * sBias + col + 1];
                v0 += b0; v1 += b1; v2 += b0; v3 += b1;
            }
            if (RELU) {
                v0 = fmaxf(v0, 0.f); v1 = fmaxf(v1, 0.f);
                v2 = fmaxf(v2, 0.f); v3 = fmaxf(v3, 0.f);
            }
            if (OUTH) {
                __half* C = (__half*)Cb + (long)b * sC;
                __half2 h01 = __floats2half2_rn(v0, v1);
                __half2 h23 = __floats2half2_rn(v2, v3);
                if (row0 < M)     *(__half2*)&C[(long)row0 * ldc + col]       = h01;
                if (row0 + 8 < M) *(__half2*)&C[(long)(row0 + 8) * ldc + col] = h23;
            } else {
                float* C = (float*)Cb + (long)b * sC;
                if (row0 < M)     *(float2*)&C[(long)row0 * ldc + col]       = make_float2(v0, v1);
                if (row0 + 8 < M) *(float2*)&C[(long)(row0 + 8) * ldc + col] = make_float2(v2, v3);
            }
        }
    }
}

// ---------------- float -> half elementwise (x) ----------------
__global__ __launch_bounds__(256)
void f2h_kernel(const float* __restrict__ in, __half* __restrict__ out, long n4)
{
    long i = (long)blockIdx.x * 256 + threadIdx.x;
    if (i >= n4) return;
    float4 v = ((const float4*)in)[i];
    ((__half2*)out)[i * 2]     = __floats2half2_rn(v.x, v.y);
    ((__half2*)out)[i * 2 + 1] = __floats2half2_rn(v.z, v.w);
}

// ------- weight transpose float[R][C] -> half[C][R], batched -------
__global__ __launch_bounds__(256)
void trw_kernel(const float* __restrict__ in, __half* __restrict__ out,
                int R, int C, long sIn, long sOut)
{
    __shared__ float t[32][33];
    long z = blockIdx.z;
    const float* src = in + z * sIn;
    __half* dst = out + z * sOut;
    int c0 = blockIdx.x * 32, r0 = blockIdx.y * 32;
    int tx = threadIdx.x, ty = threadIdx.y;
    #pragma unroll
    for (int j = ty; j < 32; j += 8) {
        int r = r0 + j, cc = c0 + tx;
        if (r < R && cc < C) t[j][tx] = src[(long)r * C + cc];
    }
    __syncthreads();
    #pragma unroll
    for (int j = ty; j < 32; j += 8) {
        int cc = c0 + j, r = r0 + tx;
        if (r < R && cc < C) dst[(long)cc * R + r] = __float2half_rn(t[tx][j]);
    }
}

// ------- activation transpose half[R][C] -> half[C][R], batched -------
__global__ __launch_bounds__(256)
void trh_kernel(const __half* __restrict__ in, __half* __restrict__ out, int R, int C)
{
    __shared__ __half t[32][33];
    long z = blockIdx.z;
    const __half* src = in + z * (long)R * C;
    __half* dst = out + z * (long)R * C;
    int c0 = blockIdx.x * 32, r0 = blockIdx.y * 32;
    int tx = threadIdx.x, ty = threadIdx.y;
    #pragma unroll
    for (int j = ty; j < 32; j += 8) {
        int r = r0 + j, cc = c0 + tx;
        if (r < R && cc < C) t[j][tx] = src[(long)r * C + cc];
    }
    __syncthreads();
    #pragma unroll
    for (int j = ty; j < 32; j += 8) {
        int cc = c0 + j, r = r0 + tx;
        if (r < R && cc < C) dst[(long)cc * R + r] = t[tx][j];
    }
}

// ---------------- row softmax on half (pre-scale, padded stride) ----------
__global__ __launch_bounds__(256)
void softmax_kernel(__half* __restrict__ data, int n, int stride, float scale)
{
    long row = blockIdx.x;
    __half* p = data + row * (long)stride;
    int t = threadIdx.x;
    int w = t >> 5, lane = t & 31;

    float loc[4];
    int cnt = 0;
    float mx = -3.0e38f;
    for (int i = t; i < n; i += 256) {
        float v = __half2float(p[i]) * scale;
        loc[cnt++] = v;
        mx = fmaxf(mx, v);
    }
    #pragma unroll
    for (int o = 16; o > 0; o >>= 1) mx = fmaxf(mx, __shfl_xor_sync(0xffffffffu, mx, o));
    __shared__ float red[8];
    if (lane == 0) red[w] = mx;
    __syncthreads();
    if (t < 8) {
        float v = red[t];
        #pragma unroll
        for (int o = 4; o > 0; o >>= 1) v = fmaxf(v, __shfl_xor_sync(0xffu, v, o));
        if (t == 0) red[0] = v;
    }
    __syncthreads();
    mx = red[0];
    __syncthreads();

    float sum = 0.0f;
    for (int cc = 0; cc < cnt; cc++) {
        float e = __expf(loc[cc] - mx);
        loc[cc] = e;
        sum += e;
    }
    #pragma unroll
    for (int o = 16; o > 0; o >>= 1) sum += __shfl_xor_sync(0xffffffffu, sum, o);
    if (lane == 0) red[w] = sum;
    __syncthreads();
    if (t < 8) {
        float v = red[t];
        #pragma unroll
        for (int o = 4; o > 0; o >>= 1) v += __shfl_xor_sync(0xffu, v, o);
        if (t == 0) red[0] = v;
    }
    __syncthreads();
    float inv = 1.0f / red[0];

    cnt = 0;
    for (int i = t; i < n; i += 256) p[i] = __float2half_rn(loc[cnt++] * inv);
    for (int i = t; i < stride; i += 256) if (i >= n) p[i] = __float2half_rn(0.0f);
}

// -------- fused residual + LayerNorm; fp32 out (+ optional fp16 mirror) ------
__global__ __launch_bounds__(256)
void ln_kernel(const float* __restrict__ resid, const float* __restrict__ h,
               const float* __restrict__ gam, const float* __restrict__ bet,
               float* __restrict__ out, __half* __restrict__ outh, int J,
               long ri, long rj, long hi, long hj, long oi, long oj, long gstride)
{
    long b = blockIdx.x;
    long i = b / J, j = b % J;
    const float* r  = resid + (i * ri + j * rj) * DD;
    const float* hh = h     + (i * hi + j * hj) * DD;
    long orow = i * oi + j * oj;
    float* op = out + orow * DD;
    const float* gp = gam + i * gstride;
    const float* bp = bet + i * gstride;
    int t = threadIdx.x;
    int w = t >> 5, lane = t & 31;

    float v[3];
    float s = 0.0f, s2 = 0.0f;
    #pragma unroll
    for (int k = 0; k < 3; k++) {
        int d = t + k * 256;
        float val = r[d] + hh[d];
        v[k] = val;
        s += val;
        s2 += val * val;
    }
    #pragma unroll
    for (int o = 16; o > 0; o >>= 1) {
        s  += __shfl_xor_sync(0xffffffffu, s, o);
        s2 += __shfl_xor_sync(0xffffffffu, s2, o);
    }
    __shared__ float rs[8], rs2[8];
    if (lane == 0) { rs[w] = s; rs2[w] = s2; }
    __syncthreads();
    if (t < 8) {
        s = rs[t]; s2 = rs2[t];
        #pragma unroll
        for (int o = 4; o > 0; o >>= 1) {
            s  += __shfl_xor_sync(0xffu, s, o);
            s2 += __shfl_xor_sync(0xffu, s2, o);
        }
        if (t == 0) { rs[0] = s; rs2[0] = s2; }
    }
    __syncthreads();
    float mean = rs[0] * (1.0f / DD);
    float var  = rs2[0] * (1.0f / DD) - mean * mean;
    float inv  = rsqrtf(var + 1e-5f);

    #pragma unroll
    for (int k = 0; k < 3; k++) {
        int d = t + k * 256;
        float o = (v[k] - mean) * inv * gp[d] + bp[d];
        op[d] = o;
        if (outh) outh[orow * DD + d] = __float2half_rn(o);
    }
}

// ---------------- zero pad rows of xt_pad (float + half) ----------------
__global__ __launch_bounds__(256)
void zero_pad_kernel(float* __restrict__ xt, __half* __restrict__ xth)
{
    long idx = (long)blockIdx.x * 256 + threadIdx.x;
    const long per_l = (long)(SP - SS) * DD;
    const long total = (long)LL * per_l;
    if (idx >= total) return;
    long l = idx / per_l;
    long off = idx % per_l;
    long p = ((long)l * SP + SS) * DD + off;
    xt[p] = 0.0f;
    xth[p] = __float2half_rn(0.0f);
}

// ---------------- launch plumbing ----------------
static inline int cdiv(int a, int b) { return (a + b - 1) / b; }

template<int MODE>
static void launch_gemm(const __half* A, const __half* B, const float* bias, void* C,
                        int M, int N, int K, int lda, int ldb, int ldc, int batch,
                        long sA, long sB, long sBias, long sC)
{
    dim3 grid(cdiv(N, BNt), cdiv(M, BMt), batch);
    cudaFuncSetAttribute(mma_gemm_kernel<MODE>,
                         cudaFuncAttributeMaxDynamicSharedMemorySize, GEMM_SMEM_BYTES);
    mma_gemm_kernel<MODE><<<grid, 256, GEMM_SMEM_BYTES>>>(
        A, B, bias, C, M, N, K, lda, ldb, ldc, sA, sB, sBias, sC);
}

static void trw(const float* in, __half* out, int R, int C, int batch, long sIn, long sOut)
{
    dim3 grid(cdiv(C, 32), cdiv(R, 32), batch);
    trw_kernel<<<grid, dim3(32, 8)>>>(in, out, R, C, sIn, sOut);
}
static void trh(const __half* in, __half* out, int R, int C, int batch)
{
    dim3 grid(cdiv(C, 32), cdiv(R, 32), batch);
    trh_kernel<<<grid, dim3(32, 8)>>>(in, out, R, C);
}

extern "C" void kernel_launch(void* const* d_in, const int* in_sizes, int n_in,
                              void* d_out, int out_size)
{
    (void)in_sizes; (void)n_in; (void)out_size;

    const float* x        = (const float*)d_in[0];
    const float* pre_Wq   = (const float*)d_in[1];
    const float* pre_Wk   = (const float*)d_in[2];
    const float* pre_Wv   = (const float*)d_in[3];
    const float* ln1_g    = (const float*)d_in[4];
    const float* ln1_b    = (const float*)d_in[5];
    const float* pre_W1   = (const float*)d_in[6];
    const float* pre_b1   = (const float*)d_in[7];
    const float* pre_W2   = (const float*)d_in[8];
    const float* pre_b2   = (const float*)d_in[9];
    const float* ln4p_g   = (const float*)d_in[10];
    const float* ln4p_b   = (const float*)d_in[11];
    const float* cross_Wq = (const float*)d_in[12];
    const float* cross_Wk = (const float*)d_in[13];
    const float* cross_Wv = (const float*)d_in[14];
    const float* ln2_g    = (const float*)d_in[15];
    const float* ln2_b    = (const float*)d_in[16];
    const float* post_Wq  = (const float*)d_in[17];
    const float* post_Wk  = (const float*)d_in[18];
    const float* post_Wv  = (const float*)d_in[19];
    const float* ln3_g    = (const float*)d_in[20];
    const float* ln3_b    = (const float*)d_in[21];
    const float* post_W1  = (const float*)d_in[22];
    const float* post_b1  = (const float*)d_in[23];
    const float* post_W2  = (const float*)d_in[24];
    const float* post_b2  = (const float*)d_in[25];
    const float* ln4_g    = (const float*)d_in[26];
    const float* ln4_b    = (const float*)d_in[27];
    float* out = (float*)d_out;

    float *bufA, *bufB, *bufC, *xt_pad;
    __half *xh, *lnh, *xtph, *qkh, *avh, *scoresh, *hT, *wh;
    cudaGetSymbolAddress((void**)&bufA, g_bufA);
    cudaGetSymbolAddress((void**)&bufB, g_bufB);
    cudaGetSymbolAddress((void**)&bufC, g_bufC);
    cudaGetSymbolAddress((void**)&xt_pad, g_xtpad);
    cudaGetSymbolAddress((void**)&xh, g_xh);
    cudaGetSymbolAddress((void**)&lnh, g_lnh);
    cudaGetSymbolAddress((void**)&xtph, g_xtph);
    cudaGetSymbolAddress((void**)&qkh, g_qkh);
    cudaGetSymbolAddress((void**)&avh, g_avh);
    cudaGetSymbolAddress((void**)&scoresh, g_scoresh);
    cudaGetSymbolAddress((void**)&hT, g_hT);
    cudaGetSymbolAddress((void**)&wh, g_wh);

    const long SZ_QKW = (long)SS * QKN * DD;
    const long SZ_VW  = (long)SS * DD * DD;
    const long SZ_W1  = (long)SS * DD4 * DD;
    __half* qkPreT   = wh;
    __half* qkPostT  = qkPreT  + SZ_QKW;
    __half* qkCrossT = qkPostT + SZ_QKW;
    __half* WvPreT   = qkCrossT + (long)QKN * DD;
    __half* WvPostT  = WvPreT  + SZ_VW;
    __half* WvCrossT = WvPostT + SZ_VW;
    __half* W1PreT   = WvCrossT + (long)DD * DD;
    __half* W1PostT  = W1PreT  + SZ_W1;
    __half* W2PreT   = W1PostT + SZ_W1;
    __half* W2PostT  = W2PreT  + SZ_W1;

    const float scale = 1.0f / sqrtf((float)DD4);
    const long LD = (long)LL * DD;

    // ---------------- weight prep: transpose + f16 ----------------
    trw(pre_Wq,  qkPreT,                  DD, DD4, SS, (long)DD * DD4, (long)QKN * DD);
    trw(pre_Wk,  qkPreT + (long)DD4 * DD, DD, DD4, SS, (long)DD * DD4, (long)QKN * DD);
    trw(post_Wq, qkPostT,                  DD, DD4, SS, (long)DD * DD4, (long)QKN * DD);
    trw(post_Wk, qkPostT + (long)DD4 * DD, DD, DD4, SS, (long)DD * DD4, (long)QKN * DD);
    trw(cross_Wq, qkCrossT,                  DD, DD4, 1, 0, 0);
    trw(cross_Wk, qkCrossT + (long)DD4 * DD, DD, DD4, 1, 0, 0);
    trw(pre_Wv,  WvPreT,  DD, DD, SS, (long)DD * DD, (long)DD * DD);
    trw(post_Wv, WvPostT, DD, DD, SS, (long)DD * DD, (long)DD * DD);
    trw(cross_Wv, WvCrossT, DD, DD, 1, 0, 0);
    trw(pre_W1,  W1PreT,  DD, DD4, SS, (long)DD * DD4, (long)DD4 * DD);
    trw(post_W1, W1PostT, DD, DD4, SS, (long)DD * DD4, (long)DD4 * DD);
    trw(pre_W2,  W2PreT,  DD4, DD, SS, (long)DD4 * DD, (long)DD * DD4);
    trw(post_W2, W2PostT, DD4, DD, SS, (long)DD4 * DD, (long)DD * DD4);

    f2h_kernel<<<cdiv((int)(SS * LD / 4), 256), 256>>>(x, xh, SS * LD / 4);

    // ================= pre_self_step attention =================
    launch_gemm<3>(xh, qkPreT, nullptr, qkh, LL, QKN, DD, DD, DD, QKN, SS,
                   LD, SZ_QKW / SS, 0, (long)LL * QKN);
    launch_gemm<3>(qkh, qkh + DD4, nullptr, scoresh, LL, LL, DD4, QKN, QKN, LL, SS,
                   (long)LL * QKN, (long)LL * QKN, 0, (long)LL * LL);
    softmax_kernel<<<SS * LL, 256>>>(scoresh, LL, LL, scale);
    trh(xh, hT, LL, DD, SS);
    launch_gemm<3>(scoresh, hT, nullptr, avh, LL, DD, LL, LL, LL, DD, SS,
                   (long)LL * LL, LD, 0, LD);
    launch_gemm<0>(avh, WvPreT, nullptr, bufB, LL, DD, DD, DD, DD, DD, SS,
                   LD, (long)DD * DD, 0, LD);
    ln_kernel<<<SS * LL, 256>>>(x, bufB, ln1_g, ln1_b, bufA, lnh, LL,
                                LL, 1, LL, 1, LL, 1, DD);

    // ================= pre_mlp =================
    launch_gemm<2>(lnh, W1PreT, pre_b1, qkh, LL, DD4, DD, DD, DD, DD4, SS,
                   LD, (long)DD4 * DD, DD4, (long)LL * DD4);
    launch_gemm<1>(qkh, W2PreT, pre_b2, bufB, LL, DD, DD4, DD4, DD4, DD, SS,
                   (long)LL * DD4, (long)DD * DD4, DD, LD);
    ln_kernel<<<SS * LL, 256>>>(bufA, bufB, ln4p_g, ln4p_b, xt_pad, xtph, LL,
                                LL, 1, LL, 1, 1, SP, DD);
    zero_pad_kernel<<<cdiv(LL * (SP - SS) * DD, 256), 256>>>(xt_pad, xtph);

    // ================= cross_step attention (padded S -> SP) =================
    launch_gemm<3>(xtph, qkCrossT, nullptr, qkh, LL * SP, QKN, DD, DD, DD, QKN, 1,
                   0, 0, 0, 0);
    launch_gemm<3>(qkh, qkh + DD4, nullptr, scoresh, SP, SP, DD4, QKN, QKN, SP, LL,
                   (long)SP * QKN, (long)SP * QKN, 0, (long)SP * SP);
    softmax_kernel<<<LL * SP, 256>>>(scoresh, SS, SP, scale);
    trh(xtph, hT, SP, DD, LL);
    launch_gemm<3>(scoresh, hT, nullptr, avh, SS, DD, SP, SP, SP, DD, LL,
                   (long)SP * SP, (long)DD * SP, 0, (long)SS * DD);
    launch_gemm<0>(avh, WvCrossT, nullptr, bufB, LL * SS, DD, DD, DD, DD, DD, 1,
                   0, 0, 0, 0);
    ln_kernel<<<LL * SS, 256>>>(xt_pad, bufB, ln2_g, ln2_b, bufA, lnh, SS,
                                SP, 1, SS, 1, 1, LL, 0);

    // ================= post_self_step attention =================
    launch_gemm<3>(lnh, qkPostT, nullptr, qkh, LL, QKN, DD, DD, DD, QKN, SS,
                   LD, SZ_QKW / SS, 0, (long)LL * QKN);
    launch_gemm<3>(qkh, qkh + DD4, nullptr, scoresh, LL, LL, DD4, QKN, QKN, LL, SS,
                   (long)LL * QKN, (long)LL * QKN, 0, (long)LL * LL);
    softmax_kernel<<<SS * LL, 256>>>(scoresh, LL, LL, scale);
    trh(lnh, hT, LL, DD, SS);
    launch_gemm<3>(scoresh, hT, nullptr, avh, LL, DD, LL, LL, LL, DD, SS,
                   (long)LL * LL, LD, 0, LD);
    launch_gemm<0>(avh, WvPostT, nullptr, bufB, LL, DD, DD, DD, DD, DD, SS,
                   LD, (long)DD * DD, 0, LD);
    ln_kernel<<<SS * LL, 256>>>(bufA, bufB, ln3_g, ln3_b, bufC, lnh, LL,
                                LL, 1, LL, 1, LL, 1, DD);

    // ================= post_mlp =================
    launch_gemm<2>(lnh, W1PostT, post_b1, qkh, LL, DD4, DD, DD, DD, DD4, SS,
                   LD, (long)DD4 * DD, DD4, (long)LL * DD4);
    launch_gemm<1>(qkh, W2PostT, post_b2, bufB, LL, DD, DD4, DD4, DD4, DD, SS,
                   (long)LL * DD4, (long)DD * DD4, DD, LD);
    ln_kernel<<<SS * LL, 256>>>(bufC, bufB, ln4_g, ln4_b, out, nullptr, LL,
                                LL, 1, LL, 1, LL, 1, DD);
}

// round 12
// speedup vs baseline: 2.0300x; 1.2063x over previous
#include <cuda_runtime.h>
#include <cuda_fp16.h>
#include <math.h>
#include <stdint.h>

// Problem dims
#define SS 50
#define LL 1024
#define DD 768
#define DD4 192
#define SP 64   // padded step dim for cross attention
#define QKN 384 // fused q||k projection width

// ---------------- static scratch (alloc-free rule) ----------------
__device__ __half g_xh[(size_t)SS * LL * DD];        // 39.3M
__device__ __half g_lnh[(size_t)SS * LL * DD];       // 39.3M
__device__ __half g_xtph[(size_t)LL * SP * DD];      // 50.3M
__device__ __half g_qkh[(size_t)LL * SP * QKN];      // 25.2M
__device__ __half g_avh[(size_t)SS * LL * DD];       // 39.3M
__device__ __half g_scoresh[(size_t)SS * LL * LL];   // 52.4M
__device__ __half g_wh[119000000];                   // half weights (NN layout)

// =============== helpers =====================
__device__ __forceinline__ uint32_t smem_u32(const void* p) {
    uint32_t a;
    asm("{ .reg .u64 t; cvta.to.shared.u64 t, %1; cvt.u32.u64 %0, t; }" : "=r"(a) : "l"(p));
    return a;
}
__device__ __forceinline__ void mma_f16(float* d, const uint32_t* a, const uint32_t* b) {
    asm volatile(
        "mma.sync.aligned.m16n8k16.row.col.f32.f16.f16.f32 "
        "{%0,%1,%2,%3}, {%4,%5,%6,%7}, {%8,%9}, {%0,%1,%2,%3};\n"
        : "+f"(d[0]), "+f"(d[1]), "+f"(d[2]), "+f"(d[3])
        : "r"(a[0]), "r"(a[1]), "r"(a[2]), "r"(a[3]),
          "r"(b[0]), "r"(b[1]));
}
__device__ __forceinline__ void ldsm_x4(uint32_t& r0, uint32_t& r1, uint32_t& r2, uint32_t& r3,
                                        uint32_t addr) {
    asm volatile("ldmatrix.sync.aligned.m8n8.x4.shared.b16 {%0,%1,%2,%3}, [%4];"
                 : "=r"(r0), "=r"(r1), "=r"(r2), "=r"(r3) : "r"(addr));
}
__device__ __forceinline__ void ldsm_x4_t(uint32_t& r0, uint32_t& r1, uint32_t& r2, uint32_t& r3,
                                          uint32_t addr) {
    asm volatile("ldmatrix.sync.aligned.m8n8.x4.trans.shared.b16 {%0,%1,%2,%3}, [%4];"
                 : "=r"(r0), "=r"(r1), "=r"(r2), "=r"(r3) : "r"(addr));
}
__device__ __forceinline__ void cp_async16(uint32_t smem_addr, const void* gptr, uint32_t src_bytes) {
    asm volatile("cp.async.ca.shared.global [%0], [%1], 16, %2;"
                 :: "r"(smem_addr), "l"(gptr), "r"(src_bytes));
}
#define CP_COMMIT() asm volatile("cp.async.commit_group;" ::: "memory")
#define CP_WAIT2()  asm volatile("cp.async.wait_group 2;" ::: "memory")

// =================================================================
// cp.async-pipelined FP16 GEMM (mma.sync m16n8k16, ldmatrix frags)
// NT: C = A @ B^T, B [N,K] half (ldmatrix plain)
// NN: C = A @ B,   B [K,N] half (ldmatrix.trans)
// A: [M,K] half. K % 32 == 0, N % 8 == 0. All outputs fp16 (fp32 accum).
// CTA 128x256, 8 warps, warp tile 64x64, K-tile 32, 4-stage ring.
// MODE: 0 plain | 1 +bias | 2 +bias+relu
// =================================================================
#define BMt 128
#define BNt 256
#define RS 20                    // NT smem row stride (words; 40 halves)
#define BRS_NN 132               // NN B row stride (words; 264 halves)
#define AWORDS (BMt * RS)        // 2560
#define BWORDS 5120              // max(256*20, 32*132=4224)
#define STGW (AWORDS + BWORDS)   // 7680
#define NSTAGE 4
#define GEMM_SMEM_BYTES (NSTAGE * STGW * 4)   // 122880

template<bool TRANSB, int MODE>
__global__ __launch_bounds__(256, 1)
void mma_gemm_kernel(const __half* __restrict__ Ab, const __half* __restrict__ Bb,
                     const float* __restrict__ biasb, __half* __restrict__ Cb,
                     int M, int N, int K, int lda, int ldb, int ldc,
                     long sA, long sB, long sBias, long sC)
{
    constexpr bool BIAS = (MODE >= 1);
    constexpr bool RELU = (MODE == 2);

    extern __shared__ __align__(16) uint32_t sm[];
    const uint32_t smb = smem_u32(sm);

    const int b = blockIdx.z;
    const __half* A = Ab + (long)b * sA;
    const __half* B = Bb + (long)b * sB;
    __half* C = Cb + (long)b * sC;

    const int brow = blockIdx.y * BMt;
    const int bcol = blockIdx.x * BNt;
    const int tid = threadIdx.x;
    const int wid = tid >> 5;
    const int lane = tid & 31;
    const int g = lane >> 2;
    const int c = lane & 3;
    const int warp_m = (wid & 1) * 64;
    const int warp_n = (wid >> 1) * 64;

    // ldmatrix lane-address components
    const int a_row  = (lane & 7) + ((lane >> 3) & 1) * 8;
    const int a_koff = ((lane >> 4) & 1) * 8;
    const int bt_row  = (lane & 7) + ((lane >> 4) & 1) * 8;  // NT
    const int bt_koff = ((lane >> 3) & 1) * 8;
    const int bn_k = (lane & 7) + ((lane >> 3) & 1) * 8;     // NN (.trans)
    const int bn_n = ((lane >> 4) & 1) * 8;

    const int nkt = K >> 5;

    float acc[4][8][4];
    #pragma unroll
    for (int i = 0; i < 4; i++)
        #pragma unroll
        for (int j = 0; j < 8; j++)
            #pragma unroll
            for (int r = 0; r < 4; r++)
                acc[i][j][r] = 0.0f;

    auto issue_stage = [&](int kt) {
        if (kt < nkt) {
            int k0 = kt << 5;
            uint32_t sbase = smb + ((kt & (NSTAGE - 1)) * STGW) * 4;
            // A: 128 rows x 4 chunks -> 2/thread
            #pragma unroll
            for (int i = 0; i < 2; i++) {
                int idx = i * 256 + tid;
                int row = idx >> 2, q = idx & 3;
                int gr = brow + row;
                const __half* gp = A + (long)gr * lda + k0 + q * 8;
                uint32_t dst = sbase + (row * RS + q * 4) * 4;
                cp_async16(dst, gp, (gr < M) ? 16u : 0u);
            }
            if (TRANSB) {
                // B [N,K]: 256 rows x 4 chunks -> 4/thread
                #pragma unroll
                for (int i = 0; i < 4; i++) {
                    int idx = i * 256 + tid;
                    int row = idx >> 2, q = idx & 3;
                    int gn = bcol + row;
                    const __half* gp = B + (long)gn * ldb + k0 + q * 8;
                    uint32_t dst = sbase + (AWORDS + row * RS + q * 4) * 4;
                    cp_async16(dst, gp, (gn < N) ? 16u : 0u);
                }
            } else {
                // B [K,N]: 32 k-rows x 32 n-chunks -> 4/thread
                #pragma unroll
                for (int i = 0; i < 4; i++) {
                    int idx = i * 256 + tid;
                    int kk = idx >> 5, ch = idx & 31;
                    int gn = bcol + ch * 8;
                    const __half* gp = B + (long)(k0 + kk) * ldb + gn;
                    uint32_t dst = sbase + (AWORDS + kk * BRS_NN + ch * 4) * 4;
                    cp_async16(dst, gp, (gn < N) ? 16u : 0u);
                }
            }
        }
        CP_COMMIT();
    };

    issue_stage(0);
    issue_stage(1);
    issue_stage(2);

    for (int kt = 0; kt < nkt; kt++) {
        CP_WAIT2();
        __syncthreads();
        issue_stage(kt + 3);

        uint32_t As = smb + ((kt & (NSTAGE - 1)) * STGW) * 4;
        uint32_t Bs = As + AWORDS * 4;

        #pragma unroll
        for (int ks = 0; ks < 2; ks++) {
            int kh = ks * 16;
            uint32_t af[4][4], bf[8][2];
            #pragma unroll
            for (int am = 0; am < 4; am++) {
                uint32_t addr = As + ((warp_m + am * 16 + a_row) * RS) * 4
                                   + (kh + a_koff) * 2;
                ldsm_x4(af[am][0], af[am][1], af[am][2], af[am][3], addr);
            }
            #pragma unroll
            for (int p = 0; p < 4; p++) {
                if (TRANSB) {
                    uint32_t addr = Bs + ((warp_n + p * 16 + bt_row) * RS) * 4
                                       + (kh + bt_koff) * 2;
                    ldsm_x4(bf[2 * p][0], bf[2 * p][1], bf[2 * p + 1][0], bf[2 * p + 1][1], addr);
                } else {
                    uint32_t addr = Bs + ((kh + bn_k) * BRS_NN) * 4
                                       + (warp_n + p * 16 + bn_n) * 2;
                    ldsm_x4_t(bf[2 * p][0], bf[2 * p][1], bf[2 * p + 1][0], bf[2 * p + 1][1], addr);
                }
            }
            #pragma unroll
            for (int am = 0; am < 4; am++)
                #pragma unroll
                for (int bn = 0; bn < 8; bn++)
                    mma_f16(acc[am][bn], af[am], bf[bn]);
        }
    }

    // ---- epilogue (fp16 out) ----
    #pragma unroll
    for (int am = 0; am < 4; am++) {
        int row0 = brow + warp_m + am * 16 + g;
        #pragma unroll
        for (int bn = 0; bn < 8; bn++) {
            int col = bcol + warp_n + bn * 8 + c * 2;
            if (col >= N) continue;
            float v0 = acc[am][bn][0], v1 = acc[am][bn][1];
            float v2 = acc[am][bn][2], v3 = acc[am][bn][3];
            if (BIAS) {
                float b0 = biasb[(long)b * sBias + col];
                float b1 = biasb[(long)b * sBias + col + 1];
                v0 += b0; v1 += b1; v2 += b0; v3 += b1;
            }
            if (RELU) {
                v0 = fmaxf(v0, 0.f); v1 = fmaxf(v1, 0.f);
                v2 = fmaxf(v2, 0.f); v3 = fmaxf(v3, 0.f);
            }
            __half2 h01 = __floats2half2_rn(v0, v1);
            __half2 h23 = __floats2half2_rn(v2, v3);
            if (row0 < M)     *(__half2*)&C[(long)row0 * ldc + col]       = h01;
            if (row0 + 8 < M) *(__half2*)&C[(long)(row0 + 8) * ldc + col] = h23;
        }
    }
}

// ---------------- float -> half elementwise ----------------
__global__ __launch_bounds__(256)
void f2h_kernel(const float* __restrict__ in, __half* __restrict__ out, long n4)
{
    long i = (long)blockIdx.x * 256 + threadIdx.x;
    if (i >= n4) return;
    float4 v = ((const float4*)in)[i];
    ((__half2*)out)[i * 2]     = __floats2half2_rn(v.x, v.y);
    ((__half2*)out)[i * 2 + 1] = __floats2half2_rn(v.z, v.w);
}

// ------- concat Wq||Wk -> half [batch, D, QKN] (NN layout) --------
__global__ __launch_bounds__(256)
void concat_qk_kernel(const float* __restrict__ Wq, const float* __restrict__ Wk,
                      __half* __restrict__ out, long total)
{
    long i = (long)blockIdx.x * 256 + threadIdx.x;
    if (i >= total) return;
    long j = i % QKN;
    long bd = i / QKN;
    float v = (j < DD4) ? Wq[bd * DD4 + j] : Wk[bd * DD4 + (j - DD4)];
    out[i] = __float2half_rn(v);
}

// ---------------- row softmax on half (pre-scale, padded stride) ----------
__global__ __launch_bounds__(256)
void softmax_kernel(__half* __restrict__ data, int n, int stride, float scale)
{
    long row = blockIdx.x;
    __half* p = data + row * (long)stride;
    int t = threadIdx.x;
    int w = t >> 5, lane = t & 31;

    float loc[4];
    int cnt = 0;
    float mx = -3.0e38f;
    for (int i = t; i < n; i += 256) {
        float v = __half2float(p[i]) * scale;
        loc[cnt++] = v;
        mx = fmaxf(mx, v);
    }
    #pragma unroll
    for (int o = 16; o > 0; o >>= 1) mx = fmaxf(mx, __shfl_xor_sync(0xffffffffu, mx, o));
    __shared__ float red[8];
    if (lane == 0) red[w] = mx;
    __syncthreads();
    if (t < 8) {
        float v = red[t];
        #pragma unroll
        for (int o = 4; o > 0; o >>= 1) v = fmaxf(v, __shfl_xor_sync(0xffu, v, o));
        if (t == 0) red[0] = v;
    }
    __syncthreads();
    mx = red[0];
    __syncthreads();

    float sum = 0.0f;
    for (int cc = 0; cc < cnt; cc++) {
        float e = __expf(loc[cc] - mx);
        loc[cc] = e;
        sum += e;
    }
    #pragma unroll
    for (int o = 16; o > 0; o >>= 1) sum += __shfl_xor_sync(0xffffffffu, sum, o);
    if (lane == 0) red[w] = sum;
    __syncthreads();
    if (t < 8) {
        float v = red[t];
        #pragma unroll
        for (int o = 4; o > 0; o >>= 1) v += __shfl_xor_sync(0xffu, v, o);
        if (t == 0) red[0] = v;
    }
    __syncthreads();
    float inv = 1.0f / red[0];

    cnt = 0;
    for (int i = t; i < n; i += 256) p[i] = __float2half_rn(loc[cnt++] * inv);
    for (int i = t; i < stride; i += 256) if (i >= n) p[i] = __float2half_rn(0.0f);
}

// -------- fused residual + LayerNorm (fp16 stream, fp32 math) ------
__global__ __launch_bounds__(256)
void ln_kernel(const __half* __restrict__ resid, const __half* __restrict__ h,
               const float* __restrict__ gam, const float* __restrict__ bet,
               __half* __restrict__ outh, float* __restrict__ outf, int J,
               long ri, long rj, long hi, long hj, long oi, long oj, long gstride)
{
    long b = blockIdx.x;
    long i = b / J, j = b % J;
    const __half* r  = resid + (i * ri + j * rj) * DD;
    const __half* hh = h     + (i * hi + j * hj) * DD;
    long orow = i * oi + j * oj;
    const float* gp = gam + i * gstride;
    const float* bp = bet + i * gstride;
    int t = threadIdx.x;
    int w = t >> 5, lane = t & 31;

    float v[3];
    float s = 0.0f, s2 = 0.0f;
    #pragma unroll
    for (int k = 0; k < 3; k++) {
        int d = t + k * 256;
        float val = __half2float(r[d]) + __half2float(hh[d]);
        v[k] = val;
        s += val;
        s2 += val * val;
    }
    #pragma unroll
    for (int o = 16; o > 0; o >>= 1) {
        s  += __shfl_xor_sync(0xffffffffu, s, o);
        s2 += __shfl_xor_sync(0xffffffffu, s2, o);
    }
    __shared__ float rs[8], rs2[8];
    if (lane == 0) { rs[w] = s; rs2[w] = s2; }
    __syncthreads();
    if (t < 8) {
        s = rs[t]; s2 = rs2[t];
        #pragma unroll
        for (int o = 4; o > 0; o >>= 1) {
            s  += __shfl_xor_sync(0xffu, s, o);
            s2 += __shfl_xor_sync(0xffu, s2, o);
        }
        if (t == 0) { rs[0] = s; rs2[0] = s2; }
    }
    __syncthreads();
    float mean = rs[0] * (1.0f / DD);
    float var  = rs2[0] * (1.0f / DD) - mean * mean;
    float inv  = rsqrtf(var + 1e-5f);

    #pragma unroll
    for (int k = 0; k < 3; k++) {
        int d = t + k * 256;
        float o = (v[k] - mean) * inv * gp[d] + bp[d];
        if (outh) outh[orow * DD + d] = __float2half_rn(o);
        if (outf) outf[orow * DD + d] = o;
    }
}

// ---------------- zero pad rows of xtph [LL, SP, DD] ----------------
__global__ __launch_bounds__(256)
void zero_pad_kernel(__half* __restrict__ xth)
{
    long idx = (long)blockIdx.x * 256 + threadIdx.x;
    const long per_l = (long)(SP - SS) * DD;
    const long total = (long)LL * per_l;
    if (idx >= total) return;
    long l = idx / per_l;
    long off = idx % per_l;
    xth[((long)l * SP + SS) * DD + off] = __float2half_rn(0.0f);
}

// ---------------- launch plumbing ----------------
static inline int cdiv(int a, int b) { return (a + b - 1) / b; }

template<bool TRANSB, int MODE>
static void launch_gemm(const __half* A, const __half* B, const float* bias, __half* C,
                        int M, int N, int K, int lda, int ldb, int ldc, int batch,
                        long sA, long sB, long sBias, long sC)
{
    dim3 grid(cdiv(N, BNt), cdiv(M, BMt), batch);
    cudaFuncSetAttribute(mma_gemm_kernel<TRANSB, MODE>,
                         cudaFuncAttributeMaxDynamicSharedMemorySize, GEMM_SMEM_BYTES);
    mma_gemm_kernel<TRANSB, MODE><<<grid, 256, GEMM_SMEM_BYTES>>>(
        A, B, bias, C, M, N, K, lda, ldb, ldc, sA, sB, sBias, sC);
}

extern "C" void kernel_launch(void* const* d_in, const int* in_sizes, int n_in,
                              void* d_out, int out_size)
{
    (void)in_sizes; (void)n_in; (void)out_size;

    const float* x        = (const float*)d_in[0];
    const float* pre_Wq   = (const float*)d_in[1];
    const float* pre_Wk   = (const float*)d_in[2];
    const float* pre_Wv   = (const float*)d_in[3];
    const float* ln1_g    = (const float*)d_in[4];
    const float* ln1_b    = (const float*)d_in[5];
    const float* pre_W1   = (const float*)d_in[6];
    const float* pre_b1   = (const float*)d_in[7];
    const float* pre_W2   = (const float*)d_in[8];
    const float* pre_b2   = (const float*)d_in[9];
    const float* ln4p_g   = (const float*)d_in[10];
    const float* ln4p_b   = (const float*)d_in[11];
    const float* cross_Wq = (const float*)d_in[12];
    const float* cross_Wk = (const float*)d_in[13];
    const float* cross_Wv = (const float*)d_in[14];
    const float* ln2_g    = (const float*)d_in[15];
    const float* ln2_b    = (const float*)d_in[16];
    const float* post_Wq  = (const float*)d_in[17];
    const float* post_Wk  = (const float*)d_in[18];
    const float* post_Wv  = (const float*)d_in[19];
    const float* ln3_g    = (const float*)d_in[20];
    const float* ln3_b    = (const float*)d_in[21];
    const float* post_W1  = (const float*)d_in[22];
    const float* post_b1  = (const float*)d_in[23];
    const float* post_W2  = (const float*)d_in[24];
    const float* post_b2  = (const float*)d_in[25];
    const float* ln4_g    = (const float*)d_in[26];
    const float* ln4_b    = (const float*)d_in[27];
    float* out = (float*)d_out;

    __half *xh, *lnh, *xtph, *qkh, *avh, *scoresh, *wh;
    cudaGetSymbolAddress((void**)&xh, g_xh);
    cudaGetSymbolAddress((void**)&lnh, g_lnh);
    cudaGetSymbolAddress((void**)&xtph, g_xtph);
    cudaGetSymbolAddress((void**)&qkh, g_qkh);
    cudaGetSymbolAddress((void**)&avh, g_avh);
    cudaGetSymbolAddress((void**)&scoresh, g_scoresh);
    cudaGetSymbolAddress((void**)&wh, g_wh);

    // half weight layout (NN: [K][N] natural layout)
    const long SZ_QKW = (long)SS * DD * QKN;     // 14.75M
    const long SZ_VW  = (long)SS * DD * DD;      // 29.49M
    const long SZ_W1  = (long)SS * DD * DD4;     // 7.37M
    __half* qkPreH   = wh;
    __half* qkPostH  = qkPreH  + SZ_QKW;
    __half* qkCrossH = qkPostH + SZ_QKW;
    __half* WvPreH   = qkCrossH + (long)DD * QKN;
    __half* WvPostH  = WvPreH  + SZ_VW;
    __half* WvCrossH = WvPostH + SZ_VW;
    __half* W1PreH   = WvCrossH + (long)DD * DD;
    __half* W1PostH  = W1PreH  + SZ_W1;
    __half* W2PreH   = W1PostH + SZ_W1;
    __half* W2PostH  = W2PreH  + SZ_W1;

    const float scale = 1.0f / sqrtf((float)DD4);
    const long LD = (long)LL * DD;

    // ---------------- weight prep: pure streaming f2h / concat ----------
    concat_qk_kernel<<<cdiv((int)SZ_QKW, 256), 256>>>(pre_Wq, pre_Wk, qkPreH, SZ_QKW);
    concat_qk_kernel<<<cdiv((int)SZ_QKW, 256), 256>>>(post_Wq, post_Wk, qkPostH, SZ_QKW);
    concat_qk_kernel<<<cdiv((int)(DD * QKN), 256), 256>>>(cross_Wq, cross_Wk, qkCrossH, (long)DD * QKN);
    f2h_kernel<<<cdiv((int)(SZ_VW / 4), 256), 256>>>(pre_Wv,  WvPreH,  SZ_VW / 4);
    f2h_kernel<<<cdiv((int)(SZ_VW / 4), 256), 256>>>(post_Wv, WvPostH, SZ_VW / 4);
    f2h_kernel<<<cdiv((int)((long)DD * DD / 4), 256), 256>>>(cross_Wv, WvCrossH, (long)DD * DD / 4);
    f2h_kernel<<<cdiv((int)(SZ_W1 / 4), 256), 256>>>(pre_W1,  W1PreH,  SZ_W1 / 4);
    f2h_kernel<<<cdiv((int)(SZ_W1 / 4), 256), 256>>>(post_W1, W1PostH, SZ_W1 / 4);
    f2h_kernel<<<cdiv((int)(SZ_W1 / 4), 256), 256>>>(pre_W2,  W2PreH,  SZ_W1 / 4);
    f2h_kernel<<<cdiv((int)(SZ_W1 / 4), 256), 256>>>(post_W2, W2PostH, SZ_W1 / 4);
    f2h_kernel<<<cdiv((int)(SS * LD / 4), 256), 256>>>(x, xh, SS * LD / 4);

    // ================= pre_self_step attention =================
    launch_gemm<false, 0>(xh, qkPreH, nullptr, qkh, LL, QKN, DD, DD, QKN, QKN, SS,
                          LD, (long)DD * QKN, 0, (long)LL * QKN);
    launch_gemm<true, 0>(qkh, qkh + DD4, nullptr, scoresh, LL, LL, DD4, QKN, QKN, LL, SS,
                         (long)LL * QKN, (long)LL * QKN, 0, (long)LL * LL);
    softmax_kernel<<<SS * LL, 256>>>(scoresh, LL, LL, scale);
    launch_gemm<false, 0>(scoresh, xh, nullptr, avh, LL, DD, LL, LL, DD, DD, SS,
                          (long)LL * LL, LD, 0, LD);
    launch_gemm<false, 0>(avh, WvPreH, nullptr, scoresh, LL, DD, DD, DD, DD, DD, SS,
                          LD, (long)DD * DD, 0, LD);
    ln_kernel<<<SS * LL, 256>>>(xh, scoresh, ln1_g, ln1_b, lnh, nullptr, LL,
                                LL, 1, LL, 1, LL, 1, DD);

    // ================= pre_mlp =================
    launch_gemm<false, 2>(lnh, W1PreH, pre_b1, qkh, LL, DD4, DD, DD, DD4, DD4, SS,
                          LD, (long)DD * DD4, DD4, (long)LL * DD4);
    launch_gemm<false, 1>(qkh, W2PreH, pre_b2, scoresh, LL, DD, DD4, DD4, DD, DD, SS,
                          (long)LL * DD4, (long)DD4 * DD, DD, LD);
    ln_kernel<<<SS * LL, 256>>>(lnh, scoresh, ln4p_g, ln4p_b, xtph, nullptr, LL,
                                LL, 1, LL, 1, 1, SP, DD);
    zero_pad_kernel<<<cdiv(LL * (SP - SS) * DD, 256), 256>>>(xtph);

    // ================= cross_step attention (padded S -> SP) =================
    launch_gemm<false, 0>(xtph, qkCrossH, nullptr, qkh, LL * SP, QKN, DD, DD, QKN, QKN, 1,
                          0, 0, 0, 0);
    launch_gemm<true, 0>(qkh, qkh + DD4, nullptr, avh, SP, SP, DD4, QKN, QKN, SP, LL,
                         (long)SP * QKN, (long)SP * QKN, 0, (long)SP * SP);
    softmax_kernel<<<LL * SP, 256>>>(avh, SS, SP, scale);
    launch_gemm<false, 0>(avh, xtph, nullptr, scoresh, SS, DD, SP, SP, DD, DD, LL,
                          (long)SP * SP, (long)SP * DD, 0, (long)SS * DD);
    launch_gemm<false, 0>(scoresh, WvCrossH, nullptr, avh, LL * SS, DD, DD, DD, DD, DD, 1,
                          0, 0, 0, 0);
    ln_kernel<<<LL * SS, 256>>>(xtph, avh, ln2_g, ln2_b, lnh, nullptr, SS,
                                SP, 1, SS, 1, 1, LL, 0);

    // ================= post_self_step attention =================
    launch_gemm<false, 0>(lnh, qkPostH, nullptr, qkh, LL, QKN, DD, DD, QKN, QKN, SS,
                          LD, (long)DD * QKN, 0, (long)LL * QKN);
    launch_gemm<true, 0>(qkh, qkh + DD4, nullptr, scoresh, LL, LL, DD4, QKN, QKN, LL, SS,
                         (long)LL * QKN, (long)LL * QKN, 0, (long)LL * LL);
    softmax_kernel<<<SS * LL, 256>>>(scoresh, LL, LL, scale);
    launch_gemm<false, 0>(scoresh, lnh, nullptr, avh, LL, DD, LL, LL, DD, DD, SS,
                          (long)LL * LL, LD, 0, LD);
    launch_gemm<false, 0>(avh, WvPostH, nullptr, scoresh, LL, DD, DD, DD, DD, DD, SS,
                          LD, (long)DD * DD, 0, LD);
    ln_kernel<<<SS * LL, 256>>>(lnh, scoresh, ln3_g, ln3_b, xh, nullptr, LL,
                                LL, 1, LL, 1, LL, 1, DD);

    // ================= post_mlp =================
    launch_gemm<false, 2>(xh, W1PostH, post_b1, qkh, LL, DD4, DD, DD, DD4, DD4, SS,
                          LD, (long)DD * DD4, DD4, (long)LL * DD4);
    launch_gemm<false, 1>(qkh, W2PostH, post_b2, scoresh, LL, DD, DD4, DD4, DD, DD, SS,
                          (long)LL * DD4, (long)DD4 * DD, DD, LD);
    ln_kernel<<<SS * LL, 256>>>(xh, scoresh, ln4_g, ln4_b, nullptr, out, LL,
                                LL, 1, LL, 1, LL, 1, DD);
}

// round 13
// speedup vs baseline: 2.3200x; 1.1428x over previous
#include <cuda_runtime.h>
#include <cuda_fp16.h>
#include <math.h>
#include <stdint.h>

// Problem dims
#define SS 50
#define LL 1024
#define DD 768
#define DD4 192
#define SP 64
#define QKN 384

// ---------------- static scratch (alloc-free rule) ----------------
__device__ __half g_xh[(size_t)SS * LL * DD];
__device__ __half g_lnh[(size_t)SS * LL * DD];
__device__ __half g_xtph[(size_t)LL * SP * DD];
__device__ __half g_qkh[(size_t)LL * SP * QKN];
__device__ __half g_avh[(size_t)SS * LL * DD];
__device__ __half g_scoresh[(size_t)SS * LL * LL];
__device__ __half g_wh[119000000];

// =============== helpers =====================
__device__ __forceinline__ uint32_t smem_u32(const void* p) {
    uint32_t a;
    asm("{ .reg .u64 t; cvta.to.shared.u64 t, %1; cvt.u32.u64 %0, t; }" : "=r"(a) : "l"(p));
    return a;
}
__device__ __forceinline__ void mma_f16(float* d, const uint32_t* a, const uint32_t* b) {
    asm volatile(
        "mma.sync.aligned.m16n8k16.row.col.f32.f16.f16.f32 "
        "{%0,%1,%2,%3}, {%4,%5,%6,%7}, {%8,%9}, {%0,%1,%2,%3};\n"
        : "+f"(d[0]), "+f"(d[1]), "+f"(d[2]), "+f"(d[3])
        : "r"(a[0]), "r"(a[1]), "r"(a[2]), "r"(a[3]),
          "r"(b[0]), "r"(b[1]));
}
__device__ __forceinline__ void ldsm_x4(uint32_t& r0, uint32_t& r1, uint32_t& r2, uint32_t& r3,
                                        uint32_t addr) {
    asm volatile("ldmatrix.sync.aligned.m8n8.x4.shared.b16 {%0,%1,%2,%3}, [%4];"
                 : "=r"(r0), "=r"(r1), "=r"(r2), "=r"(r3) : "r"(addr));
}
__device__ __forceinline__ void ldsm_x4_t(uint32_t& r0, uint32_t& r1, uint32_t& r2, uint32_t& r3,
                                          uint32_t addr) {
    asm volatile("ldmatrix.sync.aligned.m8n8.x4.trans.shared.b16 {%0,%1,%2,%3}, [%4];"
                 : "=r"(r0), "=r"(r1), "=r"(r2), "=r"(r3) : "r"(addr));
}
__device__ __forceinline__ void cp_async16(uint32_t smem_addr, const void* gptr, uint32_t src_bytes) {
    asm volatile("cp.async.ca.shared.global [%0], [%1], 16, %2;"
                 :: "r"(smem_addr), "l"(gptr), "r"(src_bytes));
}
#define CP_COMMIT() asm volatile("cp.async.commit_group;" ::: "memory")
#define CP_WAIT2()  asm volatile("cp.async.wait_group 2;" ::: "memory")

// =================================================================
// cp.async-pipelined FP16 GEMM (mma.sync m16n8k16, ldmatrix frags)
// NT: C = A @ B^T (B [N,K]); NN: C = A @ B (B [K,N], ldmatrix.trans)
// SMALL=false: CTA 128x256, warp tile 64x64.
// SMALL=true:  CTA 128x128, warp tile 32x64 (for N in {384, 64,...}).
// MODE: 0 plain | 1 +bias | 2 +bias+relu. fp16 out, fp32 accum.
// =================================================================
#define BMt 128
#define RS 20
#define BRS_NN 132      // BN=256 NN row stride (words)
#define BRS_NN_S 68     // BN=128 NN row stride (words)
#define AWORDS (BMt * RS)   // 2560
#define NSTAGE 4

template<bool TRANSB, int MODE, bool SMALL>
__global__ __launch_bounds__(256, 1)
void mma_gemm_kernel(const __half* __restrict__ Ab, const __half* __restrict__ Bb,
                     const float* __restrict__ biasb, __half* __restrict__ Cb,
                     int M, int N, int K, int lda, int ldb, int ldc,
                     long sA, long sB, long sBias, long sC)
{
    constexpr bool BIAS = (MODE >= 1);
    constexpr bool RELU = (MODE == 2);
    constexpr int BN = SMALL ? 128 : 256;
    constexpr int BWRD = SMALL ? 2560 : 5120;
    constexpr int STGW_L = AWORDS + BWRD;
    constexpr int NAM = SMALL ? 2 : 4;

    extern __shared__ __align__(16) uint32_t sm[];
    const uint32_t smb = smem_u32(sm);

    const int b = blockIdx.z;
    const __half* A = Ab + (long)b * sA;
    const __half* B = Bb + (long)b * sB;
    __half* C = Cb + (long)b * sC;

    const int brow = blockIdx.y * BMt;
    const int bcol = blockIdx.x * BN;
    const int tid = threadIdx.x;
    const int wid = tid >> 5;
    const int lane = tid & 31;
    const int g = lane >> 2;
    const int c = lane & 3;
    const int warp_m = SMALL ? (wid & 3) * 32 : (wid & 1) * 64;
    const int warp_n = SMALL ? (wid >> 2) * 64 : (wid >> 1) * 64;

    const int a_row  = (lane & 7) + ((lane >> 3) & 1) * 8;
    const int a_koff = ((lane >> 4) & 1) * 8;
    const int bt_row  = (lane & 7) + ((lane >> 4) & 1) * 8;
    const int bt_koff = ((lane >> 3) & 1) * 8;
    const int bn_k = (lane & 7) + ((lane >> 3) & 1) * 8;
    const int bn_n = ((lane >> 4) & 1) * 8;

    const int nkt = K >> 5;

    float acc[NAM][8][4];
    #pragma unroll
    for (int i = 0; i < NAM; i++)
        #pragma unroll
        for (int j = 0; j < 8; j++)
            #pragma unroll
            for (int r = 0; r < 4; r++)
                acc[i][j][r] = 0.0f;

    auto issue_stage = [&](int kt) {
        if (kt < nkt) {
            int k0 = kt << 5;
            uint32_t sbase = smb + ((kt & (NSTAGE - 1)) * STGW_L) * 4;
            #pragma unroll
            for (int i = 0; i < 2; i++) {
                int idx = i * 256 + tid;
                int row = idx >> 2, q = idx & 3;
                int gr = brow + row;
                const __half* gp = A + (long)gr * lda + k0 + q * 8;
                uint32_t dst = sbase + (row * RS + q * 4) * 4;
                cp_async16(dst, gp, (gr < M) ? 16u : 0u);
            }
            if (TRANSB) {
                constexpr int NIT = SMALL ? 2 : 4;
                #pragma unroll
                for (int i = 0; i < NIT; i++) {
                    int idx = i * 256 + tid;
                    int row = idx >> 2, q = idx & 3;
                    int gn = bcol + row;
                    const __half* gp = B + (long)gn * ldb + k0 + q * 8;
                    uint32_t dst = sbase + (AWORDS + row * RS + q * 4) * 4;
                    cp_async16(dst, gp, (gn < N) ? 16u : 0u);
                }
            } else {
                if (SMALL) {
                    #pragma unroll
                    for (int i = 0; i < 2; i++) {
                        int idx = i * 256 + tid;
                        int kk = idx >> 4, ch = idx & 15;
                        int gn = bcol + ch * 8;
                        const __half* gp = B + (long)(k0 + kk) * ldb + gn;
                        uint32_t dst = sbase + (AWORDS + kk * BRS_NN_S + ch * 4) * 4;
                        cp_async16(dst, gp, (gn < N) ? 16u : 0u);
                    }
                } else {
                    #pragma unroll
                    for (int i = 0; i < 4; i++) {
                        int idx = i * 256 + tid;
                        int kk = idx >> 5, ch = idx & 31;
                        int gn = bcol + ch * 8;
                        const __half* gp = B + (long)(k0 + kk) * ldb + gn;
                        uint32_t dst = sbase + (AWORDS + kk * BRS_NN + ch * 4) * 4;
                        cp_async16(dst, gp, (gn < N) ? 16u : 0u);
                    }
                }
            }
        }
        CP_COMMIT();
    };

    issue_stage(0);
    issue_stage(1);
    issue_stage(2);

    for (int kt = 0; kt < nkt; kt++) {
        CP_WAIT2();
        __syncthreads();
        issue_stage(kt + 3);

        uint32_t As = smb + ((kt & (NSTAGE - 1)) * STGW_L) * 4;
        uint32_t Bs = As + AWORDS * 4;

        #pragma unroll
        for (int ks = 0; ks < 2; ks++) {
            int kh = ks * 16;
            uint32_t af[NAM][4], bf[8][2];
            #pragma unroll
            for (int am = 0; am < NAM; am++) {
                uint32_t addr = As + ((warp_m + am * 16 + a_row) * RS) * 4
                                   + (kh + a_koff) * 2;
                ldsm_x4(af[am][0], af[am][1], af[am][2], af[am][3], addr);
            }
            #pragma unroll
            for (int p = 0; p < 4; p++) {
                if (TRANSB) {
                    uint32_t addr = Bs + ((warp_n + p * 16 + bt_row) * RS) * 4
                                       + (kh + bt_koff) * 2;
                    ldsm_x4(bf[2 * p][0], bf[2 * p][1], bf[2 * p + 1][0], bf[2 * p + 1][1], addr);
                } else {
                    uint32_t brs = SMALL ? BRS_NN_S : BRS_NN;
                    uint32_t addr = Bs + ((kh + bn_k) * brs) * 4
                                       + (warp_n + p * 16 + bn_n) * 2;
                    ldsm_x4_t(bf[2 * p][0], bf[2 * p][1], bf[2 * p + 1][0], bf[2 * p + 1][1], addr);
                }
            }
            #pragma unroll
            for (int am = 0; am < NAM; am++)
                #pragma unroll
                for (int bn = 0; bn < 8; bn++)
                    mma_f16(acc[am][bn], af[am], bf[bn]);
        }
    }

    // ---- epilogue (fp16 out) ----
    #pragma unroll
    for (int am = 0; am < NAM; am++) {
        int row0 = brow + warp_m + am * 16 + g;
        #pragma unroll
        for (int bn = 0; bn < 8; bn++) {
            int col = bcol + warp_n + bn * 8 + c * 2;
            if (col >= N) continue;
            float v0 = acc[am][bn][0], v1 = acc[am][bn][1];
            float v2 = acc[am][bn][2], v3 = acc[am][bn][3];
            if (BIAS) {
                float b0 = biasb[(long)b * sBias + col];
                float b1 = biasb[(long)b * sBias + col + 1];
                v0 += b0; v1 += b1; v2 += b0; v3 += b1;
            }
            if (RELU) {
                v0 = fmaxf(v0, 0.f); v1 = fmaxf(v1, 0.f);
                v2 = fmaxf(v2, 0.f); v3 = fmaxf(v3, 0.f);
            }
            __half2 h01 = __floats2half2_rn(v0, v1);
            __half2 h23 = __floats2half2_rn(v2, v3);
            if (row0 < M)     *(__half2*)&C[(long)row0 * ldc + col]       = h01;
            if (row0 + 8 < M) *(__half2*)&C[(long)(row0 + 8) * ldc + col] = h23;
        }
    }
}

// ---------------- float -> half elementwise ----------------
__global__ __launch_bounds__(256)
void f2h_kernel(const float* __restrict__ in, __half* __restrict__ out, long n4)
{
    long i = (long)blockIdx.x * 256 + threadIdx.x;
    if (i >= n4) return;
    float4 v = ((const float4*)in)[i];
    ((__half2*)out)[i * 2]     = __floats2half2_rn(v.x, v.y);
    ((__half2*)out)[i * 2 + 1] = __floats2half2_rn(v.z, v.w);
}

// ------- concat Wq||Wk -> half [batch, D, QKN] --------
__global__ __launch_bounds__(256)
void concat_qk_kernel(const float* __restrict__ Wq, const float* __restrict__ Wk,
                      __half* __restrict__ out, long total)
{
    long i = (long)blockIdx.x * 256 + threadIdx.x;
    if (i >= total) return;
    long j = i % QKN;
    long bd = i / QKN;
    float v = (j < DD4) ? Wq[bd * DD4 + j] : Wk[bd * DD4 + (j - DD4)];
    out[i] = __float2half_rn(v);
}

// ---------- warp-per-row softmax on half (pre-scale, padded stride) ---------
// 8 rows per 256-thread block. n, stride even. Zeros pad cols [n, stride).
__global__ __launch_bounds__(256)
void softmax_kernel(__half* __restrict__ data, int n, int stride, float scale, long nrows)
{
    int wid = threadIdx.x >> 5, lane = threadIdx.x & 31;
    long row = (long)blockIdx.x * 8 + wid;
    if (row >= nrows) return;
    __half2* p2 = (__half2*)(data + row * (long)stride);
    int n2 = n >> 1;

    float2 loc[16];
    int cnt = 0;
    float mx = -3.0e38f;
    for (int i = lane; i < n2; i += 32) {
        float2 v = __half22float2(p2[i]);
        v.x *= scale; v.y *= scale;
        loc[cnt++] = v;
        mx = fmaxf(mx, fmaxf(v.x, v.y));
    }
    #pragma unroll
    for (int o = 16; o > 0; o >>= 1) mx = fmaxf(mx, __shfl_xor_sync(0xffffffffu, mx, o));

    float sum = 0.0f;
    for (int k = 0; k < cnt; k++) {
        loc[k].x = __expf(loc[k].x - mx);
        loc[k].y = __expf(loc[k].y - mx);
        sum += loc[k].x + loc[k].y;
    }
    #pragma unroll
    for (int o = 16; o > 0; o >>= 1) sum += __shfl_xor_sync(0xffffffffu, sum, o);
    float inv = 1.0f / sum;

    cnt = 0;
    for (int i = lane; i < n2; i += 32) {
        float2 v = loc[cnt++];
        p2[i] = __floats2half2_rn(v.x * inv, v.y * inv);
    }
    int s2 = stride >> 1;
    for (int i = n2 + lane; i < s2; i += 32) p2[i] = __floats2half2_rn(0.f, 0.f);
}

// ------ warp-per-row fused residual + LayerNorm (fp16 stream, fp32 math) ------
__global__ __launch_bounds__(256)
void ln_kernel(const __half* __restrict__ resid, const __half* __restrict__ h,
               const float* __restrict__ gam, const float* __restrict__ bet,
               __half* __restrict__ outh, float* __restrict__ outf, int J,
               long ri, long rj, long hi, long hj, long oi, long oj, long gstride,
               long nrows)
{
    int wid = threadIdx.x >> 5, lane = threadIdx.x & 31;
    long row = (long)blockIdx.x * 8 + wid;
    if (row >= nrows) return;
    long i = row / J, j = row % J;
    const __half2* r2 = (const __half2*)(resid + (i * ri + j * rj) * DD);
    const __half2* h2 = (const __half2*)(h     + (i * hi + j * hj) * DD);
    long orow = i * oi + j * oj;
    const float2* gp = (const float2*)(gam + i * gstride);
    const float2* bp = (const float2*)(bet + i * gstride);

    float2 v[12];
    float s = 0.0f, s2 = 0.0f;
    #pragma unroll
    for (int k = 0; k < 12; k++) {
        int d = lane + k * 32;
        float2 a = __half22float2(r2[d]);
        float2 b = __half22float2(h2[d]);
        float2 val = make_float2(a.x + b.x, a.y + b.y);
        v[k] = val;
        s += val.x + val.y;
        s2 += val.x * val.x + val.y * val.y;
    }
    #pragma unroll
    for (int o = 16; o > 0; o >>= 1) {
        s  += __shfl_xor_sync(0xffffffffu, s, o);
        s2 += __shfl_xor_sync(0xffffffffu, s2, o);
    }
    float mean = s * (1.0f / DD);
    float var  = s2 * (1.0f / DD) - mean * mean;
    float inv  = rsqrtf(var + 1e-5f);

    #pragma unroll
    for (int k = 0; k < 12; k++) {
        int d = lane + k * 32;
        float2 gg = gp[d], bb = bp[d];
        float o0 = (v[k].x - mean) * inv * gg.x + bb.x;
        float o1 = (v[k].y - mean) * inv * gg.y + bb.y;
        if (outh) ((__half2*)(outh + orow * DD))[d] = __floats2half2_rn(o0, o1);
        if (outf) ((float2*)(outf + orow * DD))[d] = make_float2(o0, o1);
    }
}

// ---------------- zero pad rows of xtph [LL, SP, DD] ----------------
__global__ __launch_bounds__(256)
void zero_pad_kernel(__half* __restrict__ xth)
{
    long idx = (long)blockIdx.x * 256 + threadIdx.x;
    const long per_l = (long)(SP - SS) * DD;
    const long total = (long)LL * per_l;
    if (idx >= total) return;
    long l = idx / per_l;
    long off = idx % per_l;
    xth[((long)l * SP + SS) * DD + off] = __float2half_rn(0.0f);
}

// ---------------- launch plumbing ----------------
static inline int cdiv(int a, int b) { return (a + b - 1) / b; }

#define SMEM_L ((AWORDS + 5120) * NSTAGE * 4)
#define SMEM_S ((AWORDS + 2560) * NSTAGE * 4)

template<bool TRANSB, int MODE, bool SMALL>
static void launch_gemm(const __half* A, const __half* B, const float* bias, __half* C,
                        int M, int N, int K, int lda, int ldb, int ldc, int batch,
                        long sA, long sB, long sBias, long sC)
{
    const int BN = SMALL ? 128 : 256;
    const int smem = SMALL ? SMEM_S : SMEM_L;
    dim3 grid(cdiv(N, BN), cdiv(M, BMt), batch);
    cudaFuncSetAttribute(mma_gemm_kernel<TRANSB, MODE, SMALL>,
                         cudaFuncAttributeMaxDynamicSharedMemorySize, smem);
    mma_gemm_kernel<TRANSB, MODE, SMALL><<<grid, 256, smem>>>(
        A, B, bias, C, M, N, K, lda, ldb, ldc, sA, sB, sBias, sC);
}

extern "C" void kernel_launch(void* const* d_in, const int* in_sizes, int n_in,
                              void* d_out, int out_size)
{
    (void)in_sizes; (void)n_in; (void)out_size;

    const float* x        = (const float*)d_in[0];
    const float* pre_Wq   = (const float*)d_in[1];
    const float* pre_Wk   = (const float*)d_in[2];
    const float* pre_Wv   = (const float*)d_in[3];
    const float* ln1_g    = (const float*)d_in[4];
    const float* ln1_b    = (const float*)d_in[5];
    const float* pre_W1   = (const float*)d_in[6];
    const float* pre_b1   = (const float*)d_in[7];
    const float* pre_W2   = (const float*)d_in[8];
    const float* pre_b2   = (const float*)d_in[9];
    const float* ln4p_g   = (const float*)d_in[10];
    const float* ln4p_b   = (const float*)d_in[11];
    const float* cross_Wq = (const float*)d_in[12];
    const float* cross_Wk = (const float*)d_in[13];
    const float* cross_Wv = (const float*)d_in[14];
    const float* ln2_g    = (const float*)d_in[15];
    const float* ln2_b    = (const float*)d_in[16];
    const float* post_Wq  = (const float*)d_in[17];
    const float* post_Wk  = (const float*)d_in[18];
    const float* post_Wv  = (const float*)d_in[19];
    const float* ln3_g    = (const float*)d_in[20];
    const float* ln3_b    = (const float*)d_in[21];
    const float* post_W1  = (const float*)d_in[22];
    const float* post_b1  = (const float*)d_in[23];
    const float* post_W2  = (const float*)d_in[24];
    const float* post_b2  = (const float*)d_in[25];
    const float* ln4_g    = (const float*)d_in[26];
    const float* ln4_b    = (const float*)d_in[27];
    float* out = (float*)d_out;

    __half *xh, *lnh, *xtph, *qkh, *avh, *scoresh, *wh;
    cudaGetSymbolAddress((void**)&xh, g_xh);
    cudaGetSymbolAddress((void**)&lnh, g_lnh);
    cudaGetSymbolAddress((void**)&xtph, g_xtph);
    cudaGetSymbolAddress((void**)&qkh, g_qkh);
    cudaGetSymbolAddress((void**)&avh, g_avh);
    cudaGetSymbolAddress((void**)&scoresh, g_scoresh);
    cudaGetSymbolAddress((void**)&wh, g_wh);

    const long SZ_QKW = (long)SS * DD * QKN;
    const long SZ_VW  = (long)SS * DD * DD;
    const long SZ_W1  = (long)SS * DD * DD4;
    __half* qkPreH   = wh;
    __half* qkPostH  = qkPreH  + SZ_QKW;
    __half* qkCrossH = qkPostH + SZ_QKW;
    __half* WvPreH   = qkCrossH + (long)DD * QKN;
    __half* WvPostH  = WvPreH  + SZ_VW;
    __half* WvCrossH = WvPostH + SZ_VW;
    __half* W1PreH   = WvCrossH + (long)DD * DD;
    __half* W1PostH  = W1PreH  + SZ_W1;
    __half* W2PreH   = W1PostH + SZ_W1;
    __half* W2PostH  = W2PreH  + SZ_W1;

    const float scale = 1.0f / sqrtf((float)DD4);
    const long LD = (long)LL * DD;

    // ---------------- weight prep: pure streaming f2h / concat ----------
    concat_qk_kernel<<<cdiv((int)SZ_QKW, 256), 256>>>(pre_Wq, pre_Wk, qkPreH, SZ_QKW);
    concat_qk_kernel<<<cdiv((int)SZ_QKW, 256), 256>>>(post_Wq, post_Wk, qkPostH, SZ_QKW);
    concat_qk_kernel<<<cdiv((int)(DD * QKN), 256), 256>>>(cross_Wq, cross_Wk, qkCrossH, (long)DD * QKN);
    f2h_kernel<<<cdiv((int)(SZ_VW / 4), 256), 256>>>(pre_Wv,  WvPreH,  SZ_VW / 4);
    f2h_kernel<<<cdiv((int)(SZ_VW / 4), 256), 256>>>(post_Wv, WvPostH, SZ_VW / 4);
    f2h_kernel<<<cdiv((int)((long)DD * DD / 4), 256), 256>>>(cross_Wv, WvCrossH, (long)DD * DD / 4);
    f2h_kernel<<<cdiv((int)(SZ_W1 / 4), 256), 256>>>(pre_W1,  W1PreH,  SZ_W1 / 4);
    f2h_kernel<<<cdiv((int)(SZ_W1 / 4), 256), 256>>>(post_W1, W1PostH, SZ_W1 / 4);
    f2h_kernel<<<cdiv((int)(SZ_W1 / 4), 256), 256>>>(pre_W2,  W2PreH,  SZ_W1 / 4);
    f2h_kernel<<<cdiv((int)(SZ_W1 / 4), 256), 256>>>(post_W2, W2PostH, SZ_W1 / 4);
    f2h_kernel<<<cdiv((int)(SS * LD / 4), 256), 256>>>(x, xh, SS * LD / 4);

    // ================= pre_self_step attention =================
    launch_gemm<false, 0, true>(xh, qkPreH, nullptr, qkh, LL, QKN, DD, DD, QKN, QKN, SS,
                                LD, (long)DD * QKN, 0, (long)LL * QKN);
    launch_gemm<true, 0, false>(qkh, qkh + DD4, nullptr, scoresh, LL, LL, DD4, QKN, QKN, LL, SS,
                                (long)LL * QKN, (long)LL * QKN, 0, (long)LL * LL);
    softmax_kernel<<<SS * LL / 8, 256>>>(scoresh, LL, LL, scale, (long)SS * LL);
    launch_gemm<false, 0, false>(scoresh, xh, nullptr, avh, LL, DD, LL, LL, DD, DD, SS,
                                 (long)LL * LL, LD, 0, LD);
    launch_gemm<false, 0, false>(avh, WvPreH, nullptr, scoresh, LL, DD, DD, DD, DD, DD, SS,
                                 LD, (long)DD * DD, 0, LD);
    ln_kernel<<<SS * LL / 8, 256>>>(xh, scoresh, ln1_g, ln1_b, lnh, nullptr, LL,
                                    LL, 1, LL, 1, LL, 1, DD, (long)SS * LL);

    // ================= pre_mlp =================
    launch_gemm<false, 2, false>(lnh, W1PreH, pre_b1, qkh, LL, DD4, DD, DD, DD4, DD4, SS,
                                 LD, (long)DD * DD4, DD4, (long)LL * DD4);
    launch_gemm<false, 1, false>(qkh, W2PreH, pre_b2, scoresh, LL, DD, DD4, DD4, DD, DD, SS,
                                 (long)LL * DD4, (long)DD4 * DD, DD, LD);
    ln_kernel<<<SS * LL / 8, 256>>>(lnh, scoresh, ln4p_g, ln4p_b, xtph, nullptr, LL,
                                    LL, 1, LL, 1, 1, SP, DD, (long)SS * LL);
    zero_pad_kernel<<<cdiv(LL * (SP - SS) * DD, 256), 256>>>(xtph);

    // ================= cross_step attention (padded S -> SP) =================
    launch_gemm<false, 0, true>(xtph, qkCrossH, nullptr, qkh, LL * SP, QKN, DD, DD, QKN, QKN, 1,
                                0, 0, 0, 0);
    launch_gemm<true, 0, true>(qkh, qkh + DD4, nullptr, avh, SP, SP, DD4, QKN, QKN, SP, LL,
                               (long)SP * QKN, (long)SP * QKN, 0, (long)SP * SP);
    softmax_kernel<<<LL * SP / 8, 256>>>(avh, SS, SP, scale, (long)LL * SP);
    launch_gemm<false, 0, false>(avh, xtph, nullptr, scoresh, SS, DD, SP, SP, DD, DD, LL,
                                 (long)SP * SP, (long)SP * DD, 0, (long)SS * DD);
    launch_gemm<false, 0, false>(scoresh, WvCrossH, nullptr, avh, LL * SS, DD, DD, DD, DD, DD, 1,
                                 0, 0, 0, 0);
    ln_kernel<<<LL * SS / 8, 256>>>(xtph, avh, ln2_g, ln2_b, lnh, nullptr, SS,
                                    SP, 1, SS, 1, 1, LL, 0, (long)LL * SS);

    // ================= post_self_step attention =================
    launch_gemm<false, 0, true>(lnh, qkPostH, nullptr, qkh, LL, QKN, DD, DD, QKN, QKN, SS,
                                LD, (long)DD * QKN, 0, (long)LL * QKN);
    launch_gemm<true, 0, false>(qkh, qkh + DD4, nullptr, scoresh, LL, LL, DD4, QKN, QKN, LL, SS,
                                (long)LL * QKN, (long)LL * QKN, 0, (long)LL * LL);
    softmax_kernel<<<SS * LL / 8, 256>>>(scoresh, LL, LL, scale, (long)SS * LL);
    launch_gemm<false, 0, false>(scoresh, lnh, nullptr, avh, LL, DD, LL, LL, DD, DD, SS,
                                 (long)LL * LL, LD, 0, LD);
    launch_gemm<false, 0, false>(avh, WvPostH, nullptr, scoresh, LL, DD, DD, DD, DD, DD, SS,
                                 LD, (long)DD * DD, 0, LD);
    ln_kernel<<<SS * LL / 8, 256>>>(lnh, scoresh, ln3_g, ln3_b, xh, nullptr, LL,
                                    LL, 1, LL, 1, LL, 1, DD, (long)SS * LL);

    // ================= post_mlp =================
    launch_gemm<false, 2, false>(xh, W1PostH, post_b1, qkh, LL, DD4, DD, DD, DD4, DD4, SS,
                                 LD, (long)DD * DD4, DD4, (long)LL * DD4);
    launch_gemm<false, 1, false>(qkh, W2PostH, post_b2, scoresh, LL, DD, DD4, DD4, DD, DD, SS,
                                 (long)LL * DD4, (long)DD4 * DD, DD, LD);
    ln_kernel<<<SS * LL / 8, 256>>>(xh, scoresh, ln4_g, ln4_b, nullptr, out, LL,
                                    LL, 1, LL, 1, LL, 1, DD, (long)SS * LL);
}

// round 14
// speedup vs baseline: 2.4311x; 1.0479x over previous
#include <cuda_runtime.h>
#include <cuda_fp16.h>
#include <math.h>
#include <stdint.h>

// Problem dims
#define SS 50
#define LL 1024
#define DD 768
#define DD4 192
#define SP 64
#define QKN 384

// ---------------- static scratch (alloc-free rule) ----------------
__device__ __half g_xh[(size_t)SS * LL * DD];
__device__ __half g_lnh[(size_t)SS * LL * DD];
__device__ __half g_xtph[(size_t)LL * SP * DD];
__device__ __half g_qkh[(size_t)LL * SP * QKN];
__device__ __half g_avh[(size_t)SS * LL * DD];
__device__ __half g_scoresh[(size_t)SS * LL * LL];
__device__ float  g_rsum[(size_t)LL * SP];
__device__ __half g_wh[119000000];

// =============== helpers =====================
__device__ __forceinline__ uint32_t smem_u32(const void* p) {
    uint32_t a;
    asm("{ .reg .u64 t; cvta.to.shared.u64 t, %1; cvt.u32.u64 %0, t; }" : "=r"(a) : "l"(p));
    return a;
}
__device__ __forceinline__ void mma_f16(float* d, const uint32_t* a, const uint32_t* b) {
    asm volatile(
        "mma.sync.aligned.m16n8k16.row.col.f32.f16.f16.f32 "
        "{%0,%1,%2,%3}, {%4,%5,%6,%7}, {%8,%9}, {%0,%1,%2,%3};\n"
        : "+f"(d[0]), "+f"(d[1]), "+f"(d[2]), "+f"(d[3])
        : "r"(a[0]), "r"(a[1]), "r"(a[2]), "r"(a[3]),
          "r"(b[0]), "r"(b[1]));
}
__device__ __forceinline__ void ldsm_x4(uint32_t& r0, uint32_t& r1, uint32_t& r2, uint32_t& r3,
                                        uint32_t addr) {
    asm volatile("ldmatrix.sync.aligned.m8n8.x4.shared.b16 {%0,%1,%2,%3}, [%4];"
                 : "=r"(r0), "=r"(r1), "=r"(r2), "=r"(r3) : "r"(addr));
}
__device__ __forceinline__ void ldsm_x4_t(uint32_t& r0, uint32_t& r1, uint32_t& r2, uint32_t& r3,
                                          uint32_t addr) {
    asm volatile("ldmatrix.sync.aligned.m8n8.x4.trans.shared.b16 {%0,%1,%2,%3}, [%4];"
                 : "=r"(r0), "=r"(r1), "=r"(r2), "=r"(r3) : "r"(addr));
}
__device__ __forceinline__ void cp_async16(uint32_t smem_addr, const void* gptr, uint32_t src_bytes) {
    asm volatile("cp.async.ca.shared.global [%0], [%1], 16, %2;"
                 :: "r"(smem_addr), "l"(gptr), "r"(src_bytes));
}
#define CP_COMMIT() asm volatile("cp.async.commit_group;" ::: "memory")
#define CP_WAIT2()  asm volatile("cp.async.wait_group 2;" ::: "memory")

// =================================================================
// cp.async-pipelined FP16 GEMM (mma.sync m16n8k16, ldmatrix frags)
// NT: C = A @ B^T (B [N,K]); NN: C = A @ B (B [K,N], ldmatrix.trans)
// SMALL=false: CTA 128x256, warp 64x64.  SMALL=true: CTA 128x128, warp 32x64.
// MODE: 0 plain | 1 +bias | 2 +bias+relu | 3 exp(escale*v) | 4 *rowscale[row]
// fp16 out, fp32 accum.
// =================================================================
#define BMt 128
#define RS 20
#define BRS_NN 132
#define BRS_NN_S 68
#define AWORDS (BMt * RS)
#define NSTAGE 4

template<bool TRANSB, int MODE, bool SMALL>
__global__ __launch_bounds__(256, SMALL ? 2 : 1)
void mma_gemm_kernel(const __half* __restrict__ Ab, const __half* __restrict__ Bb,
                     const float* __restrict__ biasb, __half* __restrict__ Cb,
                     int M, int N, int K, int lda, int ldb, int ldc,
                     long sA, long sB, long sBias, long sC,
                     float escale, const float* __restrict__ rowscale, long sRS)
{
    constexpr bool BIAS = (MODE == 1 || MODE == 2);
    constexpr bool RELU = (MODE == 2);
    constexpr int BN = SMALL ? 128 : 256;
    constexpr int BWRD = SMALL ? 2560 : 5120;
    constexpr int STGW_L = AWORDS + BWRD;
    constexpr int NAM = SMALL ? 2 : 4;

    extern __shared__ __align__(16) uint32_t sm[];
    const uint32_t smb = smem_u32(sm);

    const int b = blockIdx.z;
    const __half* A = Ab + (long)b * sA;
    const __half* B = Bb + (long)b * sB;
    __half* C = Cb + (long)b * sC;

    const int brow = blockIdx.y * BMt;
    const int bcol = blockIdx.x * BN;
    const int tid = threadIdx.x;
    const int wid = tid >> 5;
    const int lane = tid & 31;
    const int g = lane >> 2;
    const int c = lane & 3;
    const int warp_m = SMALL ? (wid & 3) * 32 : (wid & 1) * 64;
    const int warp_n = SMALL ? (wid >> 2) * 64 : (wid >> 1) * 64;

    const int a_row  = (lane & 7) + ((lane >> 3) & 1) * 8;
    const int a_koff = ((lane >> 4) & 1) * 8;
    const int bt_row  = (lane & 7) + ((lane >> 4) & 1) * 8;
    const int bt_koff = ((lane >> 3) & 1) * 8;
    const int bn_k = (lane & 7) + ((lane >> 3) & 1) * 8;
    const int bn_n = ((lane >> 4) & 1) * 8;

    const int nkt = K >> 5;

    float acc[NAM][8][4];
    #pragma unroll
    for (int i = 0; i < NAM; i++)
        #pragma unroll
        for (int j = 0; j < 8; j++)
            #pragma unroll
            for (int r = 0; r < 4; r++)
                acc[i][j][r] = 0.0f;

    auto issue_stage = [&](int kt) {
        if (kt < nkt) {
            int k0 = kt << 5;
            uint32_t sbase = smb + ((kt & (NSTAGE - 1)) * STGW_L) * 4;
            #pragma unroll
            for (int i = 0; i < 2; i++) {
                int idx = i * 256 + tid;
                int row = idx >> 2, q = idx & 3;
                int gr = brow + row;
                const __half* gp = A + (long)gr * lda + k0 + q * 8;
                uint32_t dst = sbase + (row * RS + q * 4) * 4;
                cp_async16(dst, gp, (gr < M) ? 16u : 0u);
            }
            if (TRANSB) {
                constexpr int NIT = SMALL ? 2 : 4;
                #pragma unroll
                for (int i = 0; i < NIT; i++) {
                    int idx = i * 256 + tid;
                    int row = idx >> 2, q = idx & 3;
                    int gn = bcol + row;
                    const __half* gp = B + (long)gn * ldb + k0 + q * 8;
                    uint32_t dst = sbase + (AWORDS + row * RS + q * 4) * 4;
                    cp_async16(dst, gp, (gn < N) ? 16u : 0u);
                }
            } else {
                if (SMALL) {
                    #pragma unroll
                    for (int i = 0; i < 2; i++) {
                        int idx = i * 256 + tid;
                        int kk = idx >> 4, ch = idx & 15;
                        int gn = bcol + ch * 8;
                        const __half* gp = B + (long)(k0 + kk) * ldb + gn;
                        uint32_t dst = sbase + (AWORDS + kk * BRS_NN_S + ch * 4) * 4;
                        cp_async16(dst, gp, (gn < N) ? 16u : 0u);
                    }
                } else {
                    #pragma unroll
                    for (int i = 0; i < 4; i++) {
                        int idx = i * 256 + tid;
                        int kk = idx >> 5, ch = idx & 31;
                        int gn = bcol + ch * 8;
                        const __half* gp = B + (long)(k0 + kk) * ldb + gn;
                        uint32_t dst = sbase + (AWORDS + kk * BRS_NN + ch * 4) * 4;
                        cp_async16(dst, gp, (gn < N) ? 16u : 0u);
                    }
                }
            }
        }
        CP_COMMIT();
    };

    issue_stage(0);
    issue_stage(1);
    issue_stage(2);

    for (int kt = 0; kt < nkt; kt++) {
        CP_WAIT2();
        __syncthreads();
        issue_stage(kt + 3);

        uint32_t As = smb + ((kt & (NSTAGE - 1)) * STGW_L) * 4;
        uint32_t Bs = As + AWORDS * 4;

        #pragma unroll
        for (int ks = 0; ks < 2; ks++) {
            int kh = ks * 16;
            uint32_t af[NAM][4], bf[8][2];
            #pragma unroll
            for (int am = 0; am < NAM; am++) {
                uint32_t addr = As + ((warp_m + am * 16 + a_row) * RS) * 4
                                   + (kh + a_koff) * 2;
                ldsm_x4(af[am][0], af[am][1], af[am][2], af[am][3], addr);
            }
            #pragma unroll
            for (int p = 0; p < 4; p++) {
                if (TRANSB) {
                    uint32_t addr = Bs + ((warp_n + p * 16 + bt_row) * RS) * 4
                                       + (kh + bt_koff) * 2;
                    ldsm_x4(bf[2 * p][0], bf[2 * p][1], bf[2 * p + 1][0], bf[2 * p + 1][1], addr);
                } else {
                    uint32_t brs = SMALL ? BRS_NN_S : BRS_NN;
                    uint32_t addr = Bs + ((kh + bn_k) * brs) * 4
                                       + (warp_n + p * 16 + bn_n) * 2;
                    ldsm_x4_t(bf[2 * p][0], bf[2 * p][1], bf[2 * p + 1][0], bf[2 * p + 1][1], addr);
                }
            }
            #pragma unroll
            for (int am = 0; am < NAM; am++)
                #pragma unroll
                for (int bn = 0; bn < 8; bn++)
                    mma_f16(acc[am][bn], af[am], bf[bn]);
        }
    }

    // ---- epilogue (fp16 out) ----
    #pragma unroll
    for (int am = 0; am < NAM; am++) {
        int row0 = brow + warp_m + am * 16 + g;
        float rs0 = 1.0f, rs1 = 1.0f;
        if (MODE == 4) {
            rs0 = (row0 < M)     ? rowscale[(long)b * sRS + row0]     : 0.0f;
            rs1 = (row0 + 8 < M) ? rowscale[(long)b * sRS + row0 + 8] : 0.0f;
        }
        #pragma unroll
        for (int bn = 0; bn < 8; bn++) {
            int col = bcol + warp_n + bn * 8 + c * 2;
            if (col >= N) continue;
            float v0 = acc[am][bn][0], v1 = acc[am][bn][1];
            float v2 = acc[am][bn][2], v3 = acc[am][bn][3];
            if (BIAS) {
                float b0 = biasb[(long)b * sBias + col];
                float b1 = biasb[(long)b * sBias + col + 1];
                v0 += b0; v1 += b1; v2 += b0; v3 += b1;
            }
            if (RELU) {
                v0 = fmaxf(v0, 0.f); v1 = fmaxf(v1, 0.f);
                v2 = fmaxf(v2, 0.f); v3 = fmaxf(v3, 0.f);
            }
            if (MODE == 3) {
                v0 = __expf(v0 * escale); v1 = __expf(v1 * escale);
                v2 = __expf(v2 * escale); v3 = __expf(v3 * escale);
            }
            if (MODE == 4) {
                v0 *= rs0; v1 *= rs0; v2 *= rs1; v3 *= rs1;
            }
            __half2 h01 = __floats2half2_rn(v0, v1);
            __half2 h23 = __floats2half2_rn(v2, v3);
            if (row0 < M)     *(__half2*)&C[(long)row0 * ldc + col]       = h01;
            if (row0 + 8 < M) *(__half2*)&C[(long)(row0 + 8) * ldc + col] = h23;
        }
    }
}

// ---------------- float -> half elementwise ----------------
__global__ __launch_bounds__(256)
void f2h_kernel(const float* __restrict__ in, __half* __restrict__ out, long n4)
{
    long i = (long)blockIdx.x * 256 + threadIdx.x;
    if (i >= n4) return;
    float4 v = ((const float4*)in)[i];
    ((__half2*)out)[i * 2]     = __floats2half2_rn(v.x, v.y);
    ((__half2*)out)[i * 2 + 1] = __floats2half2_rn(v.z, v.w);
}

// ------- concat Wq||Wk -> half [batch, D, QKN] --------
__global__ __launch_bounds__(256)
void concat_qk_kernel(const float* __restrict__ Wq, const float* __restrict__ Wk,
                      __half* __restrict__ out, long total)
{
    long i = (long)blockIdx.x * 256 + threadIdx.x;
    if (i >= total) return;
    long j = i % QKN;
    long bd = i / QKN;
    float v = (j < DD4) ? Wq[bd * DD4 + j] : Wk[bd * DD4 + (j - DD4)];
    out[i] = __float2half_rn(v);
}

// ------- warp-per-row reciprocal row sum (+ zero pad cols) --------
// data rows hold exp-scores; rsum[row] = 1/sum(cols < n); zeros cols [n, stride).
__global__ __launch_bounds__(256)
void rowsum_kernel(__half* __restrict__ data, float* __restrict__ rsum,
                   int n, int stride, long nrows)
{
    int wid = threadIdx.x >> 5, lane = threadIdx.x & 31;
    long row = (long)blockIdx.x * 8 + wid;
    if (row >= nrows) return;
    __half2* p2 = (__half2*)(data + row * (long)stride);
    int n2 = n >> 1;

    float s = 0.0f;
    for (int i = lane; i < n2; i += 32) {
        float2 v = __half22float2(p2[i]);
        s += v.x + v.y;
    }
    #pragma unroll
    for (int o = 16; o > 0; o >>= 1) s += __shfl_xor_sync(0xffffffffu, s, o);
    if (lane == 0) rsum[row] = 1.0f / s;

    int s2 = stride >> 1;
    for (int i = n2 + lane; i < s2; i += 32) p2[i] = __floats2half2_rn(0.f, 0.f);
}

// ------ warp-per-row fused residual + LayerNorm (fp16 stream, fp32 math) ------
__global__ __launch_bounds__(256)
void ln_kernel(const __half* __restrict__ resid, const __half* __restrict__ h,
               const float* __restrict__ gam, const float* __restrict__ bet,
               __half* __restrict__ outh, float* __restrict__ outf, int J,
               long ri, long rj, long hi, long hj, long oi, long oj, long gstride,
               long nrows)
{
    int wid = threadIdx.x >> 5, lane = threadIdx.x & 31;
    long row = (long)blockIdx.x * 8 + wid;
    if (row >= nrows) return;
    long i = row / J, j = row % J;
    const __half2* r2 = (const __half2*)(resid + (i * ri + j * rj) * DD);
    const __half2* h2 = (const __half2*)(h     + (i * hi + j * hj) * DD);
    long orow = i * oi + j * oj;
    const float2* gp = (const float2*)(gam + i * gstride);
    const float2* bp = (const float2*)(bet + i * gstride);

    float2 v[12];
    float s = 0.0f, s2 = 0.0f;
    #pragma unroll
    for (int k = 0; k < 12; k++) {
        int d = lane + k * 32;
        float2 a = __half22float2(r2[d]);
        float2 b = __half22float2(h2[d]);
        float2 val = make_float2(a.x + b.x, a.y + b.y);
        v[k] = val;
        s += val.x + val.y;
        s2 += val.x * val.x + val.y * val.y;
    }
    #pragma unroll
    for (int o = 16; o > 0; o >>= 1) {
        s  += __shfl_xor_sync(0xffffffffu, s, o);
        s2 += __shfl_xor_sync(0xffffffffu, s2, o);
    }
    float mean = s * (1.0f / DD);
    float var  = s2 * (1.0f / DD) - mean * mean;
    float inv  = rsqrtf(var + 1e-5f);

    #pragma unroll
    for (int k = 0; k < 12; k++) {
        int d = lane + k * 32;
        float2 gg = gp[d], bb = bp[d];
        float o0 = (v[k].x - mean) * inv * gg.x + bb.x;
        float o1 = (v[k].y - mean) * inv * gg.y + bb.y;
        if (outh) ((__half2*)(outh + orow * DD))[d] = __floats2half2_rn(o0, o1);
        if (outf) ((float2*)(outf + orow * DD))[d] = make_float2(o0, o1);
    }
}

// ---------------- zero pad rows of xtph [LL, SP, DD] ----------------
__global__ __launch_bounds__(256)
void zero_pad_kernel(__half* __restrict__ xth)
{
    long idx = (long)blockIdx.x * 256 + threadIdx.x;
    const long per_l = (long)(SP - SS) * DD;
    const long total = (long)LL * per_l;
    if (idx >= total) return;
    long l = idx / per_l;
    long off = idx % per_l;
    xth[((long)l * SP + SS) * DD + off] = __float2half_rn(0.0f);
}

// ---------------- launch plumbing ----------------
static inline int cdiv(int a, int b) { return (a + b - 1) / b; }

#define SMEM_L ((AWORDS + 5120) * NSTAGE * 4)
#define SMEM_S ((AWORDS + 2560) * NSTAGE * 4)

template<bool TRANSB, int MODE, bool SMALL>
static void launch_gemm(const __half* A, const __half* B, const float* bias, __half* C,
                        int M, int N, int K, int lda, int ldb, int ldc, int batch,
                        long sA, long sB, long sBias, long sC,
                        float escale = 0.0f, const float* rowscale = nullptr, long sRS = 0)
{
    const int BN = SMALL ? 128 : 256;
    const int smem = SMALL ? SMEM_S : SMEM_L;
    dim3 grid(cdiv(N, BN), cdiv(M, BMt), batch);
    cudaFuncSetAttribute(mma_gemm_kernel<TRANSB, MODE, SMALL>,
                         cudaFuncAttributeMaxDynamicSharedMemorySize, smem);
    mma_gemm_kernel<TRANSB, MODE, SMALL><<<grid, 256, smem>>>(
        A, B, bias, C, M, N, K, lda, ldb, ldc, sA, sB, sBias, sC, escale, rowscale, sRS);
}

extern "C" void kernel_launch(void* const* d_in, const int* in_sizes, int n_in,
                              void* d_out, int out_size)
{
    (void)in_sizes; (void)n_in; (void)out_size;

    const float* x        = (const float*)d_in[0];
    const float* pre_Wq   = (const float*)d_in[1];
    const float* pre_Wk   = (const float*)d_in[2];
    const float* pre_Wv   = (const float*)d_in[3];
    const float* ln1_g    = (const float*)d_in[4];
    const float* ln1_b    = (const float*)d_in[5];
    const float* pre_W1   = (const float*)d_in[6];
    const float* pre_b1   = (const float*)d_in[7];
    const float* pre_W2   = (const float*)d_in[8];
    const float* pre_b2   = (const float*)d_in[9];
    const float* ln4p_g   = (const float*)d_in[10];
    const float* ln4p_b   = (const float*)d_in[11];
    const float* cross_Wq = (const float*)d_in[12];
    const float* cross_Wk = (const float*)d_in[13];
    const float* cross_Wv = (const float*)d_in[14];
    const float* ln2_g    = (const float*)d_in[15];
    const float* ln2_b    = (const float*)d_in[16];
    const float* post_Wq  = (const float*)d_in[17];
    const float* post_Wk  = (const float*)d_in[18];
    const float* post_Wv  = (const float*)d_in[19];
    const float* ln3_g    = (const float*)d_in[20];
    const float* ln3_b    = (const float*)d_in[21];
    const float* post_W1  = (const float*)d_in[22];
    const float* post_b1  = (const float*)d_in[23];
    const float* post_W2  = (const float*)d_in[24];
    const float* post_b2  = (const float*)d_in[25];
    const float* ln4_g    = (const float*)d_in[26];
    const float* ln4_b    = (const float*)d_in[27];
    float* out = (float*)d_out;

    __half *xh, *lnh, *xtph, *qkh, *avh, *scoresh, *wh;
    float* rsum;
    cudaGetSymbolAddress((void**)&xh, g_xh);
    cudaGetSymbolAddress((void**)&lnh, g_lnh);
    cudaGetSymbolAddress((void**)&xtph, g_xtph);
    cudaGetSymbolAddress((void**)&qkh, g_qkh);
    cudaGetSymbolAddress((void**)&avh, g_avh);
    cudaGetSymbolAddress((void**)&scoresh, g_scoresh);
    cudaGetSymbolAddress((void**)&rsum, g_rsum);
    cudaGetSymbolAddress((void**)&wh, g_wh);

    const long SZ_QKW = (long)SS * DD * QKN;
    const long SZ_VW  = (long)SS * DD * DD;
    const long SZ_W1  = (long)SS * DD * DD4;
    __half* qkPreH   = wh;
    __half* qkPostH  = qkPreH  + SZ_QKW;
    __half* qkCrossH = qkPostH + SZ_QKW;
    __half* WvPreH   = qkCrossH + (long)DD * QKN;
    __half* WvPostH  = WvPreH  + SZ_VW;
    __half* WvCrossH = WvPostH + SZ_VW;
    __half* W1PreH   = WvCrossH + (long)DD * DD;
    __half* W1PostH  = W1PreH  + SZ_W1;
    __half* W2PreH   = W1PostH + SZ_W1;
    __half* W2PostH  = W2PreH  + SZ_W1;

    const float scale = 1.0f / sqrtf((float)DD4);
    const long LD = (long)LL * DD;

    // ---------------- weight prep: pure streaming f2h / concat ----------
    concat_qk_kernel<<<cdiv((int)SZ_QKW, 256), 256>>>(pre_Wq, pre_Wk, qkPreH, SZ_QKW);
    concat_qk_kernel<<<cdiv((int)SZ_QKW, 256), 256>>>(post_Wq, post_Wk, qkPostH, SZ_QKW);
    concat_qk_kernel<<<cdiv((int)(DD * QKN), 256), 256>>>(cross_Wq, cross_Wk, qkCrossH, (long)DD * QKN);
    f2h_kernel<<<cdiv((int)(SZ_VW / 4), 256), 256>>>(pre_Wv,  WvPreH,  SZ_VW / 4);
    f2h_kernel<<<cdiv((int)(SZ_VW / 4), 256), 256>>>(post_Wv, WvPostH, SZ_VW / 4);
    f2h_kernel<<<cdiv((int)((long)DD * DD / 4), 256), 256>>>(cross_Wv, WvCrossH, (long)DD * DD / 4);
    f2h_kernel<<<cdiv((int)(SZ_W1 / 4), 256), 256>>>(pre_W1,  W1PreH,  SZ_W1 / 4);
    f2h_kernel<<<cdiv((int)(SZ_W1 / 4), 256), 256>>>(post_W1, W1PostH, SZ_W1 / 4);
    f2h_kernel<<<cdiv((int)(SZ_W1 / 4), 256), 256>>>(pre_W2,  W2PreH,  SZ_W1 / 4);
    f2h_kernel<<<cdiv((int)(SZ_W1 / 4), 256), 256>>>(post_W2, W2PostH, SZ_W1 / 4);
    f2h_kernel<<<cdiv((int)(SS * LD / 4), 256), 256>>>(x, xh, SS * LD / 4);

    // ================= pre_self_step attention =================
    launch_gemm<false, 0, true>(xh, qkPreH, nullptr, qkh, LL, QKN, DD, DD, QKN, QKN, SS,
                                LD, (long)DD * QKN, 0, (long)LL * QKN);
    launch_gemm<true, 3, false>(qkh, qkh + DD4, nullptr, scoresh, LL, LL, DD4, QKN, QKN, LL, SS,
                                (long)LL * QKN, (long)LL * QKN, 0, (long)LL * LL, scale);
    rowsum_kernel<<<SS * LL / 8, 256>>>(scoresh, rsum, LL, LL, (long)SS * LL);
    launch_gemm<false, 4, false>(scoresh, xh, nullptr, avh, LL, DD, LL, LL, DD, DD, SS,
                                 (long)LL * LL, LD, 0, LD, 0.0f, rsum, LL);
    launch_gemm<false, 0, false>(avh, WvPreH, nullptr, scoresh, LL, DD, DD, DD, DD, DD, SS,
                                 LD, (long)DD * DD, 0, LD);
    ln_kernel<<<SS * LL / 8, 256>>>(xh, scoresh, ln1_g, ln1_b, lnh, nullptr, LL,
                                    LL, 1, LL, 1, LL, 1, DD, (long)SS * LL);

    // ================= pre_mlp =================
    launch_gemm<false, 2, false>(lnh, W1PreH, pre_b1, qkh, LL, DD4, DD, DD, DD4, DD4, SS,
                                 LD, (long)DD * DD4, DD4, (long)LL * DD4);
    launch_gemm<false, 1, false>(qkh, W2PreH, pre_b2, scoresh, LL, DD, DD4, DD4, DD, DD, SS,
                                 (long)LL * DD4, (long)DD4 * DD, DD, LD);
    ln_kernel<<<SS * LL / 8, 256>>>(lnh, scoresh, ln4p_g, ln4p_b, xtph, nullptr, LL,
                                    LL, 1, LL, 1, 1, SP, DD, (long)SS * LL);
    zero_pad_kernel<<<cdiv(LL * (SP - SS) * DD, 256), 256>>>(xtph);

    // ================= cross_step attention (padded S -> SP) =================
    launch_gemm<false, 0, true>(xtph, qkCrossH, nullptr, qkh, LL * SP, QKN, DD, DD, QKN, QKN, 1,
                                0, 0, 0, 0);
    launch_gemm<true, 3, true>(qkh, qkh + DD4, nullptr, avh, SP, SP, DD4, QKN, QKN, SP, LL,
                               (long)SP * QKN, (long)SP * QKN, 0, (long)SP * SP, scale);
    rowsum_kernel<<<LL * SP / 8, 256>>>(avh, rsum, SS, SP, (long)LL * SP);
    launch_gemm<false, 4, false>(avh, xtph, nullptr, scoresh, SS, DD, SP, SP, DD, DD, LL,
                                 (long)SP * SP, (long)SP * DD, 0, (long)SS * DD, 0.0f, rsum, SP);
    launch_gemm<false, 0, false>(scoresh, WvCrossH, nullptr, avh, LL * SS, DD, DD, DD, DD, DD, 1,
                                 0, 0, 0, 0);
    ln_kernel<<<LL * SS / 8, 256>>>(xtph, avh, ln2_g, ln2_b, lnh, nullptr, SS,
                                    SP, 1, SS, 1, 1, LL, 0, (long)LL * SS);

    // ================= post_self_step attention =================
    launch_gemm<false, 0, true>(lnh, qkPostH, nullptr, qkh, LL, QKN, DD, DD, QKN, QKN, SS,
                                LD, (long)DD * QKN, 0, (long)LL * QKN);
    launch_gemm<true, 3, false>(qkh, qkh + DD4, nullptr, scoresh, LL, LL, DD4, QKN, QKN, LL, SS,
                                (long)LL * QKN, (long)LL * QKN, 0, (long)LL * LL, scale);
    rowsum_kernel<<<SS * LL / 8, 256>>>(scoresh, rsum, LL, LL, (long)SS * LL);
    launch_gemm<false, 4, false>(scoresh, lnh, nullptr, avh, LL, DD, LL, LL, DD, DD, SS,
                                 (long)LL * LL, LD, 0, LD, 0.0f, rsum, LL);
    launch_gemm<false, 0, false>(avh, WvPostH, nullptr, scoresh, LL, DD, DD, DD, DD, DD, SS,
                                 LD, (long)DD * DD, 0, LD);
    ln_kernel<<<SS * LL / 8, 256>>>(lnh, scoresh, ln3_g, ln3_b, xh, nullptr, LL,
                                    LL, 1, LL, 1, LL, 1, DD, (long)SS * LL);

    // ================= post_mlp =================
    launch_gemm<false, 2, false>(xh, W1PostH, post_b1, qkh, LL, DD4, DD, DD, DD4, DD4, SS,
                                 LD, (long)DD * DD4, DD4, (long)LL * DD4);
    launch_gemm<false, 1, false>(qkh, W2PostH, post_b2, scoresh, LL, DD, DD4, DD4, DD, DD, SS,
                                 (long)LL * DD4, (long)DD4 * DD, DD, LD);
    ln_kernel<<<SS * LL / 8, 256>>>(xh, scoresh, ln4_g, ln4_b, nullptr, out, LL,
                                    LL, 1, LL, 1, LL, 1, DD, (long)SS * LL);
}